// round 1
// baseline (speedup 1.0000x reference)
#include <cuda_runtime.h>

// Problem constants
#define Bsz 512
#define Lsz 256
#define Esz 300
#define Hsz 200
constexpr long BL  = (long)Bsz * Lsz;      // 131072
constexpr long BLE = BL * Esz;             // 39,321,600
constexpr long BLH = BL * Hsz;             // 26,214,400
constexpr long LL  = (long)Lsz * Lsz;      // 65536
constexpr long BLL = BL * Lsz;             // 33,554,432

// ---------------- device scratch (static, no runtime allocation) -------------
__device__ float g_e[2 * BLE];     // [e1 ; e2]          (2*BL x 300)
__device__ float g_ta[2 * BLH];    // temp hidden A      (2*BL x 200)
__device__ float g_h[2 * BLH];     // h = attend_ff out / compare out (2*BL x 200)
__device__ float g_scores[BLL];    // e scores, later eb (B x 256 x 256)
__device__ float g_ea[BLL];        // ea (unnormalized)
__device__ float g_ab[2 * BLE];    // [betas ; alphas]   (2*BL x 300)
__device__ float g_mask[2 * BL];   // [mask1 ; mask2]
__device__ float g_rowmax[BL];
__device__ float g_colmax[BL];
__device__ float g_rsa[BL];        // mask2 / d_alpha (per (b,j))
__device__ float g_rsb[BL];        // mask1 / d_beta  (per (b,i))
__device__ float g_v[2 * Bsz * Hsz];
__device__ float g_vcat[Bsz * 2 * Hsz];
__device__ float g_u[Bsz * Hsz];

// ---------------- generic tiled GEMM ----------------------------------------
// C[bz][m,n] = epi( sum_k A(m,k) * B(k,n) )
// TA=false: A[m,k] = A[m*lda + k]   TA=true: A[m,k] = A[k*lda + m]
// TB=false: B[k,n] = B[k*ldb + n]   TB=true: B[k,n] = B[n*ldb + k]
// epilogue: v = acc (+ C if accum) (+ bias[n]) ; relu ; * rowscale[bz*sRS + m]
// Requires M % 64 == 0 (true for all call sites). N, K arbitrary (guarded).
template <bool TA, bool TB>
__global__ void gemm_k(const float* __restrict__ A, long sA, int lda,
                       const float* __restrict__ Bw, long sB, int ldb,
                       const float* __restrict__ bias,
                       const float* __restrict__ rs, int sRS,
                       float* __restrict__ C, long sC, int ldc,
                       int M, int N, int K, int accum, int relu)
{
    __shared__ float As[16][65];
    __shared__ float Bs[16][65];
    int bz = blockIdx.z;
    const float* Ab = A + (long)bz * sA;
    const float* Bb = Bw + (long)bz * sB;
    float* Cb = C + (long)bz * sC;
    int m0 = blockIdx.y * 64, n0 = blockIdx.x * 64;
    int tid = threadIdx.x;
    int tn = tid & 15, tm = tid >> 4;

    float acc[4][4];
#pragma unroll
    for (int i = 0; i < 4; i++)
#pragma unroll
        for (int j = 0; j < 4; j++) acc[i][j] = 0.f;

    for (int k0 = 0; k0 < K; k0 += 16) {
        // ---- load A tile into As[k][m]
        if (!TA) {
            int r = tid >> 4, kk = tid & 15;
#pragma unroll
            for (int it = 0; it < 4; it++) {
                int m = r + it * 16;
                float v = 0.f;
                if (k0 + kk < K) v = Ab[(long)(m0 + m) * lda + (k0 + kk)];
                As[kk][m] = v;
            }
        } else {
            int kk = tid >> 6, o = tid & 63;
#pragma unroll
            for (int it = 0; it < 4; it++) {
                int k = kk + it * 4;
                float v = 0.f;
                if (k0 + k < K) v = Ab[(long)(k0 + k) * lda + (m0 + o)];
                As[k][o] = v;
            }
        }
        // ---- load B tile into Bs[k][n]
        if (!TB) {
            int kk = tid >> 6, o = tid & 63;
#pragma unroll
            for (int it = 0; it < 4; it++) {
                int k = kk + it * 4;
                float v = 0.f;
                if (k0 + k < K && n0 + o < N) v = Bb[(long)(k0 + k) * ldb + (n0 + o)];
                Bs[k][o] = v;
            }
        } else {
            int r = tid >> 4, kk = tid & 15;
#pragma unroll
            for (int it = 0; it < 4; it++) {
                int n = r + it * 16;
                float v = 0.f;
                if (k0 + kk < K && n0 + n < N) v = Bb[(long)(n0 + n) * ldb + (k0 + kk)];
                Bs[kk][n] = v;
            }
        }
        __syncthreads();
#pragma unroll
        for (int k = 0; k < 16; k++) {
            float a[4], b[4];
#pragma unroll
            for (int i = 0; i < 4; i++) a[i] = As[k][tm * 4 + i];
#pragma unroll
            for (int j = 0; j < 4; j++) b[j] = Bs[k][tn * 4 + j];
#pragma unroll
            for (int i = 0; i < 4; i++)
#pragma unroll
                for (int j = 0; j < 4; j++) acc[i][j] += a[i] * b[j];
        }
        __syncthreads();
    }

#pragma unroll
    for (int i = 0; i < 4; i++) {
        int m = m0 + tm * 4 + i;
        float rsv = rs ? rs[(long)bz * sRS + m] : 1.f;
#pragma unroll
        for (int j = 0; j < 4; j++) {
            int n = n0 + tn * 4 + j;
            if (n < N) {
                long idx = (long)m * ldc + n;
                float v = acc[i][j];
                if (accum) v += Cb[idx];
                if (bias) v += bias[n];
                if (relu) v = fmaxf(v, 0.f);
                v *= rsv;
                Cb[idx] = v;
            }
        }
    }
}

// ---------------- small helper kernels ---------------------------------------
__global__ void gather_k(const float* __restrict__ emb,
                         const int* __restrict__ s1, const int* __restrict__ s2)
{
    long row = blockIdx.x;                 // 0 .. 2*BL-1
    long r = row < BL ? row : row - BL;
    int tok = (row < BL) ? s1[r] : s2[r];
    const float* src = emb + (long)tok * Esz;
    float* dst = g_e + row * Esz;
    for (int t = threadIdx.x; t < Esz; t += blockDim.x) dst[t] = src[t];
}

__global__ void mask_k(const int* __restrict__ len1, const int* __restrict__ len2)
{
    long idx = (long)blockIdx.x * blockDim.x + threadIdx.x;
    if (idx >= 2 * BL) return;
    int seq = (int)(idx / BL);
    long r = idx % BL;
    int b = (int)(r / Lsz), l = (int)(r % Lsz);
    int len = seq ? len2[b] : len1[b];
    g_mask[idx] = (l < len) ? 1.f : 0.f;
}

__global__ void rowmax_k()
{
    long row = (long)blockIdx.x * 8 + (threadIdx.x >> 5);   // 0..BL-1
    int lane = threadIdx.x & 31;
    const float* p = g_scores + row * Lsz;
    float m = -1e30f;
    for (int j = lane; j < Lsz; j += 32) m = fmaxf(m, p[j]);
#pragma unroll
    for (int o = 16; o; o >>= 1) m = fmaxf(m, __shfl_xor_sync(~0u, m, o));
    if (lane == 0) g_rowmax[row] = m;
}

__global__ void colmax_k()
{
    int b = blockIdx.x;
    int j = threadIdx.x;
    const float* p = g_scores + (long)b * LL;
    float m = -1e30f;
    for (int i = 0; i < Lsz; i++) m = fmaxf(m, p[(long)i * Lsz + j]);
    g_colmax[(long)b * Lsz + j] = m;
}

// ea[b,i,j] = exp(e - rowmax[b,j]) * mask1[b,i]   -> g_ea, col-sum -> rsa
// eb[b,i,j] = exp(e - colmax[b,i]) * mask2[b,j]   -> in-place over g_scores
__global__ void softpre_k()
{
    int b = blockIdx.x;
    int j = threadIdx.x;
    long base = (long)b * LL;
    float rm  = g_rowmax[(long)b * Lsz + j];
    float m2j = g_mask[BL + (long)b * Lsz + j];
    float da = 0.f;
    for (int i = 0; i < Lsz; i++) {
        long idx = base + (long)i * Lsz + j;
        float e = g_scores[idx];
        float m1i = g_mask[(long)b * Lsz + i];
        float cm  = g_colmax[(long)b * Lsz + i];
        float ea = __expf(e - rm) * m1i;
        da += ea;
        g_ea[idx] = ea;
        g_scores[idx] = __expf(e - cm) * m2j;
    }
    g_rsa[(long)b * Lsz + j] = m2j / da;
}

__global__ void rowsum_k()   // d_beta row sums over eb (= g_scores), -> rsb
{
    long row = (long)blockIdx.x * 8 + (threadIdx.x >> 5);
    int lane = threadIdx.x & 31;
    const float* p = g_scores + row * Lsz;
    float s = 0.f;
    for (int j = lane; j < Lsz; j += 32) s += p[j];
#pragma unroll
    for (int o = 16; o; o >>= 1) s += __shfl_xor_sync(~0u, s, o);
    if (lane == 0) g_rsb[row] = g_mask[row] / s;
}

__global__ void colsum_k()   // v[b2,h] = sum_l h[b2,l,h]  (mask already applied)
{
    int b2 = blockIdx.x;     // 0 .. 2B-1
    int h = threadIdx.x;
    if (h >= Hsz) return;
    const float* p = g_h + (long)b2 * Lsz * Hsz;
    float s = 0.f;
    for (int l = 0; l < Lsz; l++) s += p[(long)l * Hsz + h];
    g_v[(long)b2 * Hsz + h] = s;
}

__global__ void vcat_k()
{
    int idx = blockIdx.x * blockDim.x + threadIdx.x;   // B*400
    if (idx >= Bsz * 2 * Hsz) return;
    int b = idx / (2 * Hsz), c = idx % (2 * Hsz);
    float v = (c < Hsz) ? g_v[(long)b * Hsz + c]
                        : g_v[(long)(Bsz + b) * Hsz + (c - Hsz)];
    g_vcat[idx] = v;
}

__global__ void final_k(const float* __restrict__ W2g,
                        const float* __restrict__ b2g, float* __restrict__ out)
{
    int b = blockIdx.x;
    int o = threadIdx.x >> 5;       // 0 or 1 (64 threads)
    int lane = threadIdx.x & 31;
    const float* u = g_u + (long)b * Hsz;
    float s = 0.f;
    for (int h = lane; h < Hsz; h += 32) s += u[h] * W2g[h * 2 + o];
#pragma unroll
    for (int off = 16; off; off >>= 1) s += __shfl_xor_sync(~0u, s, off);
    if (lane == 0) out[b * 2 + o] = s + b2g[o];
}

// ---------------- launch -----------------------------------------------------
extern "C" void kernel_launch(void* const* d_in, const int* in_sizes, int n_in,
                              void* d_out, int out_size)
{
    const float* emb = (const float*)d_in[0];
    const float* W1a = (const float*)d_in[1];
    const float* b1a = (const float*)d_in[2];
    const float* W2a = (const float*)d_in[3];
    const float* b2a = (const float*)d_in[4];
    const float* W1c = (const float*)d_in[5];
    const float* b1c = (const float*)d_in[6];
    const float* W2c = (const float*)d_in[7];
    const float* b2c = (const float*)d_in[8];
    const float* W1g = (const float*)d_in[9];
    const float* b1g = (const float*)d_in[10];
    const float* W2g = (const float*)d_in[11];
    const float* b2g = (const float*)d_in[12];
    const int* s1   = (const int*)d_in[13];
    const int* s2   = (const int*)d_in[14];
    const int* len1 = (const int*)d_in[15];
    const int* len2 = (const int*)d_in[16];
    float* out = (float*)d_out;

    float *pe, *pta, *ph, *psc, *pea, *pab, *pmask, *prsa, *prsb, *pvcat, *pu;
    cudaGetSymbolAddress((void**)&pe,   g_e);
    cudaGetSymbolAddress((void**)&pta,  g_ta);
    cudaGetSymbolAddress((void**)&ph,   g_h);
    cudaGetSymbolAddress((void**)&psc,  g_scores);
    cudaGetSymbolAddress((void**)&pea,  g_ea);
    cudaGetSymbolAddress((void**)&pab,  g_ab);
    cudaGetSymbolAddress((void**)&pmask,g_mask);
    cudaGetSymbolAddress((void**)&prsa, g_rsa);
    cudaGetSymbolAddress((void**)&prsb, g_rsb);
    cudaGetSymbolAddress((void**)&pvcat,g_vcat);
    cudaGetSymbolAddress((void**)&pu,   g_u);

    const int M2 = (int)(2 * BL);          // 262144
    const long LsH = (long)Lsz * Hsz;
    const long LsE = (long)Lsz * Esz;

    // 1. embedding gather + masks
    gather_k<<<(unsigned)(2 * BL), 128>>>(emb, s1, s2);
    mask_k<<<(unsigned)((2 * BL + 255) / 256), 256>>>(len1, len2);

    // 2. attend_ff: h = relu(relu(e@W1a+b1a)@W2a+b2a)   (M=262144)
    gemm_k<false,false><<<dim3(4, M2 / 64, 1), 256>>>(
        pe, 0, Esz, W1a, 0, Hsz, b1a, nullptr, 0, pta, 0, Hsz, M2, Hsz, Esz, 0, 1);
    gemm_k<false,false><<<dim3(4, M2 / 64, 1), 256>>>(
        pta, 0, Hsz, W2a, 0, Hsz, b2a, nullptr, 0, ph, 0, Hsz, M2, Hsz, Hsz, 0, 1);

    // 3. scores[b] = h1[b] @ h2[b]^T   (B batched 256x256x200, NT)
    gemm_k<false,true><<<dim3(4, 4, Bsz), 256>>>(
        ph, LsH, Hsz, ph + BLH, LsH, Hsz, nullptr, nullptr, 0,
        psc, LL, Lsz, Lsz, Lsz, Hsz, 0, 0);

    // 4. maxima + exp stage
    rowmax_k<<<(unsigned)(BL / 8), 256>>>();
    colmax_k<<<Bsz, Lsz>>>();
    softpre_k<<<Bsz, Lsz>>>();
    rowsum_k<<<(unsigned)(BL / 8), 256>>>();

    // 5. alphas[b] = diag(rsa) * (ea^T @ e1)  -> g_ab second half  (TN)
    gemm_k<true,false><<<dim3(5, 4, Bsz), 256>>>(
        pea, LL, Lsz, pe, LsE, Esz, nullptr, prsa, Lsz,
        pab + BLE, LsE, Esz, Lsz, Esz, Lsz, 0, 0);
    //    betas[b]  = diag(rsb) * (eb @ e2)   -> g_ab first half   (NN)
    gemm_k<false,false><<<dim3(5, 4, Bsz), 256>>>(
        psc, LL, Lsz, pe + BLE, LsE, Esz, nullptr, prsb, Lsz,
        pab, LsE, Esz, Lsz, Esz, Lsz, 0, 0);

    // 6. compare_ff on concat([e; ab]) via two accumulate passes (K=600)
    gemm_k<false,false><<<dim3(4, M2 / 64, 1), 256>>>(
        pe, 0, Esz, W1c, 0, Hsz, nullptr, nullptr, 0, pta, 0, Hsz, M2, Hsz, Esz, 0, 0);
    gemm_k<false,false><<<dim3(4, M2 / 64, 1), 256>>>(
        pab, 0, Esz, W1c + (long)Esz * Hsz, 0, Hsz, b1c, nullptr, 0,
        pta, 0, Hsz, M2, Hsz, Esz, 1, 1);
    //    layer 2 with mask folded into epilogue
    gemm_k<false,false><<<dim3(4, M2 / 64, 1), 256>>>(
        pta, 0, Hsz, W2c, 0, Hsz, b2c, pmask, 0, ph, 0, Hsz, M2, Hsz, Hsz, 0, 1);

    // 7. masked sums over L -> v1,v2 ; aggregate head
    colsum_k<<<2 * Bsz, 256>>>();
    vcat_k<<<(Bsz * 2 * Hsz + 255) / 256, 256>>>();
    gemm_k<false,false><<<dim3(4, Bsz / 64, 1), 256>>>(
        pvcat, 0, 2 * Hsz, W1g, 0, Hsz, b1g, nullptr, 0,
        pu, 0, Hsz, Bsz, Hsz, 2 * Hsz, 0, 1);
    final_k<<<Bsz, 64>>>(W2g, b2g, out);
}

// round 2
// speedup vs baseline: 1.4871x; 1.4871x over previous
#include <cuda_runtime.h>

// Problem constants
#define Bsz 512
#define Lsz 256
#define Esz 300
#define Hsz 200
constexpr long BL  = (long)Bsz * Lsz;      // 131072
constexpr long BLE = BL * Esz;             // 39,321,600
constexpr long BLH = BL * Hsz;             // 26,214,400
constexpr long LL  = (long)Lsz * Lsz;      // 65536
constexpr long BLL = BL * Lsz;             // 33,554,432

// ---------------- device scratch (static, no runtime allocation) -------------
__device__ float g_e[2 * BLE];     // [e1 ; e2]          (2*BL x 300)
__device__ float g_ta[2 * BLH];    // temp hidden       (2*BL x 200)
__device__ float g_h[2 * BLH];     // attend_ff / compare out (2*BL x 200)
__device__ float g_scores[BLL];    // e scores, later eb (B x 256 x 256)
__device__ float g_ea[BLL];        // ea (unnormalized)
__device__ float g_ab[2 * BLE];    // [betas ; alphas]   (2*BL x 300)
__device__ float g_mask[2 * BL];   // [mask1 ; mask2]
__device__ float g_rowmax[BL];
__device__ float g_colmax[BL];
__device__ float g_rsa[BL];        // mask2 / d_alpha (per (b,j))
__device__ float g_rsb[BL];        // mask1 / d_beta  (per (b,i))
__device__ float g_v[2 * Bsz * Hsz];
__device__ float g_vcat[Bsz * 2 * Hsz];
__device__ float g_u[Bsz * Hsz];

// ---------------- 128x128x16 tiled GEMM, 8x8 microtile -----------------------
// C[bz][m,n] = epi( sum_k A(m,k) * B(k,n) )
// TA=false: A[m,k] = A[m*lda + k]   TA=true: A[m,k] = A[k*lda + m]
// TB=false: B[k,n] = B[k*ldb + n]   TB=true: B[k,n] = B[n*ldb + k]
// epilogue: v = acc (+ C if accum) (+ bias[n]) ; relu ; * rowscale[bz*sRS + m]
// Requires: M % 128 == 0; N, K, lda, ldb divisible by 4 (true everywhere).
template <bool TA, bool TB>
__global__ __launch_bounds__(256, 2)
void gemm_k(const float* __restrict__ A, long sA, int lda,
            const float* __restrict__ Bw, long sB, int ldb,
            const float* __restrict__ bias,
            const float* __restrict__ rs, int sRS,
            float* __restrict__ C, long sC, int ldc,
            int M, int N, int K, int accum, int relu)
{
    __shared__ float As[16][132];
    __shared__ float Bs[16][132];
    int bz = blockIdx.z;
    const float* Ab = A + (long)bz * sA;
    const float* Bb = Bw + (long)bz * sB;
    float* Cb = C + (long)bz * sC;
    int m0 = blockIdx.y * 128, n0 = blockIdx.x * 128;
    int tid = threadIdx.x;
    int tx = tid & 15, ty = tid >> 4;   // 16 x 16 compute layout

    float acc[8][8];
#pragma unroll
    for (int i = 0; i < 8; i++)
#pragma unroll
        for (int j = 0; j < 8; j++) acc[i][j] = 0.f;

    for (int k0 = 0; k0 < K; k0 += 16) {
        // ---- load A tile -> As[k][m]
        if (!TA) {
            // row-major: rows of 16 consecutive k. 128 rows x 4 float4.
            int row = tid >> 2;
            int kk = (tid & 3) * 4;
            float4 v;
#pragma unroll
            for (int it = 0; it < 2; it++) {
                int m = row + it * 64;
                if (k0 + kk < K)
                    v = *(const float4*)&Ab[(long)(m0 + m) * lda + (k0 + kk)];
                else
                    v = make_float4(0.f, 0.f, 0.f, 0.f);
                As[kk + 0][m] = v.x; As[kk + 1][m] = v.y;
                As[kk + 2][m] = v.z; As[kk + 3][m] = v.w;
            }
        } else {
            // A[m,k] = Ab[k*lda + m]: m contiguous -> direct float4
            int kk = tid >> 5;
            int m4 = (tid & 31) * 4;
            float4 v;
#pragma unroll
            for (int it = 0; it < 2; it++) {
                int k = kk + it * 8;
                if (k0 + k < K)
                    v = *(const float4*)&Ab[(long)(k0 + k) * lda + (m0 + m4)];
                else
                    v = make_float4(0.f, 0.f, 0.f, 0.f);
                *(float4*)&As[k][m4] = v;
            }
        }
        // ---- load B tile -> Bs[k][n]
        if (!TB) {
            int kk = tid >> 5;
            int n4 = (tid & 31) * 4;
            float4 v;
#pragma unroll
            for (int it = 0; it < 2; it++) {
                int k = kk + it * 8;
                if (k0 + k < K && n0 + n4 < N)
                    v = *(const float4*)&Bb[(long)(k0 + k) * ldb + (n0 + n4)];
                else
                    v = make_float4(0.f, 0.f, 0.f, 0.f);
                *(float4*)&Bs[k][n4] = v;
            }
        } else {
            // B[k,n] = Bb[n*ldb + k]: k contiguous per n-row
            int nrow = tid >> 2;
            int kk = (tid & 3) * 4;
            float4 v;
#pragma unroll
            for (int it = 0; it < 2; it++) {
                int n = nrow + it * 64;
                if (k0 + kk < K && n0 + n < N)
                    v = *(const float4*)&Bb[(long)(n0 + n) * ldb + (k0 + kk)];
                else
                    v = make_float4(0.f, 0.f, 0.f, 0.f);
                Bs[kk + 0][n] = v.x; Bs[kk + 1][n] = v.y;
                Bs[kk + 2][n] = v.z; Bs[kk + 3][n] = v.w;
            }
        }
        __syncthreads();
#pragma unroll
        for (int k = 0; k < 16; k++) {
            float4 a0 = *(const float4*)&As[k][ty * 4];
            float4 a1 = *(const float4*)&As[k][64 + ty * 4];
            float4 b0 = *(const float4*)&Bs[k][tx * 4];
            float4 b1 = *(const float4*)&Bs[k][64 + tx * 4];
            float a[8] = {a0.x, a0.y, a0.z, a0.w, a1.x, a1.y, a1.z, a1.w};
            float b[8] = {b0.x, b0.y, b0.z, b0.w, b1.x, b1.y, b1.z, b1.w};
#pragma unroll
            for (int i = 0; i < 8; i++)
#pragma unroll
                for (int j = 0; j < 8; j++) acc[i][j] += a[i] * b[j];
        }
        __syncthreads();
    }

#pragma unroll
    for (int i = 0; i < 8; i++) {
        int m = m0 + ((i < 4) ? (ty * 4 + i) : (64 + ty * 4 + (i - 4)));
        float rsv = rs ? rs[(long)bz * sRS + m] : 1.f;
#pragma unroll
        for (int j = 0; j < 8; j++) {
            int n = n0 + ((j < 4) ? (tx * 4 + j) : (64 + tx * 4 + (j - 4)));
            if (n < N) {
                long idx = (long)m * ldc + n;
                float v = acc[i][j];
                if (accum) v += Cb[idx];
                if (bias) v += bias[n];
                if (relu) v = fmaxf(v, 0.f);
                v *= rsv;
                Cb[idx] = v;
            }
        }
    }
}

// ---------------- small helper kernels ---------------------------------------
__global__ void gather_k(const float* __restrict__ emb,
                         const int* __restrict__ s1, const int* __restrict__ s2)
{
    long row = blockIdx.x;                 // 0 .. 2*BL-1
    long r = row < BL ? row : row - BL;
    int tok = (row < BL) ? s1[r] : s2[r];
    const float* src = emb + (long)tok * Esz;
    float* dst = g_e + row * Esz;
    for (int t = threadIdx.x; t < Esz; t += blockDim.x) dst[t] = src[t];
}

__global__ void mask_k(const int* __restrict__ len1, const int* __restrict__ len2)
{
    long idx = (long)blockIdx.x * blockDim.x + threadIdx.x;
    if (idx >= 2 * BL) return;
    int seq = (int)(idx / BL);
    long r = idx % BL;
    int b = (int)(r / Lsz), l = (int)(r % Lsz);
    int len = seq ? len2[b] : len1[b];
    g_mask[idx] = (l < len) ? 1.f : 0.f;
}

__global__ void rowmax_k()
{
    long row = (long)blockIdx.x * 8 + (threadIdx.x >> 5);   // 0..BL-1
    int lane = threadIdx.x & 31;
    const float* p = g_scores + row * Lsz;
    float m = -1e30f;
    for (int j = lane; j < Lsz; j += 32) m = fmaxf(m, p[j]);
#pragma unroll
    for (int o = 16; o; o >>= 1) m = fmaxf(m, __shfl_xor_sync(~0u, m, o));
    if (lane == 0) g_rowmax[row] = m;
}

__global__ void colmax_k()
{
    int b = blockIdx.x;
    int j = threadIdx.x;
    const float* p = g_scores + (long)b * LL;
    float m = -1e30f;
    for (int i = 0; i < Lsz; i++) m = fmaxf(m, p[(long)i * Lsz + j]);
    g_colmax[(long)b * Lsz + j] = m;
}

// ea[b,i,j] = exp(e - rowmax[b,j]) * mask1[b,i]   -> g_ea, col-sum -> rsa
// eb[b,i,j] = exp(e - colmax[b,i]) * mask2[b,j]   -> in-place over g_scores
__global__ void softpre_k()
{
    int b = blockIdx.x;
    int j = threadIdx.x;
    long base = (long)b * LL;
    float rm  = g_rowmax[(long)b * Lsz + j];
    float m2j = g_mask[BL + (long)b * Lsz + j];
    float da = 0.f;
    for (int i = 0; i < Lsz; i++) {
        long idx = base + (long)i * Lsz + j;
        float e = g_scores[idx];
        float m1i = g_mask[(long)b * Lsz + i];
        float cm  = g_colmax[(long)b * Lsz + i];
        float ea = __expf(e - rm) * m1i;
        da += ea;
        g_ea[idx] = ea;
        g_scores[idx] = __expf(e - cm) * m2j;
    }
    g_rsa[(long)b * Lsz + j] = m2j / da;
}

__global__ void rowsum_k()   // d_beta row sums over eb (= g_scores), -> rsb
{
    long row = (long)blockIdx.x * 8 + (threadIdx.x >> 5);
    int lane = threadIdx.x & 31;
    const float* p = g_scores + row * Lsz;
    float s = 0.f;
    for (int j = lane; j < Lsz; j += 32) s += p[j];
#pragma unroll
    for (int o = 16; o; o >>= 1) s += __shfl_xor_sync(~0u, s, o);
    if (lane == 0) g_rsb[row] = g_mask[row] / s;
}

__global__ void colsum_k()   // v[b2,h] = sum_l h[b2,l,h]  (mask already applied)
{
    int b2 = blockIdx.x;     // 0 .. 2B-1
    int h = threadIdx.x;
    if (h >= Hsz) return;
    const float* p = g_h + (long)b2 * Lsz * Hsz;
    float s = 0.f;
    for (int l = 0; l < Lsz; l++) s += p[(long)l * Hsz + h];
    g_v[(long)b2 * Hsz + h] = s;
}

__global__ void vcat_k()
{
    int idx = blockIdx.x * blockDim.x + threadIdx.x;   // B*400
    if (idx >= Bsz * 2 * Hsz) return;
    int b = idx / (2 * Hsz), c = idx % (2 * Hsz);
    float v = (c < Hsz) ? g_v[(long)b * Hsz + c]
                        : g_v[(long)(Bsz + b) * Hsz + (c - Hsz)];
    g_vcat[idx] = v;
}

__global__ void final_k(const float* __restrict__ W2g,
                        const float* __restrict__ b2g, float* __restrict__ out)
{
    int b = blockIdx.x;
    int o = threadIdx.x >> 5;       // 0 or 1 (64 threads)
    int lane = threadIdx.x & 31;
    const float* u = g_u + (long)b * Hsz;
    float s = 0.f;
    for (int h = lane; h < Hsz; h += 32) s += u[h] * W2g[h * 2 + o];
#pragma unroll
    for (int off = 16; off; off >>= 1) s += __shfl_xor_sync(~0u, s, off);
    if (lane == 0) out[b * 2 + o] = s + b2g[o];
}

// ---------------- launch -----------------------------------------------------
extern "C" void kernel_launch(void* const* d_in, const int* in_sizes, int n_in,
                              void* d_out, int out_size)
{
    const float* emb = (const float*)d_in[0];
    const float* W1a = (const float*)d_in[1];
    const float* b1a = (const float*)d_in[2];
    const float* W2a = (const float*)d_in[3];
    const float* b2a = (const float*)d_in[4];
    const float* W1c = (const float*)d_in[5];
    const float* b1c = (const float*)d_in[6];
    const float* W2c = (const float*)d_in[7];
    const float* b2c = (const float*)d_in[8];
    const float* W1g = (const float*)d_in[9];
    const float* b1g = (const float*)d_in[10];
    const float* W2g = (const float*)d_in[11];
    const float* b2g = (const float*)d_in[12];
    const int* s1   = (const int*)d_in[13];
    const int* s2   = (const int*)d_in[14];
    const int* len1 = (const int*)d_in[15];
    const int* len2 = (const int*)d_in[16];
    float* out = (float*)d_out;

    float *pe, *pta, *ph, *psc, *pea, *pab, *pmask, *prsa, *prsb, *pvcat, *pu;
    cudaGetSymbolAddress((void**)&pe,   g_e);
    cudaGetSymbolAddress((void**)&pta,  g_ta);
    cudaGetSymbolAddress((void**)&ph,   g_h);
    cudaGetSymbolAddress((void**)&psc,  g_scores);
    cudaGetSymbolAddress((void**)&pea,  g_ea);
    cudaGetSymbolAddress((void**)&pab,  g_ab);
    cudaGetSymbolAddress((void**)&pmask,g_mask);
    cudaGetSymbolAddress((void**)&prsa, g_rsa);
    cudaGetSymbolAddress((void**)&prsb, g_rsb);
    cudaGetSymbolAddress((void**)&pvcat,g_vcat);
    cudaGetSymbolAddress((void**)&pu,   g_u);

    const int M2 = (int)(2 * BL);          // 262144
    const long LsH = (long)Lsz * Hsz;
    const long LsE = (long)Lsz * Esz;

    // 1. embedding gather + masks
    gather_k<<<(unsigned)(2 * BL), 128>>>(emb, s1, s2);
    mask_k<<<(unsigned)((2 * BL + 255) / 256), 256>>>(len1, len2);

    // 2. attend_ff: h = relu(relu(e@W1a+b1a)@W2a+b2a)   (M=262144)
    gemm_k<false,false><<<dim3(2, M2 / 128, 1), 256>>>(
        pe, 0, Esz, W1a, 0, Hsz, b1a, nullptr, 0, pta, 0, Hsz, M2, Hsz, Esz, 0, 1);
    gemm_k<false,false><<<dim3(2, M2 / 128, 1), 256>>>(
        pta, 0, Hsz, W2a, 0, Hsz, b2a, nullptr, 0, ph, 0, Hsz, M2, Hsz, Hsz, 0, 1);

    // 3. scores[b] = h1[b] @ h2[b]^T   (B batched 256x256x200, NT)
    gemm_k<false,true><<<dim3(2, 2, Bsz), 256>>>(
        ph, LsH, Hsz, ph + BLH, LsH, Hsz, nullptr, nullptr, 0,
        psc, LL, Lsz, Lsz, Lsz, Hsz, 0, 0);

    // 4. maxima + exp stage
    rowmax_k<<<(unsigned)(BL / 8), 256>>>();
    colmax_k<<<Bsz, Lsz>>>();
    softpre_k<<<Bsz, Lsz>>>();
    rowsum_k<<<(unsigned)(BL / 8), 256>>>();

    // 5. alphas[b] = diag(rsa) * (ea^T @ e1)  -> g_ab second half  (TN)
    gemm_k<true,false><<<dim3(3, 2, Bsz), 256>>>(
        pea, LL, Lsz, pe, LsE, Esz, nullptr, prsa, Lsz,
        pab + BLE, LsE, Esz, Lsz, Esz, Lsz, 0, 0);
    //    betas[b]  = diag(rsb) * (eb @ e2)   -> g_ab first half   (NN)
    gemm_k<false,false><<<dim3(3, 2, Bsz), 256>>>(
        psc, LL, Lsz, pe + BLE, LsE, Esz, nullptr, prsb, Lsz,
        pab, LsE, Esz, Lsz, Esz, Lsz, 0, 0);

    // 6. compare_ff on concat([e; ab]) via two accumulate passes (K=600)
    gemm_k<false,false><<<dim3(2, M2 / 128, 1), 256>>>(
        pe, 0, Esz, W1c, 0, Hsz, nullptr, nullptr, 0, pta, 0, Hsz, M2, Hsz, Esz, 0, 0);
    gemm_k<false,false><<<dim3(2, M2 / 128, 1), 256>>>(
        pab, 0, Esz, W1c + (long)Esz * Hsz, 0, Hsz, b1c, nullptr, 0,
        pta, 0, Hsz, M2, Hsz, Esz, 1, 1);
    //    layer 2 with mask folded into epilogue
    gemm_k<false,false><<<dim3(2, M2 / 128, 1), 256>>>(
        pta, 0, Hsz, W2c, 0, Hsz, b2c, pmask, 0, ph, 0, Hsz, M2, Hsz, Hsz, 0, 1);

    // 7. masked sums over L -> v1,v2 ; aggregate head
    colsum_k<<<2 * Bsz, 256>>>();
    vcat_k<<<(Bsz * 2 * Hsz + 255) / 256, 256>>>();
    gemm_k<false,false><<<dim3(2, Bsz / 128, 1), 256>>>(
        pvcat, 0, 2 * Hsz, W1g, 0, Hsz, b1g, nullptr, 0,
        pu, 0, Hsz, Bsz, Hsz, 2 * Hsz, 0, 1);
    final_k<<<Bsz, 64>>>(W2g, b2g, out);
}

// round 3
// speedup vs baseline: 1.9975x; 1.3433x over previous
#include <cuda_runtime.h>

// Problem constants
#define Bsz 512
#define Lsz 256
#define Esz 300
#define Hsz 200
#define VOC 50000
constexpr long BL  = (long)Bsz * Lsz;      // 131072
constexpr long BLE = BL * Esz;             // 39,321,600
constexpr long BLH = BL * Hsz;             // 26,214,400
constexpr long LL  = (long)Lsz * Lsz;      // 65536
constexpr long BLL = BL * Lsz;             // 33,554,432

// ---------------- device scratch (static, no runtime allocation) -------------
__device__ float g_e[2 * BLE];     // [e1 ; e2]          (2*BL x 300)
__device__ float g_ta[2 * BLH];    // compare hidden accumulator (2*BL x 200)
__device__ float g_h[2 * BLH];     // attend_ff out (gathered) / compare out
__device__ float g_scores[BLL];    // e scores, later eb (B x 256 x 256)
__device__ float g_ea[BLL];        // ea (unnormalized)
__device__ float g_ab[2 * BLE];    // [betas ; alphas]   (2*BL x 300)
__device__ float g_mask[2 * BL];   // [mask1 ; mask2]
__device__ float g_rowmax[BL];
__device__ float g_colmax[BL];
__device__ float g_rsa[BL];        // mask2 / d_alpha (per (b,j))
__device__ float g_rsb[BL];        // mask1 / d_beta  (per (b,i))
__device__ float g_v[2 * Bsz * Hsz];
__device__ float g_vcat[Bsz * 2 * Hsz];
__device__ float g_u[Bsz * Hsz];
// per-vocab precompute
__device__ float g_tv[(long)VOC * Hsz];   // vocab attend L1 temp
__device__ float g_hv[(long)VOC * Hsz];   // vocab attend_ff output
__device__ float g_cv[(long)VOC * Hsz];   // vocab e@W1c (top half, no bias)

// ---------------- 128x128x16 tiled GEMM, 8x8 microtile -----------------------
// C[bz][m,n] = epi( sum_k A(m,k) * B(k,n) )
// TA=false: A[m,k] = A[m*lda + k]   TA=true: A[m,k] = A[k*lda + m]
// TB=false: B[k,n] = B[k*ldb + n]   TB=true: B[k,n] = B[n*ldb + k]
// epilogue: v = acc (+ C if accum) (+ bias[n]) ; relu ; * rowscale[bz*sRS + m]
// N, K, M arbitrary (guarded); lda/ldb/N/K divisible by 4.
template <bool TA, bool TB>
__global__ __launch_bounds__(256, 2)
void gemm_k(const float* __restrict__ A, long sA, int lda,
            const float* __restrict__ Bw, long sB, int ldb,
            const float* __restrict__ bias,
            const float* __restrict__ rs, int sRS,
            float* __restrict__ C, long sC, int ldc,
            int M, int N, int K, int accum, int relu)
{
    __shared__ float As[16][132];
    __shared__ float Bs[16][132];
    int bz = blockIdx.z;
    const float* Ab = A + (long)bz * sA;
    const float* Bb = Bw + (long)bz * sB;
    float* Cb = C + (long)bz * sC;
    int m0 = blockIdx.y * 128, n0 = blockIdx.x * 128;
    int tid = threadIdx.x;
    int tx = tid & 15, ty = tid >> 4;   // 16 x 16 compute layout

    float acc[8][8];
#pragma unroll
    for (int i = 0; i < 8; i++)
#pragma unroll
        for (int j = 0; j < 8; j++) acc[i][j] = 0.f;

    for (int k0 = 0; k0 < K; k0 += 16) {
        // ---- load A tile -> As[k][m]
        if (!TA) {
            int row = tid >> 2;
            int kk = (tid & 3) * 4;
            float4 v;
#pragma unroll
            for (int it = 0; it < 2; it++) {
                int m = row + it * 64;
                if (k0 + kk < K && m0 + m < M)
                    v = *(const float4*)&Ab[(long)(m0 + m) * lda + (k0 + kk)];
                else
                    v = make_float4(0.f, 0.f, 0.f, 0.f);
                As[kk + 0][m] = v.x; As[kk + 1][m] = v.y;
                As[kk + 2][m] = v.z; As[kk + 3][m] = v.w;
            }
        } else {
            int kk = tid >> 5;
            int m4 = (tid & 31) * 4;
            float4 v;
#pragma unroll
            for (int it = 0; it < 2; it++) {
                int k = kk + it * 8;
                if (k0 + k < K && m0 + m4 < M)
                    v = *(const float4*)&Ab[(long)(k0 + k) * lda + (m0 + m4)];
                else
                    v = make_float4(0.f, 0.f, 0.f, 0.f);
                *(float4*)&As[k][m4] = v;
            }
        }
        // ---- load B tile -> Bs[k][n]
        if (!TB) {
            int kk = tid >> 5;
            int n4 = (tid & 31) * 4;
            float4 v;
#pragma unroll
            for (int it = 0; it < 2; it++) {
                int k = kk + it * 8;
                if (k0 + k < K && n0 + n4 < N)
                    v = *(const float4*)&Bb[(long)(k0 + k) * ldb + (n0 + n4)];
                else
                    v = make_float4(0.f, 0.f, 0.f, 0.f);
                *(float4*)&Bs[k][n4] = v;
            }
        } else {
            int nrow = tid >> 2;
            int kk = (tid & 3) * 4;
            float4 v;
#pragma unroll
            for (int it = 0; it < 2; it++) {
                int n = nrow + it * 64;
                if (k0 + kk < K && n0 + n < N)
                    v = *(const float4*)&Bb[(long)(n0 + n) * ldb + (k0 + kk)];
                else
                    v = make_float4(0.f, 0.f, 0.f, 0.f);
                Bs[kk + 0][n] = v.x; Bs[kk + 1][n] = v.y;
                Bs[kk + 2][n] = v.z; Bs[kk + 3][n] = v.w;
            }
        }
        __syncthreads();
#pragma unroll
        for (int k = 0; k < 16; k++) {
            float4 a0 = *(const float4*)&As[k][ty * 4];
            float4 a1 = *(const float4*)&As[k][64 + ty * 4];
            float4 b0 = *(const float4*)&Bs[k][tx * 4];
            float4 b1 = *(const float4*)&Bs[k][64 + tx * 4];
            float a[8] = {a0.x, a0.y, a0.z, a0.w, a1.x, a1.y, a1.z, a1.w};
            float b[8] = {b0.x, b0.y, b0.z, b0.w, b1.x, b1.y, b1.z, b1.w};
#pragma unroll
            for (int i = 0; i < 8; i++)
#pragma unroll
                for (int j = 0; j < 8; j++) acc[i][j] += a[i] * b[j];
        }
        __syncthreads();
    }

#pragma unroll
    for (int i = 0; i < 8; i++) {
        int m = m0 + ((i < 4) ? (ty * 4 + i) : (64 + ty * 4 + (i - 4)));
        if (m >= M) continue;
        float rsv = rs ? rs[(long)bz * sRS + m] : 1.f;
#pragma unroll
        for (int j = 0; j < 8; j++) {
            int n = n0 + ((j < 4) ? (tx * 4 + j) : (64 + tx * 4 + (j - 4)));
            if (n < N) {
                long idx = (long)m * ldc + n;
                float v = acc[i][j];
                if (accum) v += Cb[idx];
                if (bias) v += bias[n];
                if (relu) v = fmaxf(v, 0.f);
                v *= rsv;
                Cb[idx] = v;
            }
        }
    }
}

// ---------------- helper kernels ---------------------------------------------
// One block per token row: gather e (75 float4), h (50 float4), cv (50 float4)
__global__ void gather_all_k(const float* __restrict__ emb,
                             const int* __restrict__ s1, const int* __restrict__ s2)
{
    long row = blockIdx.x;                 // 0 .. 2*BL-1
    long r = row < BL ? row : row - BL;
    int tok = (row < BL) ? s1[r] : s2[r];
    int t = threadIdx.x;                   // 128 threads
    const float4* esrc = (const float4*)(emb + (long)tok * Esz);
    float4* edst = (float4*)(g_e + row * Esz);
    if (t < 75) edst[t] = esrc[t];
    const float4* hsrc = (const float4*)(g_hv + (long)tok * Hsz);
    float4* hdst = (float4*)(g_h + row * Hsz);
    if (t < 50) hdst[t] = hsrc[t];
    const float4* csrc = (const float4*)(g_cv + (long)tok * Hsz);
    float4* cdst = (float4*)(g_ta + row * Hsz);
    if (t >= 64 && t < 114) cdst[t - 64] = csrc[t - 64];
}

__global__ void mask_k(const int* __restrict__ len1, const int* __restrict__ len2)
{
    long idx = (long)blockIdx.x * blockDim.x + threadIdx.x;
    if (idx >= 2 * BL) return;
    int seq = (int)(idx / BL);
    long r = idx % BL;
    int b = (int)(r / Lsz), l = (int)(r % Lsz);
    int len = seq ? len2[b] : len1[b];
    g_mask[idx] = (l < len) ? 1.f : 0.f;
}

__global__ void rowmax_k()
{
    long row = (long)blockIdx.x * 8 + (threadIdx.x >> 5);   // 0..BL-1
    int lane = threadIdx.x & 31;
    const float* p = g_scores + row * Lsz;
    float m = -1e30f;
    for (int j = lane; j < Lsz; j += 32) m = fmaxf(m, p[j]);
#pragma unroll
    for (int o = 16; o; o >>= 1) m = fmaxf(m, __shfl_xor_sync(~0u, m, o));
    if (lane == 0) g_rowmax[row] = m;
}

__global__ void colmax_k()    // max over i per column j, 1024 thr / 4 slices
{
    __shared__ float sm[1024];
    int b = blockIdx.x;
    int j = threadIdx.x & 255, s = threadIdx.x >> 8;
    const float* p = g_scores + (long)b * LL;
    float m = -1e30f;
#pragma unroll 4
    for (int i = s * 64; i < s * 64 + 64; i++) m = fmaxf(m, p[(long)i * Lsz + j]);
    sm[threadIdx.x] = m;
    __syncthreads();
    if (s == 0) {
        m = fmaxf(fmaxf(sm[j], sm[j + 256]), fmaxf(sm[j + 512], sm[j + 768]));
        g_colmax[(long)b * Lsz + j] = m;
    }
}

// ea[b,i,j] = exp(e - rowmax[b,j]) * mask1[b,i]   -> g_ea, col-sum -> rsa
// eb[b,i,j] = exp(e - colmax[b,i]) * mask2[b,j]   -> in-place over g_scores
__global__ void softpre_k()
{
    __shared__ float sm[1024];
    int b = blockIdx.x;
    int j = threadIdx.x & 255, s = threadIdx.x >> 8;
    long base = (long)b * LL;
    float rm  = g_rowmax[(long)b * Lsz + j];
    float m2j = g_mask[BL + (long)b * Lsz + j];
    float da = 0.f;
    for (int i = s * 64; i < s * 64 + 64; i++) {
        long idx = base + (long)i * Lsz + j;
        float e = g_scores[idx];
        float m1i = g_mask[(long)b * Lsz + i];
        float cm  = g_colmax[(long)b * Lsz + i];
        float ea = __expf(e - rm) * m1i;
        da += ea;
        g_ea[idx] = ea;
        g_scores[idx] = __expf(e - cm) * m2j;
    }
    sm[threadIdx.x] = da;
    __syncthreads();
    if (s == 0)
        g_rsa[(long)b * Lsz + j] = m2j / (sm[j] + sm[j + 256] + sm[j + 512] + sm[j + 768]);
}

__global__ void rowsum_k()   // d_beta row sums over eb (= g_scores), -> rsb
{
    long row = (long)blockIdx.x * 8 + (threadIdx.x >> 5);
    int lane = threadIdx.x & 31;
    const float* p = g_scores + row * Lsz;
    float s = 0.f;
    for (int j = lane; j < Lsz; j += 32) s += p[j];
#pragma unroll
    for (int o = 16; o; o >>= 1) s += __shfl_xor_sync(~0u, s, o);
    if (lane == 0) g_rsb[row] = g_mask[row] / s;
}

__global__ void colsum_k()   // v[b2,h] = sum_l h[b2,l,h], 1024 thr / 4 slices
{
    __shared__ float sm[1024];
    int b2 = blockIdx.x;     // 0 .. 2B-1
    int h = threadIdx.x & 255, s = threadIdx.x >> 8;
    float acc = 0.f;
    if (h < Hsz) {
        const float* p = g_h + (long)b2 * Lsz * Hsz;
#pragma unroll 4
        for (int l = s * 64; l < s * 64 + 64; l++) acc += p[(long)l * Hsz + h];
    }
    sm[threadIdx.x] = acc;
    __syncthreads();
    if (s == 0 && h < Hsz)
        g_v[(long)b2 * Hsz + h] = sm[h] + sm[h + 256] + sm[h + 512] + sm[h + 768];
}

__global__ void vcat_k()
{
    int idx = blockIdx.x * blockDim.x + threadIdx.x;   // B*400
    if (idx >= Bsz * 2 * Hsz) return;
    int b = idx / (2 * Hsz), c = idx % (2 * Hsz);
    float v = (c < Hsz) ? g_v[(long)b * Hsz + c]
                        : g_v[(long)(Bsz + b) * Hsz + (c - Hsz)];
    g_vcat[idx] = v;
}

__global__ void final_k(const float* __restrict__ W2g,
                        const float* __restrict__ b2g, float* __restrict__ out)
{
    int b = blockIdx.x;
    int o = threadIdx.x >> 5;       // 0 or 1 (64 threads)
    int lane = threadIdx.x & 31;
    const float* u = g_u + (long)b * Hsz;
    float s = 0.f;
    for (int h = lane; h < Hsz; h += 32) s += u[h] * W2g[h * 2 + o];
#pragma unroll
    for (int off = 16; off; off >>= 1) s += __shfl_xor_sync(~0u, s, off);
    if (lane == 0) out[b * 2 + o] = s + b2g[o];
}

// ---------------- launch -----------------------------------------------------
extern "C" void kernel_launch(void* const* d_in, const int* in_sizes, int n_in,
                              void* d_out, int out_size)
{
    const float* emb = (const float*)d_in[0];
    const float* W1a = (const float*)d_in[1];
    const float* b1a = (const float*)d_in[2];
    const float* W2a = (const float*)d_in[3];
    const float* b2a = (const float*)d_in[4];
    const float* W1c = (const float*)d_in[5];
    const float* b1c = (const float*)d_in[6];
    const float* W2c = (const float*)d_in[7];
    const float* b2c = (const float*)d_in[8];
    const float* W1g = (const float*)d_in[9];
    const float* b1g = (const float*)d_in[10];
    const float* W2g = (const float*)d_in[11];
    const float* b2g = (const float*)d_in[12];
    const int* s1   = (const int*)d_in[13];
    const int* s2   = (const int*)d_in[14];
    const int* len1 = (const int*)d_in[15];
    const int* len2 = (const int*)d_in[16];
    float* out = (float*)d_out;

    float *pe, *pta, *ph, *psc, *pea, *pab, *pmask, *prsa, *prsb, *pvcat, *pu;
    float *ptv, *phv, *pcv;
    cudaGetSymbolAddress((void**)&pe,   g_e);
    cudaGetSymbolAddress((void**)&pta,  g_ta);
    cudaGetSymbolAddress((void**)&ph,   g_h);
    cudaGetSymbolAddress((void**)&psc,  g_scores);
    cudaGetSymbolAddress((void**)&pea,  g_ea);
    cudaGetSymbolAddress((void**)&pab,  g_ab);
    cudaGetSymbolAddress((void**)&pmask,g_mask);
    cudaGetSymbolAddress((void**)&prsa, g_rsa);
    cudaGetSymbolAddress((void**)&prsb, g_rsb);
    cudaGetSymbolAddress((void**)&pvcat,g_vcat);
    cudaGetSymbolAddress((void**)&pu,   g_u);
    cudaGetSymbolAddress((void**)&ptv,  g_tv);
    cudaGetSymbolAddress((void**)&phv,  g_hv);
    cudaGetSymbolAddress((void**)&pcv,  g_cv);

    const int M2 = (int)(2 * BL);          // 262144
    const long LsH = (long)Lsz * Hsz;
    const long LsE = (long)Lsz * Esz;
    const unsigned MV = (VOC + 127) / 128; // 391 tiles for vocab GEMMs

    // 1. per-vocab precompute: attend_ff and compare-L1 top half
    gemm_k<false,false><<<dim3(2, MV, 1), 256>>>(
        emb, 0, Esz, W1a, 0, Hsz, b1a, nullptr, 0, ptv, 0, Hsz, VOC, Hsz, Esz, 0, 1);
    gemm_k<false,false><<<dim3(2, MV, 1), 256>>>(
        ptv, 0, Hsz, W2a, 0, Hsz, b2a, nullptr, 0, phv, 0, Hsz, VOC, Hsz, Hsz, 0, 1);
    gemm_k<false,false><<<dim3(2, MV, 1), 256>>>(
        emb, 0, Esz, W1c, 0, Hsz, nullptr, nullptr, 0, pcv, 0, Hsz, VOC, Hsz, Esz, 0, 0);

    // 2. gather e/h/cv into token space + masks
    gather_all_k<<<(unsigned)(2 * BL), 128>>>(emb, s1, s2);
    mask_k<<<(unsigned)((2 * BL + 255) / 256), 256>>>(len1, len2);

    // 3. scores[b] = h1[b] @ h2[b]^T   (B batched 256x256x200, NT)
    gemm_k<false,true><<<dim3(2, 2, Bsz), 256>>>(
        ph, LsH, Hsz, ph + BLH, LsH, Hsz, nullptr, nullptr, 0,
        psc, LL, Lsz, Lsz, Lsz, Hsz, 0, 0);

    // 4. maxima + exp stage
    rowmax_k<<<(unsigned)(BL / 8), 256>>>();
    colmax_k<<<Bsz, 1024>>>();
    softpre_k<<<Bsz, 1024>>>();
    rowsum_k<<<(unsigned)(BL / 8), 256>>>();

    // 5. alphas[b] = diag(rsa) * (ea^T @ e1)  -> g_ab second half  (TN)
    gemm_k<true,false><<<dim3(3, 2, Bsz), 256>>>(
        pea, LL, Lsz, pe, LsE, Esz, nullptr, prsa, Lsz,
        pab + BLE, LsE, Esz, Lsz, Esz, Lsz, 0, 0);
    //    betas[b]  = diag(rsb) * (eb @ e2)   -> g_ab first half   (NN)
    gemm_k<false,false><<<dim3(3, 2, Bsz), 256>>>(
        psc, LL, Lsz, pe + BLE, LsE, Esz, nullptr, prsb, Lsz,
        pab, LsE, Esz, Lsz, Esz, Lsz, 0, 0);

    // 6. compare_ff: pta already holds e@W1c (gathered); accumulate ab half
    gemm_k<false,false><<<dim3(2, M2 / 128, 1), 256>>>(
        pab, 0, Esz, W1c + (long)Esz * Hsz, 0, Hsz, b1c, nullptr, 0,
        pta, 0, Hsz, M2, Hsz, Esz, 1, 1);
    //    layer 2 with mask folded into epilogue
    gemm_k<false,false><<<dim3(2, M2 / 128, 1), 256>>>(
        pta, 0, Hsz, W2c, 0, Hsz, b2c, pmask, 0, ph, 0, Hsz, M2, Hsz, Hsz, 0, 1);

    // 7. masked sums over L -> v1,v2 ; aggregate head
    colsum_k<<<2 * Bsz, 1024>>>();
    vcat_k<<<(Bsz * 2 * Hsz + 255) / 256, 256>>>();
    gemm_k<false,false><<<dim3(2, Bsz / 128, 1), 256>>>(
        pvcat, 0, 2 * Hsz, W1g, 0, Hsz, b1g, nullptr, 0,
        pu, 0, Hsz, Bsz, Hsz, 2 * Hsz, 0, 1);
    final_k<<<Bsz, 64>>>(W2g, b2g, out);
}

// round 4
// speedup vs baseline: 2.0288x; 1.0157x over previous
#include <cuda_runtime.h>
#include <cstdint>

// Problem constants
#define Bsz 512
#define Lsz 256
#define Esz 300
#define Hsz 200
#define VOC 50000
constexpr long BL  = (long)Bsz * Lsz;      // 131072
constexpr long BLE = BL * Esz;             // 39,321,600
constexpr long BLH = BL * Hsz;             // 26,214,400
constexpr long LL  = (long)Lsz * Lsz;      // 65536
constexpr long BLL = BL * Lsz;             // 33,554,432

// ---------------- device scratch (static, no runtime allocation) -------------
__device__ float g_e[2 * BLE];     // [e1 ; e2]          (2*BL x 300)
__device__ float g_ta[2 * BLH];    // compare hidden accumulator (2*BL x 200)
__device__ float g_h[2 * BLH];     // attend_ff out (gathered) / compare out
__device__ float g_scores[BLL];    // e scores, later eb (B x 256 x 256)
__device__ float g_ea[BLL];        // ea (unnormalized)
__device__ float g_ab[2 * BLE];    // [betas ; alphas]   (2*BL x 300)
__device__ float g_mask[2 * BL];   // [mask1 ; mask2]
__device__ float g_rowmax[BL];
__device__ float g_colmax[BL];
__device__ float g_rsa[BL];        // mask2 / d_alpha (per (b,j))
__device__ float g_rsb[BL];        // mask1 / d_beta  (per (b,i))
__device__ float g_v[2 * Bsz * Hsz];
__device__ float g_vcat[Bsz * 2 * Hsz];
__device__ float g_u[Bsz * Hsz];
// per-vocab precompute
__device__ float g_tv[(long)VOC * Hsz];   // vocab attend L1 temp
__device__ float g_hv[(long)VOC * Hsz];   // vocab attend_ff output
__device__ float g_cv[(long)VOC * Hsz];   // vocab e@W1c (top half, no bias)

__device__ __forceinline__ float to_tf32(float x)
{
    float y;
    asm("cvt.rna.tf32.f32 %0, %1;" : "=f"(y) : "f"(x));
    return y;
}

__device__ __forceinline__ void mma_tf32(float c[4],
                                         uint32_t a0, uint32_t a1, uint32_t a2, uint32_t a3,
                                         uint32_t b0, uint32_t b1)
{
    asm volatile(
        "mma.sync.aligned.m16n8k8.row.col.f32.tf32.tf32.f32 "
        "{%0,%1,%2,%3}, {%4,%5,%6,%7}, {%8,%9}, {%0,%1,%2,%3};"
        : "+f"(c[0]), "+f"(c[1]), "+f"(c[2]), "+f"(c[3])
        : "r"(a0), "r"(a1), "r"(a2), "r"(a3), "r"(b0), "r"(b1));
}

// ---------------- 128x128x16 TF32 tensor-core GEMM ---------------------------
// C[bz][m,n] = epi( sum_k A(m,k) * B(k,n) )
// TA=false: A[m,k] = A[m*lda + k]   TA=true: A[m,k] = A[k*lda + m]
// TB=false: B[k,n] = B[k*ldb + n]   TB=true: B[k,n] = B[n*ldb + k]
// epilogue: v = acc (+ C if accum) (+ bias[n]) ; relu ; * rowscale[bz*sRS + m]
// M, N, K arbitrary (guarded); lda/ldb/N/K divisible by 4.
#define SSTR 136
template <bool TA, bool TB>
__global__ __launch_bounds__(256, 2)
void gemm_k(const float* __restrict__ A, long sA, int lda,
            const float* __restrict__ Bw, long sB, int ldb,
            const float* __restrict__ bias,
            const float* __restrict__ rs, int sRS,
            float* __restrict__ C, long sC, int ldc,
            int M, int N, int K, int accum, int relu)
{
    __shared__ float As[16][SSTR];
    __shared__ float Bs[16][SSTR];
    int bz = blockIdx.z;
    const float* Ab = A + (long)bz * sA;
    const float* Bb = Bw + (long)bz * sB;
    float* Cb = C + (long)bz * sC;
    int m0 = blockIdx.y * 128, n0 = blockIdx.x * 128;
    int tid = threadIdx.x;
    int wid = tid >> 5, lane = tid & 31;
    int wm = wid >> 2, wn = wid & 3;       // warps: 2 (m) x 4 (n)
    int g = lane >> 2, tig = lane & 3;     // groupID, thread-in-group

    float c[4][4][4];                      // [mtile][ntile][frag]
#pragma unroll
    for (int i = 0; i < 4; i++)
#pragma unroll
        for (int j = 0; j < 4; j++)
#pragma unroll
            for (int q = 0; q < 4; q++) c[i][j][q] = 0.f;

    for (int k0 = 0; k0 < K; k0 += 16) {
        // ---- load A tile -> As[k][m] (tf32-rounded)
        if (!TA) {
            int row = tid >> 2;
            int kk = (tid & 3) * 4;
            float4 v;
#pragma unroll
            for (int it = 0; it < 2; it++) {
                int m = row + it * 64;
                if (k0 + kk < K && m0 + m < M)
                    v = *(const float4*)&Ab[(long)(m0 + m) * lda + (k0 + kk)];
                else
                    v = make_float4(0.f, 0.f, 0.f, 0.f);
                As[kk + 0][m] = to_tf32(v.x); As[kk + 1][m] = to_tf32(v.y);
                As[kk + 2][m] = to_tf32(v.z); As[kk + 3][m] = to_tf32(v.w);
            }
        } else {
            int kk = tid >> 5;
            int m4 = (tid & 31) * 4;
            float4 v;
#pragma unroll
            for (int it = 0; it < 2; it++) {
                int k = kk + it * 8;
                if (k0 + k < K && m0 + m4 < M)
                    v = *(const float4*)&Ab[(long)(k0 + k) * lda + (m0 + m4)];
                else
                    v = make_float4(0.f, 0.f, 0.f, 0.f);
                v.x = to_tf32(v.x); v.y = to_tf32(v.y);
                v.z = to_tf32(v.z); v.w = to_tf32(v.w);
                *(float4*)&As[k][m4] = v;
            }
        }
        // ---- load B tile -> Bs[k][n] (tf32-rounded)
        if (!TB) {
            int kk = tid >> 5;
            int n4 = (tid & 31) * 4;
            float4 v;
#pragma unroll
            for (int it = 0; it < 2; it++) {
                int k = kk + it * 8;
                if (k0 + k < K && n0 + n4 < N)
                    v = *(const float4*)&Bb[(long)(k0 + k) * ldb + (n0 + n4)];
                else
                    v = make_float4(0.f, 0.f, 0.f, 0.f);
                v.x = to_tf32(v.x); v.y = to_tf32(v.y);
                v.z = to_tf32(v.z); v.w = to_tf32(v.w);
                *(float4*)&Bs[k][n4] = v;
            }
        } else {
            int nrow = tid >> 2;
            int kk = (tid & 3) * 4;
            float4 v;
#pragma unroll
            for (int it = 0; it < 2; it++) {
                int n = nrow + it * 64;
                if (k0 + kk < K && n0 + n < N)
                    v = *(const float4*)&Bb[(long)(n0 + n) * ldb + (k0 + kk)];
                else
                    v = make_float4(0.f, 0.f, 0.f, 0.f);
                Bs[kk + 0][n] = to_tf32(v.x); Bs[kk + 1][n] = to_tf32(v.y);
                Bs[kk + 2][n] = to_tf32(v.z); Bs[kk + 3][n] = to_tf32(v.w);
            }
        }
        __syncthreads();

#pragma unroll
        for (int s = 0; s < 2; s++) {
            int ks = s * 8;
            uint32_t af[4][4];
#pragma unroll
            for (int t = 0; t < 4; t++) {
                int m = wm * 64 + t * 16 + g;
                af[t][0] = __float_as_uint(As[ks + tig][m]);
                af[t][1] = __float_as_uint(As[ks + tig][m + 8]);
                af[t][2] = __float_as_uint(As[ks + tig + 4][m]);
                af[t][3] = __float_as_uint(As[ks + tig + 4][m + 8]);
            }
            uint32_t bf[4][2];
#pragma unroll
            for (int t = 0; t < 4; t++) {
                int n = wn * 32 + t * 8 + g;
                bf[t][0] = __float_as_uint(Bs[ks + tig][n]);
                bf[t][1] = __float_as_uint(Bs[ks + tig + 4][n]);
            }
#pragma unroll
            for (int mt = 0; mt < 4; mt++)
#pragma unroll
                for (int nt = 0; nt < 4; nt++)
                    mma_tf32(c[mt][nt], af[mt][0], af[mt][1], af[mt][2], af[mt][3],
                             bf[nt][0], bf[nt][1]);
        }
        __syncthreads();
    }

    // ---- epilogue
#pragma unroll
    for (int mt = 0; mt < 4; mt++) {
#pragma unroll
        for (int r = 0; r < 2; r++) {
            int m = m0 + wm * 64 + mt * 16 + g + r * 8;
            if (m >= M) continue;
            float rsv = rs ? rs[(long)bz * sRS + m] : 1.f;
#pragma unroll
            for (int nt = 0; nt < 4; nt++) {
#pragma unroll
                for (int q = 0; q < 2; q++) {
                    int n = n0 + wn * 32 + nt * 8 + tig * 2 + q;
                    if (n < N) {
                        long idx = (long)m * ldc + n;
                        float v = c[mt][nt][r * 2 + q];
                        if (accum) v += Cb[idx];
                        if (bias) v += bias[n];
                        if (relu) v = fmaxf(v, 0.f);
                        v *= rsv;
                        Cb[idx] = v;
                    }
                }
            }
        }
    }
}

// ---------------- helper kernels ---------------------------------------------
// One block per token row: gather e (75 float4), h (50 float4), cv (50 float4)
__global__ void gather_all_k(const float* __restrict__ emb,
                             const int* __restrict__ s1, const int* __restrict__ s2)
{
    long row = blockIdx.x;                 // 0 .. 2*BL-1
    long r = row < BL ? row : row - BL;
    int tok = (row < BL) ? s1[r] : s2[r];
    int t = threadIdx.x;                   // 128 threads
    const float4* esrc = (const float4*)(emb + (long)tok * Esz);
    float4* edst = (float4*)(g_e + row * Esz);
    if (t < 75) edst[t] = esrc[t];
    const float4* hsrc = (const float4*)(g_hv + (long)tok * Hsz);
    float4* hdst = (float4*)(g_h + row * Hsz);
    if (t < 50) hdst[t] = hsrc[t];
    const float4* csrc = (const float4*)(g_cv + (long)tok * Hsz);
    float4* cdst = (float4*)(g_ta + row * Hsz);
    if (t >= 64 && t < 114) cdst[t - 64] = csrc[t - 64];
}

__global__ void mask_k(const int* __restrict__ len1, const int* __restrict__ len2)
{
    long idx = (long)blockIdx.x * blockDim.x + threadIdx.x;
    if (idx >= 2 * BL) return;
    int seq = (int)(idx / BL);
    long r = idx % BL;
    int b = (int)(r / Lsz), l = (int)(r % Lsz);
    int len = seq ? len2[b] : len1[b];
    g_mask[idx] = (l < len) ? 1.f : 0.f;
}

__global__ void rowmax_k()
{
    long row = (long)blockIdx.x * 8 + (threadIdx.x >> 5);   // 0..BL-1
    int lane = threadIdx.x & 31;
    const float* p = g_scores + row * Lsz;
    float m = -1e30f;
    for (int j = lane; j < Lsz; j += 32) m = fmaxf(m, p[j]);
#pragma unroll
    for (int o = 16; o; o >>= 1) m = fmaxf(m, __shfl_xor_sync(~0u, m, o));
    if (lane == 0) g_rowmax[row] = m;
}

__global__ void colmax_k()    // max over i per column j, 1024 thr / 4 slices
{
    __shared__ float sm[1024];
    int b = blockIdx.x;
    int j = threadIdx.x & 255, s = threadIdx.x >> 8;
    const float* p = g_scores + (long)b * LL;
    float m = -1e30f;
#pragma unroll 4
    for (int i = s * 64; i < s * 64 + 64; i++) m = fmaxf(m, p[(long)i * Lsz + j]);
    sm[threadIdx.x] = m;
    __syncthreads();
    if (s == 0) {
        m = fmaxf(fmaxf(sm[j], sm[j + 256]), fmaxf(sm[j + 512], sm[j + 768]));
        g_colmax[(long)b * Lsz + j] = m;
    }
}

// ea[b,i,j] = exp(e - rowmax[b,j]) * mask1[b,i]   -> g_ea, col-sum -> rsa
// eb[b,i,j] = exp(e - colmax[b,i]) * mask2[b,j]   -> in-place over g_scores
__global__ void softpre_k()
{
    __shared__ float sm[1024];
    int b = blockIdx.x;
    int j = threadIdx.x & 255, s = threadIdx.x >> 8;
    long base = (long)b * LL;
    float rm  = g_rowmax[(long)b * Lsz + j];
    float m2j = g_mask[BL + (long)b * Lsz + j];
    float da = 0.f;
    for (int i = s * 64; i < s * 64 + 64; i++) {
        long idx = base + (long)i * Lsz + j;
        float e = g_scores[idx];
        float m1i = g_mask[(long)b * Lsz + i];
        float cm  = g_colmax[(long)b * Lsz + i];
        float ea = __expf(e - rm) * m1i;
        da += ea;
        g_ea[idx] = ea;
        g_scores[idx] = __expf(e - cm) * m2j;
    }
    sm[threadIdx.x] = da;
    __syncthreads();
    if (s == 0)
        g_rsa[(long)b * Lsz + j] = m2j / (sm[j] + sm[j + 256] + sm[j + 512] + sm[j + 768]);
}

__global__ void rowsum_k()   // d_beta row sums over eb (= g_scores), -> rsb
{
    long row = (long)blockIdx.x * 8 + (threadIdx.x >> 5);
    int lane = threadIdx.x & 31;
    const float* p = g_scores + row * Lsz;
    float s = 0.f;
    for (int j = lane; j < Lsz; j += 32) s += p[j];
#pragma unroll
    for (int o = 16; o; o >>= 1) s += __shfl_xor_sync(~0u, s, o);
    if (lane == 0) g_rsb[row] = g_mask[row] / s;
}

__global__ void colsum_k()   // v[b2,h] = sum_l h[b2,l,h], 1024 thr / 4 slices
{
    __shared__ float sm[1024];
    int b2 = blockIdx.x;     // 0 .. 2B-1
    int h = threadIdx.x & 255, s = threadIdx.x >> 8;
    float acc = 0.f;
    if (h < Hsz) {
        const float* p = g_h + (long)b2 * Lsz * Hsz;
#pragma unroll 4
        for (int l = s * 64; l < s * 64 + 64; l++) acc += p[(long)l * Hsz + h];
    }
    sm[threadIdx.x] = acc;
    __syncthreads();
    if (s == 0 && h < Hsz)
        g_v[(long)b2 * Hsz + h] = sm[h] + sm[h + 256] + sm[h + 512] + sm[h + 768];
}

__global__ void vcat_k()
{
    int idx = blockIdx.x * blockDim.x + threadIdx.x;   // B*400
    if (idx >= Bsz * 2 * Hsz) return;
    int b = idx / (2 * Hsz), c = idx % (2 * Hsz);
    float v = (c < Hsz) ? g_v[(long)b * Hsz + c]
                        : g_v[(long)(Bsz + b) * Hsz + (c - Hsz)];
    g_vcat[idx] = v;
}

__global__ void final_k(const float* __restrict__ W2g,
                        const float* __restrict__ b2g, float* __restrict__ out)
{
    int b = blockIdx.x;
    int o = threadIdx.x >> 5;       // 0 or 1 (64 threads)
    int lane = threadIdx.x & 31;
    const float* u = g_u + (long)b * Hsz;
    float s = 0.f;
    for (int h = lane; h < Hsz; h += 32) s += u[h] * W2g[h * 2 + o];
#pragma unroll
    for (int off = 16; off; off >>= 1) s += __shfl_xor_sync(~0u, s, off);
    if (lane == 0) out[b * 2 + o] = s + b2g[o];
}

// ---------------- launch -----------------------------------------------------
extern "C" void kernel_launch(void* const* d_in, const int* in_sizes, int n_in,
                              void* d_out, int out_size)
{
    const float* emb = (const float*)d_in[0];
    const float* W1a = (const float*)d_in[1];
    const float* b1a = (const float*)d_in[2];
    const float* W2a = (const float*)d_in[3];
    const float* b2a = (const float*)d_in[4];
    const float* W1c = (const float*)d_in[5];
    const float* b1c = (const float*)d_in[6];
    const float* W2c = (const float*)d_in[7];
    const float* b2c = (const float*)d_in[8];
    const float* W1g = (const float*)d_in[9];
    const float* b1g = (const float*)d_in[10];
    const float* W2g = (const float*)d_in[11];
    const float* b2g = (const float*)d_in[12];
    const int* s1   = (const int*)d_in[13];
    const int* s2   = (const int*)d_in[14];
    const int* len1 = (const int*)d_in[15];
    const int* len2 = (const int*)d_in[16];
    float* out = (float*)d_out;

    float *pe, *pta, *ph, *psc, *pea, *pab, *pmask, *prsa, *prsb, *pvcat, *pu;
    float *ptv, *phv, *pcv;
    cudaGetSymbolAddress((void**)&pe,   g_e);
    cudaGetSymbolAddress((void**)&pta,  g_ta);
    cudaGetSymbolAddress((void**)&ph,   g_h);
    cudaGetSymbolAddress((void**)&psc,  g_scores);
    cudaGetSymbolAddress((void**)&pea,  g_ea);
    cudaGetSymbolAddress((void**)&pab,  g_ab);
    cudaGetSymbolAddress((void**)&pmask,g_mask);
    cudaGetSymbolAddress((void**)&prsa, g_rsa);
    cudaGetSymbolAddress((void**)&prsb, g_rsb);
    cudaGetSymbolAddress((void**)&pvcat,g_vcat);
    cudaGetSymbolAddress((void**)&pu,   g_u);
    cudaGetSymbolAddress((void**)&ptv,  g_tv);
    cudaGetSymbolAddress((void**)&phv,  g_hv);
    cudaGetSymbolAddress((void**)&pcv,  g_cv);

    const int M2 = (int)(2 * BL);          // 262144
    const long LsH = (long)Lsz * Hsz;
    const long LsE = (long)Lsz * Esz;
    const unsigned MV = (VOC + 127) / 128; // 391 tiles for vocab GEMMs

    // 1. per-vocab precompute: attend_ff and compare-L1 top half
    gemm_k<false,false><<<dim3(2, MV, 1), 256>>>(
        emb, 0, Esz, W1a, 0, Hsz, b1a, nullptr, 0, ptv, 0, Hsz, VOC, Hsz, Esz, 0, 1);
    gemm_k<false,false><<<dim3(2, MV, 1), 256>>>(
        ptv, 0, Hsz, W2a, 0, Hsz, b2a, nullptr, 0, phv, 0, Hsz, VOC, Hsz, Hsz, 0, 1);
    gemm_k<false,false><<<dim3(2, MV, 1), 256>>>(
        emb, 0, Esz, W1c, 0, Hsz, nullptr, nullptr, 0, pcv, 0, Hsz, VOC, Hsz, Esz, 0, 0);

    // 2. gather e/h/cv into token space + masks
    gather_all_k<<<(unsigned)(2 * BL), 128>>>(emb, s1, s2);
    mask_k<<<(unsigned)((2 * BL + 255) / 256), 256>>>(len1, len2);

    // 3. scores[b] = h1[b] @ h2[b]^T   (B batched 256x256x200, NT)
    gemm_k<false,true><<<dim3(2, 2, Bsz), 256>>>(
        ph, LsH, Hsz, ph + BLH, LsH, Hsz, nullptr, nullptr, 0,
        psc, LL, Lsz, Lsz, Lsz, Hsz, 0, 0);

    // 4. maxima + exp stage
    rowmax_k<<<(unsigned)(BL / 8), 256>>>();
    colmax_k<<<Bsz, 1024>>>();
    softpre_k<<<Bsz, 1024>>>();
    rowsum_k<<<(unsigned)(BL / 8), 256>>>();

    // 5. alphas[b] = diag(rsa) * (ea^T @ e1)  -> g_ab second half  (TN)
    gemm_k<true,false><<<dim3(3, 2, Bsz), 256>>>(
        pea, LL, Lsz, pe, LsE, Esz, nullptr, prsa, Lsz,
        pab + BLE, LsE, Esz, Lsz, Esz, Lsz, 0, 0);
    //    betas[b]  = diag(rsb) * (eb @ e2)   -> g_ab first half   (NN)
    gemm_k<false,false><<<dim3(3, 2, Bsz), 256>>>(
        psc, LL, Lsz, pe + BLE, LsE, Esz, nullptr, prsb, Lsz,
        pab, LsE, Esz, Lsz, Esz, Lsz, 0, 0);

    // 6. compare_ff: pta already holds e@W1c (gathered); accumulate ab half
    gemm_k<false,false><<<dim3(2, M2 / 128, 1), 256>>>(
        pab, 0, Esz, W1c + (long)Esz * Hsz, 0, Hsz, b1c, nullptr, 0,
        pta, 0, Hsz, M2, Hsz, Esz, 1, 1);
    //    layer 2 with mask folded into epilogue
    gemm_k<false,false><<<dim3(2, M2 / 128, 1), 256>>>(
        pta, 0, Hsz, W2c, 0, Hsz, b2c, pmask, 0, ph, 0, Hsz, M2, Hsz, Hsz, 0, 1);

    // 7. masked sums over L -> v1,v2 ; aggregate head
    colsum_k<<<2 * Bsz, 1024>>>();
    vcat_k<<<(Bsz * 2 * Hsz + 255) / 256, 256>>>();
    gemm_k<false,false><<<dim3(2, Bsz / 128, 1), 256>>>(
        pvcat, 0, 2 * Hsz, W1g, 0, Hsz, b1g, nullptr, 0,
        pu, 0, Hsz, Bsz, Hsz, 2 * Hsz, 0, 1);
    final_k<<<Bsz, 64>>>(W2g, b2g, out);
}

// round 5
// speedup vs baseline: 2.4013x; 1.1836x over previous
#include <cuda_runtime.h>
#include <cstdint>

// Problem constants
#define Bsz 512
#define Lsz 256
#define Esz 300
#define Hsz 200
#define VOC 50000
constexpr long BL  = (long)Bsz * Lsz;      // 131072
constexpr long BLE = BL * Esz;             // 39,321,600
constexpr long BLH = BL * Hsz;             // 26,214,400
constexpr long LL  = (long)Lsz * Lsz;      // 65536
constexpr long BLL = BL * Lsz;             // 33,554,432

// ---------------- device scratch (static, no runtime allocation) -------------
__device__ float g_e[2 * BLE];     // [e1 ; e2]          (2*BL x 300)
__device__ float g_ta[2 * BLH];    // compare hidden accumulator (2*BL x 200)
__device__ float g_h[2 * BLH];     // attend_ff out (gathered) / compare out
__device__ float g_scores[BLL];    // e scores, later eb (B x 256 x 256)
__device__ float g_ea[BLL];        // ea (unnormalized)
__device__ float g_ab[2 * BLE];    // [betas ; alphas]   (2*BL x 300)
__device__ float g_mask[2 * BL];   // [mask1 ; mask2]
__device__ float g_bmax[Bsz];      // per-batch score max
__device__ float g_rsa[BL];        // mask2 / d_alpha (per (b,j))
__device__ float g_rsb[BL];        // mask1 / d_beta  (per (b,i))
__device__ float g_vcat[Bsz * 2 * Hsz];
__device__ float g_u[Bsz * Hsz];
// per-vocab precompute
__device__ float g_tv[(long)VOC * Hsz];   // vocab attend L1 temp
__device__ float g_hv[(long)VOC * Hsz];   // vocab attend_ff output
__device__ float g_cv[(long)VOC * Hsz];   // vocab e@W1c (top half, no bias)

// round fp32 bits to tf32 (rna): HW truncates low 13 bits, so +0x1000 = nearest
__device__ __forceinline__ uint32_t rtf(float x)
{
    return __float_as_uint(x) + 0x1000u;
}

__device__ __forceinline__ void mma_tf32(float c[4],
                                         uint32_t a0, uint32_t a1, uint32_t a2, uint32_t a3,
                                         uint32_t b0, uint32_t b1)
{
    asm volatile(
        "mma.sync.aligned.m16n8k8.row.col.f32.tf32.tf32.f32 "
        "{%0,%1,%2,%3}, {%4,%5,%6,%7}, {%8,%9}, {%0,%1,%2,%3};"
        : "+f"(c[0]), "+f"(c[1]), "+f"(c[2]), "+f"(c[3])
        : "r"(a0), "r"(a1), "r"(a2), "r"(a3), "r"(b0), "r"(b1));
}

__device__ __forceinline__ void cp16(uint32_t dst, const float* src, bool pred)
{
    int sz = pred ? 16 : 0;
    asm volatile("cp.async.cg.shared.global [%0], [%1], 16, %2;"
                 :: "r"(dst), "l"(src), "r"(sz));
}
__device__ __forceinline__ void cp_commit()
{
    asm volatile("cp.async.commit_group;");
}
template <int N>
__device__ __forceinline__ void cp_wait()
{
    asm volatile("cp.async.wait_group %0;" :: "n"(N));
}

// ---------------- 128x128x16 TF32 tensor-core GEMM, 2-stage cp.async ---------
// C[bz][m,n] = epi( sum_k A(m,k) * B(k,n) )
// TA=false: A[m,k] = A[m*lda + k]   TA=true: A[m,k] = A[k*lda + m]
// TB=false: B[k,n] = B[k*ldb + n]   TB=true: B[k,n] = B[n*ldb + k]
// epilogue: v = acc (+ C if accum) (+ bias[n]) ; relu ; * rowscale[bz*sRS + m]
// Requires M,N,K,lda,ldb divisible by 4 (true at all call sites).
template <bool TA, bool TB>
__global__ __launch_bounds__(256)
void gemm_k(const float* __restrict__ A, long sA, int lda,
            const float* __restrict__ Bw, long sB, int ldb,
            const float* __restrict__ bias,
            const float* __restrict__ rs, int sRS,
            float* __restrict__ C, long sC, int ldc,
            int M, int N, int K, int accum, int relu)
{
    // smem layouts: transposing loads use target-major [k][x] (pad 136);
    // non-transposing (cp.async friendly) use source-major [x][k] (pad 20).
    constexpr int ASZ = TA ? 16 * 136 : 128 * 20;
    constexpr int BSZ = TB ? 128 * 20 : 16 * 136;
    __shared__ float As[2][ASZ];
    __shared__ float Bs[2][BSZ];

    int bz = blockIdx.z;
    const float* Ab = A + (long)bz * sA;
    const float* Bb = Bw + (long)bz * sB;
    float* Cb = C + (long)bz * sC;
    int m0 = blockIdx.y * 128, n0 = blockIdx.x * 128;
    int tid = threadIdx.x;
    int wid = tid >> 5, lane = tid & 31;
    int wm = wid >> 2, wn = wid & 3;       // warps: 2 (m) x 4 (n)
    int g = lane >> 2, tig = lane & 3;     // groupID, thread-in-group

    uint32_t abase = (uint32_t)__cvta_generic_to_shared(&As[0][0]);
    uint32_t bbase = (uint32_t)__cvta_generic_to_shared(&Bs[0][0]);

    float c[4][4][4];
#pragma unroll
    for (int i = 0; i < 4; i++)
#pragma unroll
        for (int j = 0; j < 4; j++)
#pragma unroll
            for (int q = 0; q < 4; q++) c[i][j][q] = 0.f;

    int KT = (K + 15) / 16;

    auto load_stage = [&](int st, int k0) {
#pragma unroll
        for (int it = 0; it < 2; it++) {
            int t2 = tid + it * 256;
            if (!TA) {
                int row = t2 >> 2, cc = (t2 & 3) * 4;   // As[row][cc..cc+3]
                bool p = (m0 + row < M) && (k0 + cc < K);
                cp16(abase + (uint32_t)(st * ASZ + row * 20 + cc) * 4,
                     Ab + (long)(m0 + row) * lda + (k0 + cc), p);
            } else {
                int k = t2 >> 5, mc = (t2 & 31) * 4;    // As[k][mc..mc+3]
                bool p = (k0 + k < K) && (m0 + mc < M);
                cp16(abase + (uint32_t)(st * ASZ + k * 136 + mc) * 4,
                     Ab + (long)(k0 + k) * lda + (m0 + mc), p);
            }
            if (!TB) {
                int k = t2 >> 5, nc = (t2 & 31) * 4;    // Bs[k][nc..nc+3]
                bool p = (k0 + k < K) && (n0 + nc < N);
                cp16(bbase + (uint32_t)(st * BSZ + k * 136 + nc) * 4,
                     Bb + (long)(k0 + k) * ldb + (n0 + nc), p);
            } else {
                int row = t2 >> 2, cc = (t2 & 3) * 4;   // Bs[row][cc..cc+3]
                bool p = (n0 + row < N) && (k0 + cc < K);
                cp16(bbase + (uint32_t)(st * BSZ + row * 20 + cc) * 4,
                     Bb + (long)(n0 + row) * ldb + (k0 + cc), p);
            }
        }
        cp_commit();
    };

    load_stage(0, 0);

    for (int kt = 0; kt < KT; kt++) {
        if (kt + 1 < KT) {
            load_stage((kt + 1) & 1, (kt + 1) * 16);
            cp_wait<1>();
        } else {
            cp_wait<0>();
        }
        __syncthreads();
        int st = kt & 1;
        const float* Ap = As[st];
        const float* Bp = Bs[st];
#pragma unroll
        for (int s2 = 0; s2 < 2; s2++) {
            int ks = s2 * 8;
            uint32_t af[4][4];
#pragma unroll
            for (int t = 0; t < 4; t++) {
                int m = wm * 64 + t * 16 + g;
                if (TA) {
                    af[t][0] = rtf(Ap[(ks + tig) * 136 + m]);
                    af[t][1] = rtf(Ap[(ks + tig) * 136 + m + 8]);
                    af[t][2] = rtf(Ap[(ks + tig + 4) * 136 + m]);
                    af[t][3] = rtf(Ap[(ks + tig + 4) * 136 + m + 8]);
                } else {
                    af[t][0] = rtf(Ap[m * 20 + ks + tig]);
                    af[t][1] = rtf(Ap[(m + 8) * 20 + ks + tig]);
                    af[t][2] = rtf(Ap[m * 20 + ks + tig + 4]);
                    af[t][3] = rtf(Ap[(m + 8) * 20 + ks + tig + 4]);
                }
            }
            uint32_t bf[4][2];
#pragma unroll
            for (int t = 0; t < 4; t++) {
                int n = wn * 32 + t * 8 + g;
                if (TB) {
                    bf[t][0] = rtf(Bp[n * 20 + ks + tig]);
                    bf[t][1] = rtf(Bp[n * 20 + ks + tig + 4]);
                } else {
                    bf[t][0] = rtf(Bp[(ks + tig) * 136 + n]);
                    bf[t][1] = rtf(Bp[(ks + tig + 4) * 136 + n]);
                }
            }
#pragma unroll
            for (int mt = 0; mt < 4; mt++)
#pragma unroll
                for (int nt = 0; nt < 4; nt++)
                    mma_tf32(c[mt][nt], af[mt][0], af[mt][1], af[mt][2], af[mt][3],
                             bf[nt][0], bf[nt][1]);
        }
        __syncthreads();
    }

    // ---- epilogue
#pragma unroll
    for (int mt = 0; mt < 4; mt++) {
#pragma unroll
        for (int r = 0; r < 2; r++) {
            int m = m0 + wm * 64 + mt * 16 + g + r * 8;
            if (m >= M) continue;
            float rsv = rs ? rs[(long)bz * sRS + m] : 1.f;
#pragma unroll
            for (int nt = 0; nt < 4; nt++) {
#pragma unroll
                for (int q = 0; q < 2; q++) {
                    int n = n0 + wn * 32 + nt * 8 + tig * 2 + q;
                    if (n < N) {
                        long idx = (long)m * ldc + n;
                        float v = c[mt][nt][r * 2 + q];
                        if (accum) v += Cb[idx];
                        if (bias) v += bias[n];
                        if (relu) v = fmaxf(v, 0.f);
                        v *= rsv;
                        Cb[idx] = v;
                    }
                }
            }
        }
    }
}

// ---------------- helper kernels ---------------------------------------------
// One block per token row: gather e (75 float4), h (50 float4), cv (50 float4)
__global__ void gather_all_k(const float* __restrict__ emb,
                             const int* __restrict__ s1, const int* __restrict__ s2)
{
    long row = blockIdx.x;                 // 0 .. 2*BL-1
    long r = row < BL ? row : row - BL;
    int tok = (row < BL) ? s1[r] : s2[r];
    int t = threadIdx.x;                   // 128 threads
    const float4* esrc = (const float4*)(emb + (long)tok * Esz);
    float4* edst = (float4*)(g_e + row * Esz);
    if (t < 75) edst[t] = esrc[t];
    const float4* hsrc = (const float4*)(g_hv + (long)tok * Hsz);
    float4* hdst = (float4*)(g_h + row * Hsz);
    if (t < 50) hdst[t] = hsrc[t];
    const float4* csrc = (const float4*)(g_cv + (long)tok * Hsz);
    float4* cdst = (float4*)(g_ta + row * Hsz);
    if (t >= 64 && t < 114) cdst[t - 64] = csrc[t - 64];
}

__global__ void mask_k(const int* __restrict__ len1, const int* __restrict__ len2)
{
    long idx = (long)blockIdx.x * blockDim.x + threadIdx.x;
    if (idx >= 2 * BL) return;
    int seq = (int)(idx / BL);
    long r = idx % BL;
    int b = (int)(r / Lsz), l = (int)(r % Lsz);
    int len = seq ? len2[b] : len1[b];
    g_mask[idx] = (l < len) ? 1.f : 0.f;
}

__global__ void bmax_k()     // per-batch max over the 256x256 score tile
{
    __shared__ float sm[1024];
    int b = blockIdx.x;
    const float4* p = (const float4*)(g_scores + (long)b * LL);
    float m = -1e30f;
    for (int i = threadIdx.x; i < LL / 4; i += 1024) {
        float4 v = p[i];
        m = fmaxf(fmaxf(m, v.x), fmaxf(fmaxf(v.y, v.z), v.w));
    }
    sm[threadIdx.x] = m;
    __syncthreads();
    for (int o = 512; o; o >>= 1) {
        if (threadIdx.x < o) sm[threadIdx.x] = fmaxf(sm[threadIdx.x], sm[threadIdx.x + o]);
        __syncthreads();
    }
    if (threadIdx.x == 0) g_bmax[b] = sm[0];
}

// Shift-cancelled softmax precompute (the row/col max shifts of the reference
// cancel exactly in alphas/betas, so a single per-batch shift is equivalent):
// p = exp(e - Mb); ea = p*mask1[i] -> g_ea (colsum -> rsa); eb = p*mask2[j] in place.
__global__ void softpre_k()
{
    __shared__ float sm[1024];
    int b = blockIdx.x;
    int j = threadIdx.x & 255, s = threadIdx.x >> 8;
    long base = (long)b * LL;
    float Mb  = g_bmax[b];
    float m2j = g_mask[BL + (long)b * Lsz + j];
    float da = 0.f;
    for (int i = s * 64; i < s * 64 + 64; i++) {
        long idx = base + (long)i * Lsz + j;
        float p = __expf(g_scores[idx] - Mb);
        float q = p * g_mask[(long)b * Lsz + i];
        da += q;
        g_ea[idx] = q;
        g_scores[idx] = p * m2j;
    }
    sm[threadIdx.x] = da;
    __syncthreads();
    if (s == 0)
        g_rsa[(long)b * Lsz + j] = m2j / (sm[j] + sm[j + 256] + sm[j + 512] + sm[j + 768]);
}

__global__ void rowsum_k()   // d_beta row sums over eb (= g_scores), -> rsb
{
    long row = (long)blockIdx.x * 8 + (threadIdx.x >> 5);
    int lane = threadIdx.x & 31;
    const float* p = g_scores + row * Lsz;
    float s = 0.f;
    for (int j = lane; j < Lsz; j += 32) s += p[j];
#pragma unroll
    for (int o = 16; o; o >>= 1) s += __shfl_xor_sync(~0u, s, o);
    if (lane == 0) g_rsb[row] = g_mask[row] / s;
}

__global__ void colsum_k()   // v[b2,h] = sum_l h[b2,l,h] -> directly into vcat
{
    __shared__ float sm[1024];
    int b2 = blockIdx.x;     // 0 .. 2B-1
    int h = threadIdx.x & 255, s = threadIdx.x >> 8;
    float acc = 0.f;
    if (h < Hsz) {
        const float* p = g_h + (long)b2 * Lsz * Hsz;
#pragma unroll 4
        for (int l = s * 64; l < s * 64 + 64; l++) acc += p[(long)l * Hsz + h];
    }
    sm[threadIdx.x] = acc;
    __syncthreads();
    if (s == 0 && h < Hsz) {
        int b = (b2 < Bsz) ? b2 : b2 - Bsz;
        int off = (b2 < Bsz) ? 0 : Hsz;
        g_vcat[(long)b * 2 * Hsz + off + h] =
            sm[h] + sm[h + 256] + sm[h + 512] + sm[h + 768];
    }
}

__global__ void final_k(const float* __restrict__ W2g,
                        const float* __restrict__ b2g, float* __restrict__ out)
{
    int b = blockIdx.x;
    int o = threadIdx.x >> 5;       // 0 or 1 (64 threads)
    int lane = threadIdx.x & 31;
    const float* u = g_u + (long)b * Hsz;
    float s = 0.f;
    for (int h = lane; h < Hsz; h += 32) s += u[h] * W2g[h * 2 + o];
#pragma unroll
    for (int off = 16; off; off >>= 1) s += __shfl_xor_sync(~0u, s, off);
    if (lane == 0) out[b * 2 + o] = s + b2g[o];
}

// ---------------- launch -----------------------------------------------------
extern "C" void kernel_launch(void* const* d_in, const int* in_sizes, int n_in,
                              void* d_out, int out_size)
{
    const float* emb = (const float*)d_in[0];
    const float* W1a = (const float*)d_in[1];
    const float* b1a = (const float*)d_in[2];
    const float* W2a = (const float*)d_in[3];
    const float* b2a = (const float*)d_in[4];
    const float* W1c = (const float*)d_in[5];
    const float* b1c = (const float*)d_in[6];
    const float* W2c = (const float*)d_in[7];
    const float* b2c = (const float*)d_in[8];
    const float* W1g = (const float*)d_in[9];
    const float* b1g = (const float*)d_in[10];
    const float* W2g = (const float*)d_in[11];
    const float* b2g = (const float*)d_in[12];
    const int* s1   = (const int*)d_in[13];
    const int* s2   = (const int*)d_in[14];
    const int* len1 = (const int*)d_in[15];
    const int* len2 = (const int*)d_in[16];
    float* out = (float*)d_out;

    float *pe, *pta, *ph, *psc, *pea, *pab, *pmask, *prsa, *prsb, *pvcat, *pu;
    float *ptv, *phv, *pcv;
    cudaGetSymbolAddress((void**)&pe,   g_e);
    cudaGetSymbolAddress((void**)&pta,  g_ta);
    cudaGetSymbolAddress((void**)&ph,   g_h);
    cudaGetSymbolAddress((void**)&psc,  g_scores);
    cudaGetSymbolAddress((void**)&pea,  g_ea);
    cudaGetSymbolAddress((void**)&pab,  g_ab);
    cudaGetSymbolAddress((void**)&pmask,g_mask);
    cudaGetSymbolAddress((void**)&prsa, g_rsa);
    cudaGetSymbolAddress((void**)&prsb, g_rsb);
    cudaGetSymbolAddress((void**)&pvcat,g_vcat);
    cudaGetSymbolAddress((void**)&pu,   g_u);
    cudaGetSymbolAddress((void**)&ptv,  g_tv);
    cudaGetSymbolAddress((void**)&phv,  g_hv);
    cudaGetSymbolAddress((void**)&pcv,  g_cv);

    const int M2 = (int)(2 * BL);          // 262144
    const long LsH = (long)Lsz * Hsz;
    const long LsE = (long)Lsz * Esz;
    const unsigned MV = (VOC + 127) / 128; // 391 tiles for vocab GEMMs

    // 1. per-vocab precompute: attend_ff and compare-L1 top half
    gemm_k<false,false><<<dim3(2, MV, 1), 256>>>(
        emb, 0, Esz, W1a, 0, Hsz, b1a, nullptr, 0, ptv, 0, Hsz, VOC, Hsz, Esz, 0, 1);
    gemm_k<false,false><<<dim3(2, MV, 1), 256>>>(
        ptv, 0, Hsz, W2a, 0, Hsz, b2a, nullptr, 0, phv, 0, Hsz, VOC, Hsz, Hsz, 0, 1);
    gemm_k<false,false><<<dim3(2, MV, 1), 256>>>(
        emb, 0, Esz, W1c, 0, Hsz, nullptr, nullptr, 0, pcv, 0, Hsz, VOC, Hsz, Esz, 0, 0);

    // 2. gather e/h/cv into token space + masks
    gather_all_k<<<(unsigned)(2 * BL), 128>>>(emb, s1, s2);
    mask_k<<<(unsigned)((2 * BL + 255) / 256), 256>>>(len1, len2);

    // 3. scores[b] = h1[b] @ h2[b]^T   (B batched 256x256x200, NT)
    gemm_k<false,true><<<dim3(2, 2, Bsz), 256>>>(
        ph, LsH, Hsz, ph + BLH, LsH, Hsz, nullptr, nullptr, 0,
        psc, LL, Lsz, Lsz, Lsz, Hsz, 0, 0);

    // 4. per-batch max + single-exp softmax stage
    bmax_k<<<Bsz, 1024>>>();
    softpre_k<<<Bsz, 1024>>>();
    rowsum_k<<<(unsigned)(BL / 8), 256>>>();

    // 5. alphas[b] = diag(rsa) * (ea^T @ e1)  -> g_ab second half  (TN)
    gemm_k<true,false><<<dim3(3, 2, Bsz), 256>>>(
        pea, LL, Lsz, pe, LsE, Esz, nullptr, prsa, Lsz,
        pab + BLE, LsE, Esz, Lsz, Esz, Lsz, 0, 0);
    //    betas[b]  = diag(rsb) * (eb @ e2)   -> g_ab first half   (NN)
    gemm_k<false,false><<<dim3(3, 2, Bsz), 256>>>(
        psc, LL, Lsz, pe + BLE, LsE, Esz, nullptr, prsb, Lsz,
        pab, LsE, Esz, Lsz, Esz, Lsz, 0, 0);

    // 6. compare_ff: pta already holds e@W1c (gathered); accumulate ab half
    gemm_k<false,false><<<dim3(2, M2 / 128, 1), 256>>>(
        pab, 0, Esz, W1c + (long)Esz * Hsz, 0, Hsz, b1c, nullptr, 0,
        pta, 0, Hsz, M2, Hsz, Esz, 1, 1);
    //    layer 2 with mask folded into epilogue
    gemm_k<false,false><<<dim3(2, M2 / 128, 1), 256>>>(
        pta, 0, Hsz, W2c, 0, Hsz, b2c, pmask, 0, ph, 0, Hsz, M2, Hsz, Hsz, 0, 1);

    // 7. masked sums over L -> vcat directly ; aggregate head
    colsum_k<<<2 * Bsz, 1024>>>();
    gemm_k<false,false><<<dim3(2, Bsz / 128, 1), 256>>>(
        pvcat, 0, 2 * Hsz, W1g, 0, Hsz, b1g, nullptr, 0,
        pu, 0, Hsz, Bsz, Hsz, 2 * Hsz, 0, 1);
    final_k<<<Bsz, 64>>>(W2g, b2g, out);
}

// round 6
// speedup vs baseline: 6.0803x; 2.5321x over previous
#include <cuda_runtime.h>
#include <cuda_fp16.h>
#include <cstdint>

// Problem constants
#define Bsz 512
#define Lsz 256
#define Esz 300
#define EP  304              // padded E (16B-aligned fp16 rows)
#define Hsz 200
#define VOC 50000
constexpr long BL  = (long)Bsz * Lsz;      // 131072
constexpr long LL  = (long)Lsz * Lsz;      // 65536
constexpr long BLL = BL * Lsz;             // 33,554,432

// ---------------- device scratch (static, no runtime allocation) -------------
__device__ __half g_embh[(long)VOC * EP];
__device__ __half g_W1a[EP * Hsz];
__device__ __half g_W2a[Hsz * Hsz];
__device__ __half g_W1cT[EP * Hsz];
__device__ __half g_W1cB[EP * Hsz];
__device__ __half g_W2c[Hsz * Hsz];
__device__ __half g_W1g[2 * Hsz * Hsz];
__device__ __half g_tvh[(long)VOC * Hsz];
__device__ __half g_hvh[(long)VOC * Hsz];
__device__ __half g_eh[2 * BL * EP];
__device__ __half g_phh[2 * BL * Hsz];
__device__ __half g_eanh[BLL];
__device__ __half g_ebnh[BLL];
__device__ __half g_abh[2 * BL * EP];
__device__ __half g_thh[2 * BL * Hsz];
__device__ __half g_hoh[2 * BL * Hsz];
__device__ __half g_vch[Bsz * 2 * Hsz];
__device__ float g_cv[(long)VOC * Hsz];
__device__ float g_pta[2 * BL * Hsz];
__device__ float g_scores[BLL];
__device__ float g_ea[BLL];
__device__ float g_mask[2 * BL];
__device__ float g_bmax[Bsz];
__device__ float g_rsa[BL];
__device__ float g_rsb[BL];
__device__ float g_u[Bsz * Hsz];

// ---------------- PTX helpers ------------------------------------------------
__device__ __forceinline__ void cp16(uint32_t dst, const void* src, bool pred)
{
    int sz = pred ? 16 : 0;
    asm volatile("cp.async.cg.shared.global [%0], [%1], 16, %2;"
                 :: "r"(dst), "l"(src), "r"(sz));
}
__device__ __forceinline__ void cp_commit() { asm volatile("cp.async.commit_group;"); }
template <int N>
__device__ __forceinline__ void cp_wait() { asm volatile("cp.async.wait_group %0;" :: "n"(N)); }

__device__ __forceinline__ void ldsm4(uint32_t* r, uint32_t a)
{
    asm volatile("ldmatrix.sync.aligned.m8n8.x4.shared.b16 {%0,%1,%2,%3}, [%4];"
                 : "=r"(r[0]), "=r"(r[1]), "=r"(r[2]), "=r"(r[3]) : "r"(a));
}
__device__ __forceinline__ void ldsm4t(uint32_t* r, uint32_t a)
{
    asm volatile("ldmatrix.sync.aligned.m8n8.x4.trans.shared.b16 {%0,%1,%2,%3}, [%4];"
                 : "=r"(r[0]), "=r"(r[1]), "=r"(r[2]), "=r"(r[3]) : "r"(a));
}
__device__ __forceinline__ void ldsm2(uint32_t* r, uint32_t a)
{
    asm volatile("ldmatrix.sync.aligned.m8n8.x2.shared.b16 {%0,%1}, [%2];"
                 : "=r"(r[0]), "=r"(r[1]) : "r"(a));
}
__device__ __forceinline__ void ldsm2t(uint32_t* r, uint32_t a)
{
    asm volatile("ldmatrix.sync.aligned.m8n8.x2.trans.shared.b16 {%0,%1}, [%2];"
                 : "=r"(r[0]), "=r"(r[1]) : "r"(a));
}
__device__ __forceinline__ void mma16816(float c[4], const uint32_t a[4], const uint32_t b[2])
{
    asm volatile(
        "mma.sync.aligned.m16n8k16.row.col.f32.f16.f16.f32 "
        "{%0,%1,%2,%3}, {%4,%5,%6,%7}, {%8,%9}, {%0,%1,%2,%3};"
        : "+f"(c[0]), "+f"(c[1]), "+f"(c[2]), "+f"(c[3])
        : "r"(a[0]), "r"(a[1]), "r"(a[2]), "r"(a[3]), "r"(b[0]), "r"(b[1]));
}

// ---------------- 128x128x32 fp16 tensor GEMM, 2-stage cp.async + LDSM -------
// C[bz][m,n] = epi( sum_k A(m,k) * B(k,n) ), fp32 accumulate.
// TA: A[m,k]=A[k*lda+m]; TB: B[k,n]=B[n*ldb+k].
// epilogue: v = acc (+ Cin[m,n]) (+ bias[n]); relu; * rs[bz*sRS+m]; fp16/fp32 out.
// Requires K % 8 == 0, N even, fp16 rows 16B-aligned (lda*2 % 16 == 0).
template <bool TA, bool TB, bool OUTH>
__global__ __launch_bounds__(256)
void gemm_h(const __half* __restrict__ A, long sA, int lda,
            const __half* __restrict__ Bw, long sB, int ldb,
            const float* __restrict__ bias,
            const float* __restrict__ rs, int sRS,
            const float* __restrict__ Cin,
            void* __restrict__ Cv, long sC, int ldc,
            int M, int N, int K, int relu)
{
    constexpr int A_SZ = TA ? 32 * 136 : 128 * 40;   // halfs per stage
    constexpr int B_SZ = TB ? 128 * 40 : 32 * 136;
    __shared__ __half As[2][A_SZ];
    __shared__ __half Bs[2][B_SZ];

    int bz = blockIdx.z;
    const __half* Ab = A + (long)bz * sA;
    const __half* Bb = Bw + (long)bz * sB;
    int m0 = blockIdx.y * 128, n0 = blockIdx.x * 128;
    int tid = threadIdx.x;
    int wid = tid >> 5, lane = tid & 31;
    int wm = wid >> 2, wn = wid & 3;       // 2 (m) x 4 (n) warps
    int g = lane >> 2, tig = lane & 3;

    uint32_t abase = (uint32_t)__cvta_generic_to_shared(&As[0][0]);
    uint32_t bbase = (uint32_t)__cvta_generic_to_shared(&Bs[0][0]);

    float c[4][4][4];
#pragma unroll
    for (int i = 0; i < 4; i++)
#pragma unroll
        for (int j = 0; j < 4; j++)
#pragma unroll
            for (int q = 0; q < 4; q++) c[i][j][q] = 0.f;

    int KT = (K + 31) / 32;

    auto load_stage = [&](int st, int k0) {
#pragma unroll
        for (int it = 0; it < 2; it++) {
            int id = tid + it * 256;
            if (!TA) {
                int row = id >> 2, c8 = (id & 3) * 8;
                bool p = (m0 + row < M) && (k0 + c8 < K);
                cp16(abase + (uint32_t)(st * A_SZ + row * 40 + c8) * 2,
                     Ab + (long)(m0 + row) * lda + k0 + c8, p);
            } else {
                int kr = id >> 4, c8 = (id & 15) * 8;
                bool p = (k0 + kr < K) && (m0 + c8 < M);
                cp16(abase + (uint32_t)(st * A_SZ + kr * 136 + c8) * 2,
                     Ab + (long)(k0 + kr) * lda + m0 + c8, p);
            }
            if (!TB) {
                int kr = id >> 4, c8 = (id & 15) * 8;
                bool p = (k0 + kr < K) && (n0 + c8 < N);
                cp16(bbase + (uint32_t)(st * B_SZ + kr * 136 + c8) * 2,
                     Bb + (long)(k0 + kr) * ldb + n0 + c8, p);
            } else {
                int row = id >> 2, c8 = (id & 3) * 8;
                bool p = (n0 + row < N) && (k0 + c8 < K);
                cp16(bbase + (uint32_t)(st * B_SZ + row * 40 + c8) * 2,
                     Bb + (long)(n0 + row) * ldb + k0 + c8, p);
            }
        }
        cp_commit();
    };

    load_stage(0, 0);

    for (int kt = 0; kt < KT; kt++) {
        if (kt + 1 < KT) { load_stage((kt + 1) & 1, (kt + 1) * 32); cp_wait<1>(); }
        else             { cp_wait<0>(); }
        __syncthreads();
        int st = kt & 1;
        uint32_t ab2 = abase + (uint32_t)(st * A_SZ) * 2;
        uint32_t bb2 = bbase + (uint32_t)(st * B_SZ) * 2;

#pragma unroll
        for (int s2 = 0; s2 < 2; s2++) {
            int ks = s2 * 16;
            uint32_t af[4][4], bf[4][2];
#pragma unroll
            for (int mt = 0; mt < 4; mt++) {
                if (!TA) {
                    int m = wm * 64 + mt * 16 + (lane & 15);
                    int kc = ks + ((lane >> 4) << 3);
                    ldsm4(af[mt], ab2 + (uint32_t)(m * 40 + kc) * 2);
                } else {
                    int kr = ks + (lane & 7) + ((lane >> 4) << 3);
                    int mc = wm * 64 + mt * 16 + (((lane >> 3) & 1) << 3);
                    ldsm4t(af[mt], ab2 + (uint32_t)(kr * 136 + mc) * 2);
                }
            }
#pragma unroll
            for (int nt = 0; nt < 4; nt++) {
                if (TB) {
                    int n = wn * 32 + nt * 8 + (lane & 7);
                    int kc = ks + (((lane >> 3) & 1) << 3);
                    ldsm2(bf[nt], bb2 + (uint32_t)(n * 40 + kc) * 2);
                } else {
                    int kr = ks + (lane & 7) + (((lane >> 3) & 1) << 3);
                    int nc = wn * 32 + nt * 8;
                    ldsm2t(bf[nt], bb2 + (uint32_t)(kr * 136 + nc) * 2);
                }
            }
#pragma unroll
            for (int mt = 0; mt < 4; mt++)
#pragma unroll
                for (int nt = 0; nt < 4; nt++)
                    mma16816(c[mt][nt], af[mt], bf[nt]);
        }
        __syncthreads();
    }

    __half* Ch = (__half*)Cv + (long)bz * sC;
    float*  Cf = (float*)Cv + (long)bz * sC;
#pragma unroll
    for (int mt = 0; mt < 4; mt++) {
#pragma unroll
        for (int r = 0; r < 2; r++) {
            int m = m0 + wm * 64 + mt * 16 + g + r * 8;
            if (m >= M) continue;
            float rsv = rs ? rs[(long)bz * sRS + m] : 1.f;
#pragma unroll
            for (int nt = 0; nt < 4; nt++) {
                int n = n0 + wn * 32 + nt * 8 + tig * 2;
                if (n < N) {
                    float v0 = c[mt][nt][r * 2 + 0];
                    float v1 = c[mt][nt][r * 2 + 1];
                    if (Cin) {
                        v0 += Cin[(long)m * ldc + n];
                        v1 += Cin[(long)m * ldc + n + 1];
                    }
                    if (bias) { v0 += bias[n]; v1 += bias[n + 1]; }
                    if (relu) { v0 = fmaxf(v0, 0.f); v1 = fmaxf(v1, 0.f); }
                    v0 *= rsv; v1 *= rsv;
                    if (OUTH)
                        *(__half2*)(Ch + (long)m * ldc + n) = __floats2half2_rn(v0, v1);
                    else {
                        Cf[(long)m * ldc + n] = v0;
                        Cf[(long)m * ldc + n + 1] = v1;
                    }
                }
            }
        }
    }
}

// ---------------- conversion / helper kernels --------------------------------
__global__ void conv2h_k(const float* __restrict__ src, __half* __restrict__ dst,
                         int rows, int cols, int srcR, int srcC)
{
    long idx = (long)blockIdx.x * blockDim.x + threadIdx.x;
    if (idx >= (long)rows * cols) return;
    int r = (int)(idx / cols), c = (int)(idx % cols);
    float v = (r < srcR && c < srcC) ? src[(long)r * srcC + c] : 0.f;
    dst[idx] = __float2half_rn(v);
}

__global__ void gather_all_k(const int* __restrict__ s1, const int* __restrict__ s2)
{
    long row = blockIdx.x;                 // 0 .. 2*BL-1
    long r = row < BL ? row : row - BL;
    int tok = (row < BL) ? s1[r] : s2[r];
    int t = threadIdx.x;                   // 128 threads
    const uint4* esrc = (const uint4*)(g_embh + (long)tok * EP);
    uint4* edst = (uint4*)(g_eh + row * EP);
    if (t < 38) edst[t] = esrc[t];
    const uint4* hsrc = (const uint4*)(g_hvh + (long)tok * Hsz);
    uint4* hdst = (uint4*)(g_phh + row * Hsz);
    if (t >= 40 && t < 65) hdst[t - 40] = hsrc[t - 40];
    const float4* csrc = (const float4*)(g_cv + (long)tok * Hsz);
    float4* cdst = (float4*)(g_pta + row * Hsz);
    if (t >= 66 && t < 116) cdst[t - 66] = csrc[t - 66];
}

__global__ void mask_k(const int* __restrict__ len1, const int* __restrict__ len2)
{
    long idx = (long)blockIdx.x * blockDim.x + threadIdx.x;
    if (idx >= 2 * BL) return;
    int seq = (int)(idx / BL);
    long r = idx % BL;
    int b = (int)(r / Lsz), l = (int)(r % Lsz);
    int len = seq ? len2[b] : len1[b];
    g_mask[idx] = (l < len) ? 1.f : 0.f;
}

__global__ void bmax_k()
{
    __shared__ float sm[1024];
    int b = blockIdx.x;
    const float4* p = (const float4*)(g_scores + (long)b * LL);
    float m = -1e30f;
    for (int i = threadIdx.x; i < LL / 4; i += 1024) {
        float4 v = p[i];
        m = fmaxf(fmaxf(m, v.x), fmaxf(fmaxf(v.y, v.z), v.w));
    }
    sm[threadIdx.x] = m;
    __syncthreads();
    for (int o = 512; o; o >>= 1) {
        if (threadIdx.x < o) sm[threadIdx.x] = fmaxf(sm[threadIdx.x], sm[threadIdx.x + o]);
        __syncthreads();
    }
    if (threadIdx.x == 0) g_bmax[b] = sm[0];
}

__global__ void softpre_k()
{
    __shared__ float sm[1024];
    int b = blockIdx.x;
    int j = threadIdx.x & 255, s = threadIdx.x >> 8;
    long base = (long)b * LL;
    float Mb  = g_bmax[b];
    float m2j = g_mask[BL + (long)b * Lsz + j];
    float da = 0.f;
    for (int i = s * 64; i < s * 64 + 64; i++) {
        long idx = base + (long)i * Lsz + j;
        float p = __expf(g_scores[idx] - Mb);
        float q = p * g_mask[(long)b * Lsz + i];
        da += q;
        g_ea[idx] = q;
        g_scores[idx] = p * m2j;
    }
    sm[threadIdx.x] = da;
    __syncthreads();
    if (s == 0)
        g_rsa[(long)b * Lsz + j] = m2j / (sm[j] + sm[j + 256] + sm[j + 512] + sm[j + 768]);
}

__global__ void rowsum_k()
{
    long row = (long)blockIdx.x * 8 + (threadIdx.x >> 5);
    int lane = threadIdx.x & 31;
    const float* p = g_scores + row * Lsz;
    float s = 0.f;
    for (int j = lane; j < Lsz; j += 32) s += p[j];
#pragma unroll
    for (int o = 16; o; o >>= 1) s += __shfl_xor_sync(~0u, s, o);
    if (lane == 0) g_rsb[row] = g_mask[row] / s;
}

__global__ void normexp_k()
{
    long idx = (long)blockIdx.x * blockDim.x + threadIdx.x;
    long r = idx >> 8;
    int j = (int)(idx & 255);
    long b = r >> 8;
    g_eanh[idx] = __float2half_rn(g_ea[idx] * g_rsa[b * Lsz + j]);
    g_ebnh[idx] = __float2half_rn(g_scores[idx] * g_rsb[r]);
}

__global__ void colsum_k()
{
    __shared__ float sm[1024];
    int b2 = blockIdx.x;
    int h = threadIdx.x & 255, s = threadIdx.x >> 8;
    float acc = 0.f;
    if (h < Hsz) {
        const __half* p = g_hoh + (long)b2 * Lsz * Hsz;
#pragma unroll 4
        for (int l = s * 64; l < s * 64 + 64; l++) acc += __half2float(p[(long)l * Hsz + h]);
    }
    sm[threadIdx.x] = acc;
    __syncthreads();
    if (s == 0 && h < Hsz) {
        int b = (b2 < Bsz) ? b2 : b2 - Bsz;
        int off = (b2 < Bsz) ? 0 : Hsz;
        g_vch[(long)b * 2 * Hsz + off + h] =
            __float2half_rn(sm[h] + sm[h + 256] + sm[h + 512] + sm[h + 768]);
    }
}

__global__ void final_k(const float* __restrict__ W2g,
                        const float* __restrict__ b2g, float* __restrict__ out)
{
    int b = blockIdx.x;
    int o = threadIdx.x >> 5;
    int lane = threadIdx.x & 31;
    const float* u = g_u + (long)b * Hsz;
    float s = 0.f;
    for (int h = lane; h < Hsz; h += 32) s += u[h] * W2g[h * 2 + o];
#pragma unroll
    for (int off = 16; off; off >>= 1) s += __shfl_xor_sync(~0u, s, off);
    if (lane == 0) out[b * 2 + o] = s + b2g[o];
}

// ---------------- launch -----------------------------------------------------
extern "C" void kernel_launch(void* const* d_in, const int* in_sizes, int n_in,
                              void* d_out, int out_size)
{
    const float* emb = (const float*)d_in[0];
    const float* W1a = (const float*)d_in[1];
    const float* b1a = (const float*)d_in[2];
    const float* W2a = (const float*)d_in[3];
    const float* b2a = (const float*)d_in[4];
    const float* W1c = (const float*)d_in[5];
    const float* b1c = (const float*)d_in[6];
    const float* W2c = (const float*)d_in[7];
    const float* b2c = (const float*)d_in[8];
    const float* W1g = (const float*)d_in[9];
    const float* b1g = (const float*)d_in[10];
    const float* W2g = (const float*)d_in[11];
    const float* b2g = (const float*)d_in[12];
    const int* s1   = (const int*)d_in[13];
    const int* s2   = (const int*)d_in[14];
    const int* len1 = (const int*)d_in[15];
    const int* len2 = (const int*)d_in[16];
    float* out = (float*)d_out;

    __half *pembh, *pW1a, *pW2a, *pW1cT, *pW1cB, *pW2c, *pW1g;
    __half *ptvh, *phvh, *peh, *pphh, *peanh, *pebnh, *pabh, *pthh, *phoh, *pvch;
    float *pcv, *ppta, *pmask, *pu, *psc;
    cudaGetSymbolAddress((void**)&pembh, g_embh);
    cudaGetSymbolAddress((void**)&pW1a,  g_W1a);
    cudaGetSymbolAddress((void**)&pW2a,  g_W2a);
    cudaGetSymbolAddress((void**)&pW1cT, g_W1cT);
    cudaGetSymbolAddress((void**)&pW1cB, g_W1cB);
    cudaGetSymbolAddress((void**)&pW2c,  g_W2c);
    cudaGetSymbolAddress((void**)&pW1g,  g_W1g);
    cudaGetSymbolAddress((void**)&ptvh,  g_tvh);
    cudaGetSymbolAddress((void**)&phvh,  g_hvh);
    cudaGetSymbolAddress((void**)&peh,   g_eh);
    cudaGetSymbolAddress((void**)&pphh,  g_phh);
    cudaGetSymbolAddress((void**)&peanh, g_eanh);
    cudaGetSymbolAddress((void**)&pebnh, g_ebnh);
    cudaGetSymbolAddress((void**)&pabh,  g_abh);
    cudaGetSymbolAddress((void**)&pthh,  g_thh);
    cudaGetSymbolAddress((void**)&phoh,  g_hoh);
    cudaGetSymbolAddress((void**)&pvch,  g_vch);
    cudaGetSymbolAddress((void**)&pcv,   g_cv);
    cudaGetSymbolAddress((void**)&ppta,  g_pta);
    cudaGetSymbolAddress((void**)&pmask, g_mask);
    cudaGetSymbolAddress((void**)&pu,    g_u);
    cudaGetSymbolAddress((void**)&psc,   g_scores);

    const int M2 = (int)(2 * BL);          // 262144
    const unsigned MV = (VOC + 127) / 128; // 391
    auto cdiv = [](long n, long d) { return (unsigned)((n + d - 1) / d); };

    // 0. fp32 -> fp16 conversions (emb + weights, zero-padded)
    conv2h_k<<<cdiv((long)VOC * EP, 256), 256>>>(emb, pembh, VOC, EP, VOC, Esz);
    conv2h_k<<<cdiv(EP * Hsz, 256), 256>>>(W1a, pW1a, EP, Hsz, Esz, Hsz);
    conv2h_k<<<cdiv(Hsz * Hsz, 256), 256>>>(W2a, pW2a, Hsz, Hsz, Hsz, Hsz);
    conv2h_k<<<cdiv(EP * Hsz, 256), 256>>>(W1c, pW1cT, EP, Hsz, Esz, Hsz);
    conv2h_k<<<cdiv(EP * Hsz, 256), 256>>>(W1c + (long)Esz * Hsz, pW1cB, EP, Hsz, Esz, Hsz);
    conv2h_k<<<cdiv(Hsz * Hsz, 256), 256>>>(W2c, pW2c, Hsz, Hsz, Hsz, Hsz);
    conv2h_k<<<cdiv(2 * Hsz * Hsz, 256), 256>>>(W1g, pW1g, 2 * Hsz, Hsz, 2 * Hsz, Hsz);

    // 1. per-vocab precompute
    gemm_h<false,false,true><<<dim3(2, MV, 1), 256>>>(
        pembh, 0, EP, pW1a, 0, Hsz, b1a, nullptr, 0, nullptr,
        ptvh, 0, Hsz, VOC, Hsz, EP, 1);
    gemm_h<false,false,true><<<dim3(2, MV, 1), 256>>>(
        ptvh, 0, Hsz, pW2a, 0, Hsz, b2a, nullptr, 0, nullptr,
        phvh, 0, Hsz, VOC, Hsz, Hsz, 1);
    gemm_h<false,false,false><<<dim3(2, MV, 1), 256>>>(
        pembh, 0, EP, pW1cT, 0, Hsz, nullptr, nullptr, 0, nullptr,
        pcv, 0, Hsz, VOC, Hsz, EP, 0);

    // 2. gather into token space + masks
    gather_all_k<<<(unsigned)(2 * BL), 128>>>(s1, s2);
    mask_k<<<cdiv(2 * BL, 256), 256>>>(len1, len2);

    // 3. scores[b] = h1[b] @ h2[b]^T  (fp16 in, fp32 out)
    gemm_h<false,true,false><<<dim3(2, 2, Bsz), 256>>>(
        pphh, (long)Lsz * Hsz, Hsz, pphh + BL * Hsz, (long)Lsz * Hsz, Hsz,
        nullptr, nullptr, 0, nullptr,
        psc, LL, Lsz, Lsz, Lsz, Hsz, 0);

    // 4. softmax stage
    bmax_k<<<Bsz, 1024>>>();
    softpre_k<<<Bsz, 1024>>>();
    rowsum_k<<<(unsigned)(BL / 8), 256>>>();
    normexp_k<<<(unsigned)(BLL / 256), 256>>>();

    // 5. alphas = ean^T @ e1 (TN) -> abh second half; betas = ebn @ e2 -> first
    gemm_h<true,false,true><<<dim3(3, 2, Bsz), 256>>>(
        peanh, LL, Lsz, peh, (long)Lsz * EP, EP, nullptr, nullptr, 0, nullptr,
        pabh + BL * EP, (long)Lsz * EP, EP, Lsz, EP, Lsz, 0);
    gemm_h<false,false,true><<<dim3(3, 2, Bsz), 256>>>(
        pebnh, LL, Lsz, peh + BL * EP, (long)Lsz * EP, EP, nullptr, nullptr, 0, nullptr,
        pabh, (long)Lsz * EP, EP, Lsz, EP, Lsz, 0);

    // 6. compare_ff: th = relu(pta + ab@W1cB + b1c); ho = relu(th@W2c + b2c)*mask
    gemm_h<false,false,true><<<dim3(2, M2 / 128, 1), 256>>>(
        pabh, 0, EP, pW1cB, 0, Hsz, b1c, nullptr, 0, ppta,
        pthh, 0, Hsz, M2, Hsz, EP, 1);
    gemm_h<false,false,true><<<dim3(2, M2 / 128, 1), 256>>>(
        pthh, 0, Hsz, pW2c, 0, Hsz, b2c, pmask, 0, nullptr,
        phoh, 0, Hsz, M2, Hsz, Hsz, 1);

    // 7. masked sums -> vcat ; aggregate head
    colsum_k<<<2 * Bsz, 1024>>>();
    gemm_h<false,false,false><<<dim3(2, 4, 1), 256>>>(
        pvch, 0, 2 * Hsz, pW1g, 0, Hsz, b1g, nullptr, 0, nullptr,
        pu, 0, Hsz, Bsz, Hsz, 2 * Hsz, 1);
    final_k<<<Bsz, 64>>>(W2g, b2g, out);
}

// round 7
// speedup vs baseline: 7.2849x; 1.1981x over previous
#include <cuda_runtime.h>
#include <cuda_fp16.h>
#include <cstdint>

// Problem constants
#define Bsz 512
#define Lsz 256
#define Esz 300
#define EP  304              // padded E (16B-aligned fp16 rows)
#define Hsz 200
#define VOC 50000
constexpr long BL  = (long)Bsz * Lsz;      // 131072
constexpr long LL  = (long)Lsz * Lsz;      // 65536
constexpr long BLL = BL * Lsz;             // 33,554,432

// ---------------- device scratch (static, no runtime allocation) -------------
__device__ __half g_embh[(long)VOC * EP];
__device__ __half g_W1a[EP * Hsz];
__device__ __half g_W2a[Hsz * Hsz];
__device__ __half g_W1cT[EP * Hsz];
__device__ __half g_W1cB[EP * Hsz];
__device__ __half g_W2c[Hsz * Hsz];
__device__ __half g_W1g[2 * Hsz * Hsz];
__device__ __half g_tvh[(long)VOC * Hsz];   // vocab attend L1 out
__device__ __half g_hvh[(long)VOC * Hsz];   // vocab attend_ff out
__device__ __half g_cvh[(long)VOC * Hsz];   // vocab e@W1c (top half, no bias)
__device__ __half g_eanh[BLL];              // normalized alpha weights
__device__ __half g_ebnh[BLL];              // normalized beta weights
__device__ __half g_abh[2 * BL * EP];       // [betas ; alphas]
__device__ __half g_thh[2 * BL * Hsz];      // compare hidden
__device__ __half g_hoh[2 * BL * Hsz];      // compare out (masked)
__device__ __half g_vch[Bsz * 2 * Hsz];     // vcat
__device__ float    g_scores[BLL];
__device__ float    g_mask[2 * BL];
__device__ int      g_tok[2 * BL];
__device__ unsigned g_bmaxu[Bsz];           // encoded per-batch max
__device__ float    g_u[Bsz * Hsz];

// ---------------- PTX helpers ------------------------------------------------
__device__ __forceinline__ void cp16(uint32_t dst, const void* src, bool pred)
{
    int sz = pred ? 16 : 0;
    asm volatile("cp.async.cg.shared.global [%0], [%1], 16, %2;"
                 :: "r"(dst), "l"(src), "r"(sz));
}
__device__ __forceinline__ void cp_commit() { asm volatile("cp.async.commit_group;"); }
template <int N>
__device__ __forceinline__ void cp_wait() { asm volatile("cp.async.wait_group %0;" :: "n"(N)); }

__device__ __forceinline__ void ldsm4(uint32_t* r, uint32_t a)
{
    asm volatile("ldmatrix.sync.aligned.m8n8.x4.shared.b16 {%0,%1,%2,%3}, [%4];"
                 : "=r"(r[0]), "=r"(r[1]), "=r"(r[2]), "=r"(r[3]) : "r"(a));
}
__device__ __forceinline__ void ldsm4t(uint32_t* r, uint32_t a)
{
    asm volatile("ldmatrix.sync.aligned.m8n8.x4.trans.shared.b16 {%0,%1,%2,%3}, [%4];"
                 : "=r"(r[0]), "=r"(r[1]), "=r"(r[2]), "=r"(r[3]) : "r"(a));
}
__device__ __forceinline__ void ldsm2(uint32_t* r, uint32_t a)
{
    asm volatile("ldmatrix.sync.aligned.m8n8.x2.shared.b16 {%0,%1}, [%2];"
                 : "=r"(r[0]), "=r"(r[1]) : "r"(a));
}
__device__ __forceinline__ void ldsm2t(uint32_t* r, uint32_t a)
{
    asm volatile("ldmatrix.sync.aligned.m8n8.x2.trans.shared.b16 {%0,%1}, [%2];"
                 : "=r"(r[0]), "=r"(r[1]) : "r"(a));
}
__device__ __forceinline__ void mma16816(float c[4], const uint32_t a[4], const uint32_t b[2])
{
    asm volatile(
        "mma.sync.aligned.m16n8k16.row.col.f32.f16.f16.f32 "
        "{%0,%1,%2,%3}, {%4,%5,%6,%7}, {%8,%9}, {%0,%1,%2,%3};"
        : "+f"(c[0]), "+f"(c[1]), "+f"(c[2]), "+f"(c[3])
        : "r"(a[0]), "r"(a[1]), "r"(a[2]), "r"(a[3]), "r"(b[0]), "r"(b[1]));
}

// ordered-uint encoding of float for atomicMax (monotone)
__device__ __forceinline__ unsigned fenc(float f)
{
    unsigned u = __float_as_uint(f);
    return (u & 0x80000000u) ? ~u : (u | 0x80000000u);
}
__device__ __forceinline__ float fdec(unsigned e)
{
    return (e & 0x80000000u) ? __uint_as_float(e & 0x7FFFFFFFu)
                             : __uint_as_float(~e);
}

// ---------------- 128x128x32 fp16 tensor GEMM, 2-stage cp.async + LDSM -------
// C[bz][m,n] = epi( sum_k A(m,k) * B(k,n) ), fp32 accumulate.
// TA: A[m,k]=A[k*lda+m]; TB: B[k,n]=B[n*ldb+k].
// iA (only !TA): source row of A-row m is iA[bz*256+m] (caller passes sA=0).
// iB: source row of B's leading dim (k if !TB, n if TB) is iB[bz*256+row].
// epilogue: v = acc (+ Cin[tok,m?]) (+ bias[n]); relu; * rs[bz*sRS+m];
//           optional per-batch atomicMax into bmaxu (exact tiles only).
template <bool TA, bool TB, bool OUTH>
__global__ __launch_bounds__(256)
void gemm_h(const __half* __restrict__ A, long sA, int lda, const int* __restrict__ iA,
            const __half* __restrict__ Bw, long sB, int ldb, const int* __restrict__ iB,
            const float* __restrict__ bias,
            const float* __restrict__ rs, int sRS,
            const __half* __restrict__ Cin, const int* __restrict__ iC,
            void* __restrict__ Cv, long sC, int ldc,
            int M, int N, int K, int relu, unsigned* bmaxu)
{
    constexpr int A_SZ = TA ? 32 * 136 : 128 * 40;   // halfs per stage
    constexpr int B_SZ = TB ? 128 * 40 : 32 * 136;
    __shared__ __half As[2][A_SZ];
    __shared__ __half Bs[2][B_SZ];

    int bz = blockIdx.z;
    const __half* Ab = A + (long)bz * sA;
    const __half* Bb = Bw + (long)bz * sB;
    int m0 = blockIdx.y * 128, n0 = blockIdx.x * 128;
    int tid = threadIdx.x;
    int wid = tid >> 5, lane = tid & 31;
    int wm = wid >> 2, wn = wid & 3;
    int g = lane >> 2, tig = lane & 3;

    uint32_t abase = (uint32_t)__cvta_generic_to_shared(&As[0][0]);
    uint32_t bbase = (uint32_t)__cvta_generic_to_shared(&Bs[0][0]);

    float c[4][4][4];
#pragma unroll
    for (int i = 0; i < 4; i++)
#pragma unroll
        for (int j = 0; j < 4; j++)
#pragma unroll
            for (int q = 0; q < 4; q++) c[i][j][q] = 0.f;

    int KT = (K + 31) / 32;

    auto load_stage = [&](int st, int k0) {
#pragma unroll
        for (int it = 0; it < 2; it++) {
            int id = tid + it * 256;
            if (!TA) {
                int row = id >> 2, c8 = (id & 3) * 8;
                bool p = (m0 + row < M) && (k0 + c8 < K);
                long rg = iA ? (p ? (long)iA[bz * 256 + m0 + row] : 0)
                             : (long)(m0 + row);
                cp16(abase + (uint32_t)(st * A_SZ + row * 40 + c8) * 2,
                     Ab + rg * lda + k0 + c8, p);
            } else {
                int kr = id >> 4, c8 = (id & 15) * 8;
                bool p = (k0 + kr < K) && (m0 + c8 < M);
                cp16(abase + (uint32_t)(st * A_SZ + kr * 136 + c8) * 2,
                     Ab + (long)(k0 + kr) * lda + m0 + c8, p);
            }
            if (!TB) {
                int kr = id >> 4, c8 = (id & 15) * 8;
                bool p = (k0 + kr < K) && (n0 + c8 < N);
                long rg = iB ? ((k0 + kr < K) ? (long)iB[bz * 256 + k0 + kr] : 0)
                             : (long)(k0 + kr);
                cp16(bbase + (uint32_t)(st * B_SZ + kr * 136 + c8) * 2,
                     Bb + rg * ldb + n0 + c8, p);
            } else {
                int row = id >> 2, c8 = (id & 3) * 8;
                bool p = (n0 + row < N) && (k0 + c8 < K);
                long rg = iB ? ((n0 + row < N) ? (long)iB[bz * 256 + n0 + row] : 0)
                             : (long)(n0 + row);
                cp16(bbase + (uint32_t)(st * B_SZ + row * 40 + c8) * 2,
                     Bb + rg * ldb + k0 + c8, p);
            }
        }
        cp_commit();
    };

    load_stage(0, 0);

    for (int kt = 0; kt < KT; kt++) {
        if (kt + 1 < KT) { load_stage((kt + 1) & 1, (kt + 1) * 32); cp_wait<1>(); }
        else             { cp_wait<0>(); }
        __syncthreads();
        int st = kt & 1;
        uint32_t ab2 = abase + (uint32_t)(st * A_SZ) * 2;
        uint32_t bb2 = bbase + (uint32_t)(st * B_SZ) * 2;

#pragma unroll
        for (int s2 = 0; s2 < 2; s2++) {
            int ks = s2 * 16;
            uint32_t af[4][4], bf[4][2];
#pragma unroll
            for (int mt = 0; mt < 4; mt++) {
                if (!TA) {
                    int m = wm * 64 + mt * 16 + (lane & 15);
                    int kc = ks + ((lane >> 4) << 3);
                    ldsm4(af[mt], ab2 + (uint32_t)(m * 40 + kc) * 2);
                } else {
                    int kr = ks + (lane & 7) + ((lane >> 4) << 3);
                    int mc = wm * 64 + mt * 16 + (((lane >> 3) & 1) << 3);
                    ldsm4t(af[mt], ab2 + (uint32_t)(kr * 136 + mc) * 2);
                }
            }
#pragma unroll
            for (int nt = 0; nt < 4; nt++) {
                if (TB) {
                    int n = wn * 32 + nt * 8 + (lane & 7);
                    int kc = ks + (((lane >> 3) & 1) << 3);
                    ldsm2(bf[nt], bb2 + (uint32_t)(n * 40 + kc) * 2);
                } else {
                    int kr = ks + (lane & 7) + (((lane >> 3) & 1) << 3);
                    int nc = wn * 32 + nt * 8;
                    ldsm2t(bf[nt], bb2 + (uint32_t)(kr * 136 + nc) * 2);
                }
            }
#pragma unroll
            for (int mt = 0; mt < 4; mt++)
#pragma unroll
                for (int nt = 0; nt < 4; nt++)
                    mma16816(c[mt][nt], af[mt], bf[nt]);
        }
        __syncthreads();
    }

    __half* Ch = (__half*)Cv + (long)bz * sC;
    float*  Cf = (float*)Cv + (long)bz * sC;
#pragma unroll
    for (int mt = 0; mt < 4; mt++) {
#pragma unroll
        for (int r = 0; r < 2; r++) {
            int m = m0 + wm * 64 + mt * 16 + g + r * 8;
            if (m >= M) continue;
            float rsv = rs ? rs[(long)bz * sRS + m] : 1.f;
            long crow = 0;
            if (Cin) crow = iC ? (long)iC[bz * 256 + m] : (long)m;
#pragma unroll
            for (int nt = 0; nt < 4; nt++) {
                int n = n0 + wn * 32 + nt * 8 + tig * 2;
                if (n < N) {
                    float v0 = c[mt][nt][r * 2 + 0];
                    float v1 = c[mt][nt][r * 2 + 1];
                    if (Cin) {
                        v0 += __half2float(Cin[crow * ldc + n]);
                        v1 += __half2float(Cin[crow * ldc + n + 1]);
                    }
                    if (bias) { v0 += bias[n]; v1 += bias[n + 1]; }
                    if (relu) { v0 = fmaxf(v0, 0.f); v1 = fmaxf(v1, 0.f); }
                    v0 *= rsv; v1 *= rsv;
                    if (OUTH)
                        *(__half2*)(Ch + (long)m * ldc + n) = __floats2half2_rn(v0, v1);
                    else {
                        Cf[(long)m * ldc + n] = v0;
                        Cf[(long)m * ldc + n + 1] = v1;
                    }
                }
            }
        }
    }

    if (bmaxu) {   // per-batch max of this block's outputs (exact tiles only)
        float mx = -1e30f;
#pragma unroll
        for (int mt = 0; mt < 4; mt++)
#pragma unroll
            for (int nt = 0; nt < 4; nt++)
#pragma unroll
                for (int q = 0; q < 4; q++) mx = fmaxf(mx, c[mt][nt][q]);
#pragma unroll
        for (int o = 16; o; o >>= 1) mx = fmaxf(mx, __shfl_xor_sync(~0u, mx, o));
        if (lane == 0) atomicMax(&bmaxu[bz], fenc(mx));
    }
}

// ---------------- helper kernels ---------------------------------------------
__global__ void conv2h_k(const float* __restrict__ src, __half* __restrict__ dst,
                         int rows, int cols, int srcR, int srcC)
{
    long idx = (long)blockIdx.x * blockDim.x + threadIdx.x;
    if (idx >= (long)rows * cols) return;
    int r = (int)(idx / cols), c = (int)(idx % cols);
    float v = (r < srcR && c < srcC) ? src[(long)r * srcC + c] : 0.f;
    dst[idx] = __float2half_rn(v);
}

// masks + token index concat + bmax init
__global__ void mask_k(const int* __restrict__ s1, const int* __restrict__ s2,
                       const int* __restrict__ len1, const int* __restrict__ len2)
{
    long idx = (long)blockIdx.x * blockDim.x + threadIdx.x;
    if (idx >= 2 * BL) return;
    int seq = (int)(idx / BL);
    long r = idx % BL;
    int b = (int)(r / Lsz), l = (int)(r % Lsz);
    int len = seq ? len2[b] : len1[b];
    g_mask[idx] = (l < len) ? 1.f : 0.f;
    g_tok[idx] = seq ? s2[r] : s1[r];
    if (idx < Bsz) g_bmaxu[idx] = 0u;
}

// Fused softmax: per batch, 1024 threads (j = tid&255, slice s = tid>>8).
// pass1: column sums (q = p*m1i) -> rsa; row sums (p*m2j) via warp-reduce +
//        smem atomicAdd -> rsb.  pass2: recompute p, write fp16 ean/ebn.
__global__ void sums_k()
{
    __shared__ float rowacc[256];
    __shared__ float colsm[1024];
    __shared__ float rsa_s[256];
    __shared__ float rsb_s[256];
    int b = blockIdx.x;
    int tid = threadIdx.x;
    int j = tid & 255, s = tid >> 8, lane = tid & 31;
    if (tid < 256) rowacc[tid] = 0.f;
    __syncthreads();

    long base = (long)b * LL;
    float Mb  = fdec(g_bmaxu[b]);
    float m2j = g_mask[BL + (long)b * Lsz + j];
    float da = 0.f;
    for (int t = 0; t < 64; t++) {
        int i = s * 64 + t;
        float p = __expf(g_scores[base + (long)i * Lsz + j] - Mb);
        da += p * g_mask[(long)b * Lsz + i];
        float v = p * m2j;
#pragma unroll
        for (int o = 16; o; o >>= 1) v += __shfl_xor_sync(~0u, v, o);
        if (lane == 0) atomicAdd(&rowacc[i], v);
    }
    colsm[tid] = da;
    __syncthreads();
    if (s == 0)
        rsa_s[j] = m2j / (colsm[j] + colsm[j + 256] + colsm[j + 512] + colsm[j + 768]);
    if (tid < 256)
        rsb_s[tid] = g_mask[(long)b * Lsz + tid] / rowacc[tid];
    __syncthreads();

    float rsaj = rsa_s[j];
    for (int t = 0; t < 64; t++) {
        int i = s * 64 + t;
        long idx = base + (long)i * Lsz + j;
        float p = __expf(g_scores[idx] - Mb);
        g_eanh[idx] = __float2half_rn(p * g_mask[(long)b * Lsz + i] * rsaj);
        g_ebnh[idx] = __float2half_rn(p * m2j * rsb_s[i]);
    }
}

__global__ void colsum_k()
{
    __shared__ float sm[1024];
    int b2 = blockIdx.x;
    int h = threadIdx.x & 255, s = threadIdx.x >> 8;
    float acc = 0.f;
    if (h < Hsz) {
        const __half* p = g_hoh + (long)b2 * Lsz * Hsz;
#pragma unroll 4
        for (int l = s * 64; l < s * 64 + 64; l++) acc += __half2float(p[(long)l * Hsz + h]);
    }
    sm[threadIdx.x] = acc;
    __syncthreads();
    if (s == 0 && h < Hsz) {
        int b = (b2 < Bsz) ? b2 : b2 - Bsz;
        int off = (b2 < Bsz) ? 0 : Hsz;
        g_vch[(long)b * 2 * Hsz + off + h] =
            __float2half_rn(sm[h] + sm[h + 256] + sm[h + 512] + sm[h + 768]);
    }
}

__global__ void final_k(const float* __restrict__ W2g,
                        const float* __restrict__ b2g, float* __restrict__ out)
{
    int b = blockIdx.x;
    int o = threadIdx.x >> 5;
    int lane = threadIdx.x & 31;
    const float* u = g_u + (long)b * Hsz;
    float s = 0.f;
    for (int h = lane; h < Hsz; h += 32) s += u[h] * W2g[h * 2 + o];
#pragma unroll
    for (int off = 16; off; off >>= 1) s += __shfl_xor_sync(~0u, s, off);
    if (lane == 0) out[b * 2 + o] = s + b2g[o];
}

// ---------------- launch -----------------------------------------------------
extern "C" void kernel_launch(void* const* d_in, const int* in_sizes, int n_in,
                              void* d_out, int out_size)
{
    const float* emb = (const float*)d_in[0];
    const float* W1a = (const float*)d_in[1];
    const float* b1a = (const float*)d_in[2];
    const float* W2a = (const float*)d_in[3];
    const float* b2a = (const float*)d_in[4];
    const float* W1c = (const float*)d_in[5];
    const float* b1c = (const float*)d_in[6];
    const float* W2c = (const float*)d_in[7];
    const float* b2c = (const float*)d_in[8];
    const float* W1g = (const float*)d_in[9];
    const float* b1g = (const float*)d_in[10];
    const float* W2g = (const float*)d_in[11];
    const float* b2g = (const float*)d_in[12];
    const int* s1   = (const int*)d_in[13];
    const int* s2   = (const int*)d_in[14];
    const int* len1 = (const int*)d_in[15];
    const int* len2 = (const int*)d_in[16];
    float* out = (float*)d_out;

    __half *pembh, *pW1a, *pW2a, *pW1cT, *pW1cB, *pW2c, *pW1g;
    __half *ptvh, *phvh, *pcvh, *peanh, *pebnh, *pabh, *pthh, *phoh, *pvch;
    float *pmask, *pu, *psc;
    int *ptok;
    unsigned *pbmx;
    cudaGetSymbolAddress((void**)&pembh, g_embh);
    cudaGetSymbolAddress((void**)&pW1a,  g_W1a);
    cudaGetSymbolAddress((void**)&pW2a,  g_W2a);
    cudaGetSymbolAddress((void**)&pW1cT, g_W1cT);
    cudaGetSymbolAddress((void**)&pW1cB, g_W1cB);
    cudaGetSymbolAddress((void**)&pW2c,  g_W2c);
    cudaGetSymbolAddress((void**)&pW1g,  g_W1g);
    cudaGetSymbolAddress((void**)&ptvh,  g_tvh);
    cudaGetSymbolAddress((void**)&phvh,  g_hvh);
    cudaGetSymbolAddress((void**)&pcvh,  g_cvh);
    cudaGetSymbolAddress((void**)&peanh, g_eanh);
    cudaGetSymbolAddress((void**)&pebnh, g_ebnh);
    cudaGetSymbolAddress((void**)&pabh,  g_abh);
    cudaGetSymbolAddress((void**)&pthh,  g_thh);
    cudaGetSymbolAddress((void**)&phoh,  g_hoh);
    cudaGetSymbolAddress((void**)&pvch,  g_vch);
    cudaGetSymbolAddress((void**)&pmask, g_mask);
    cudaGetSymbolAddress((void**)&pu,    g_u);
    cudaGetSymbolAddress((void**)&psc,   g_scores);
    cudaGetSymbolAddress((void**)&ptok,  g_tok);
    cudaGetSymbolAddress((void**)&pbmx,  g_bmaxu);

    const int M2 = (int)(2 * BL);          // 262144
    const unsigned MV = (VOC + 127) / 128; // 391
    auto cdiv = [](long n, long d) { return (unsigned)((n + d - 1) / d); };

    // 0. fp32 -> fp16 conversions (emb + weights, zero-padded)
    conv2h_k<<<cdiv((long)VOC * EP, 256), 256>>>(emb, pembh, VOC, EP, VOC, Esz);
    conv2h_k<<<cdiv(EP * Hsz, 256), 256>>>(W1a, pW1a, EP, Hsz, Esz, Hsz);
    conv2h_k<<<cdiv(Hsz * Hsz, 256), 256>>>(W2a, pW2a, Hsz, Hsz, Hsz, Hsz);
    conv2h_k<<<cdiv(EP * Hsz, 256), 256>>>(W1c, pW1cT, EP, Hsz, Esz, Hsz);
    conv2h_k<<<cdiv(EP * Hsz, 256), 256>>>(W1c + (long)Esz * Hsz, pW1cB, EP, Hsz, Esz, Hsz);
    conv2h_k<<<cdiv(Hsz * Hsz, 256), 256>>>(W2c, pW2c, Hsz, Hsz, Hsz, Hsz);
    conv2h_k<<<cdiv(2 * Hsz * Hsz, 256), 256>>>(W1g, pW1g, 2 * Hsz, Hsz, 2 * Hsz, Hsz);

    // masks + tok + bmax init (independent of vocab GEMMs)
    mask_k<<<cdiv(2 * BL, 256), 256>>>(s1, s2, len1, len2);

    // 1. per-vocab precompute
    gemm_h<false,false,true><<<dim3(2, MV, 1), 256>>>(
        pembh, 0, EP, nullptr, pW1a, 0, Hsz, nullptr, b1a, nullptr, 0,
        nullptr, nullptr, ptvh, 0, Hsz, VOC, Hsz, EP, 1, nullptr);
    gemm_h<false,false,true><<<dim3(2, MV, 1), 256>>>(
        ptvh, 0, Hsz, nullptr, pW2a, 0, Hsz, nullptr, b2a, nullptr, 0,
        nullptr, nullptr, phvh, 0, Hsz, VOC, Hsz, Hsz, 1, nullptr);
    gemm_h<false,false,true><<<dim3(2, MV, 1), 256>>>(
        pembh, 0, EP, nullptr, pW1cT, 0, Hsz, nullptr, nullptr, nullptr, 0,
        nullptr, nullptr, pcvh, 0, Hsz, VOC, Hsz, EP, 0, nullptr);

    // 2. scores[b] = h1[b] @ h2[b]^T  (indexed rows of hv; epilogue batch-max)
    gemm_h<false,true,false><<<dim3(2, 2, Bsz), 256>>>(
        phvh, 0, Hsz, s1, phvh, 0, Hsz, s2, nullptr, nullptr, 0,
        nullptr, nullptr, psc, LL, Lsz, Lsz, Lsz, Hsz, 0, pbmx);

    // 3. fused softmax -> fp16 ean / ebn
    sums_k<<<Bsz, 1024>>>();

    // 4. alphas = ean^T @ e1 (TN, B rows indexed by s1) -> abh second half
    gemm_h<true,false,true><<<dim3(3, 2, Bsz), 256>>>(
        peanh, LL, Lsz, nullptr, pembh, 0, EP, s1, nullptr, nullptr, 0,
        nullptr, nullptr, pabh + BL * EP, (long)Lsz * EP, EP, Lsz, EP, Lsz, 0, nullptr);
    //    betas = ebn @ e2 (B rows indexed by s2) -> abh first half
    gemm_h<false,false,true><<<dim3(3, 2, Bsz), 256>>>(
        pebnh, LL, Lsz, nullptr, pembh, 0, EP, s2, nullptr, nullptr, 0,
        nullptr, nullptr, pabh, (long)Lsz * EP, EP, Lsz, EP, Lsz, 0, nullptr);

    // 5. compare_ff: th = relu(cv[tok] + ab@W1cB + b1c); ho = relu(th@W2c+b2c)*mask
    gemm_h<false,false,true><<<dim3(2, M2 / 128, 1), 256>>>(
        pabh, 0, EP, nullptr, pW1cB, 0, Hsz, nullptr, b1c, nullptr, 0,
        pcvh, ptok, pthh, 0, Hsz, M2, Hsz, EP, 1, nullptr);
    gemm_h<false,false,true><<<dim3(2, M2 / 128, 1), 256>>>(
        pthh, 0, Hsz, nullptr, pW2c, 0, Hsz, nullptr, b2c, pmask, 0,
        nullptr, nullptr, phoh, 0, Hsz, M2, Hsz, Hsz, 1, nullptr);

    // 6. masked sums -> vcat ; aggregate head
    colsum_k<<<2 * Bsz, 1024>>>();
    gemm_h<false,false,false><<<dim3(2, 4, 1), 256>>>(
        pvch, 0, 2 * Hsz, nullptr, pW1g, 0, Hsz, nullptr, b1g, nullptr, 0,
        nullptr, nullptr, pu, 0, Hsz, Bsz, Hsz, 2 * Hsz, 1, nullptr);
    final_k<<<Bsz, 64>>>(W2g, b2g, out);
}

// round 8
// speedup vs baseline: 8.8022x; 1.2083x over previous
#include <cuda_runtime.h>
#include <cuda_fp16.h>
#include <cstdint>

// Problem constants
#define Bsz 512
#define Lsz 256
#define Esz 300
#define EP  304              // padded E (16B-aligned fp16 rows)
#define Hsz 200
#define VOC 50000
constexpr long BL  = (long)Bsz * Lsz;      // 131072
constexpr long LL  = (long)Lsz * Lsz;      // 65536
constexpr long BLL = BL * Lsz;             // 33,554,432

// ---------------- device scratch (static, no runtime allocation) -------------
__device__ __half g_embh[(long)VOC * EP];
__device__ __half g_W1a[EP * Hsz];
__device__ __half g_W2a[Hsz * Hsz];
__device__ __half g_W1cT[EP * Hsz];         // W1c rows 0..299   (top half)
__device__ __half g_W1cB[EP * Hsz];         // W1c rows 300..599 (bottom half)
__device__ __half g_W2c[Hsz * Hsz];
__device__ __half g_W1g[2 * Hsz * Hsz];
__device__ __half g_tvh[(long)VOC * Hsz];   // vocab attend L1 out
__device__ __half g_hvh[(long)VOC * Hsz];   // vocab attend_ff out
__device__ __half g_cvh[(long)VOC * Hsz];   // vocab e@W1c_top  (no bias)
__device__ __half g_cv2h[(long)VOC * Hsz];  // vocab e@W1c_bottom (no bias)
__device__ __half g_eanh[BLL];              // normalized alpha weights
__device__ __half g_ebnh[BLL];              // normalized beta weights
__device__ __half g_thh[2 * BL * Hsz];      // compare hidden
__device__ __half g_hoh[2 * BL * Hsz];      // compare out (masked)
__device__ __half g_vch[Bsz * 2 * Hsz];     // vcat
__device__ float    g_scores[BLL];
__device__ float    g_mask[2 * BL];
__device__ int      g_tok[2 * BL];
__device__ unsigned g_bmaxu[Bsz];           // encoded per-batch max
__device__ float    g_u[Bsz * Hsz];

// ---------------- PTX helpers ------------------------------------------------
__device__ __forceinline__ void cp16(uint32_t dst, const void* src, bool pred)
{
    int sz = pred ? 16 : 0;                 // sz=0 -> 16B zero-fill
    asm volatile("cp.async.cg.shared.global [%0], [%1], 16, %2;"
                 :: "r"(dst), "l"(src), "r"(sz));
}
__device__ __forceinline__ void cp_commit() { asm volatile("cp.async.commit_group;"); }
template <int N>
__device__ __forceinline__ void cp_wait() { asm volatile("cp.async.wait_group %0;" :: "n"(N)); }

__device__ __forceinline__ void ldsm4(uint32_t* r, uint32_t a)
{
    asm volatile("ldmatrix.sync.aligned.m8n8.x4.shared.b16 {%0,%1,%2,%3}, [%4];"
                 : "=r"(r[0]), "=r"(r[1]), "=r"(r[2]), "=r"(r[3]) : "r"(a));
}
__device__ __forceinline__ void ldsm4t(uint32_t* r, uint32_t a)
{
    asm volatile("ldmatrix.sync.aligned.m8n8.x4.trans.shared.b16 {%0,%1,%2,%3}, [%4];"
                 : "=r"(r[0]), "=r"(r[1]), "=r"(r[2]), "=r"(r[3]) : "r"(a));
}
__device__ __forceinline__ void ldsm2(uint32_t* r, uint32_t a)
{
    asm volatile("ldmatrix.sync.aligned.m8n8.x2.shared.b16 {%0,%1}, [%2];"
                 : "=r"(r[0]), "=r"(r[1]) : "r"(a));
}
__device__ __forceinline__ void ldsm2t(uint32_t* r, uint32_t a)
{
    asm volatile("ldmatrix.sync.aligned.m8n8.x2.trans.shared.b16 {%0,%1}, [%2];"
                 : "=r"(r[0]), "=r"(r[1]) : "r"(a));
}
__device__ __forceinline__ void mma16816(float c[4], const uint32_t a[4], const uint32_t b[2])
{
    asm volatile(
        "mma.sync.aligned.m16n8k16.row.col.f32.f16.f16.f32 "
        "{%0,%1,%2,%3}, {%4,%5,%6,%7}, {%8,%9}, {%0,%1,%2,%3};"
        : "+f"(c[0]), "+f"(c[1]), "+f"(c[2]), "+f"(c[3])
        : "r"(a[0]), "r"(a[1]), "r"(a[2]), "r"(a[3]), "r"(b[0]), "r"(b[1]));
}

// ordered-uint encoding of float for atomicMax (monotone)
__device__ __forceinline__ unsigned fenc(float f)
{
    unsigned u = __float_as_uint(f);
    return (u & 0x80000000u) ? ~u : (u | 0x80000000u);
}
__device__ __forceinline__ float fdec(unsigned e)
{
    return (e & 0x80000000u) ? __uint_as_float(e & 0x7FFFFFFFu)
                             : __uint_as_float(~e);
}

// ---------------- 128x128x32 fp16 tensor GEMM, 2-stage cp.async + LDSM -------
// C[bz][m,n] = epi( sum_k A(m,k) * B(k,n) ), fp32 accumulate.
// TA: A[m,k]=A[k*lda+m]; TB: B[k,n]=B[n*ldb+k].
// iA (only !TA): source row of A-row m is iA[bz*256+m] (caller passes sA=0).
// iB: source row of B's leading dim (k if !TB, n if TB) is iB[bz*256+row].
// epilogue: v = acc (+ Cin[iC[bz*256+m], n]) (+ bias[n]); relu; * rs[bz*sRS+m];
//           optional per-batch atomicMax into bmaxu (exact tiles only).
template <bool TA, bool TB, bool OUTH>
__global__ __launch_bounds__(256)
void gemm_h(const __half* __restrict__ A, long sA, int lda, const int* __restrict__ iA,
            const __half* __restrict__ Bw, long sB, int ldb, const int* __restrict__ iB,
            const float* __restrict__ bias,
            const float* __restrict__ rs, int sRS,
            const __half* __restrict__ Cin, const int* __restrict__ iC,
            void* __restrict__ Cv, long sC, int ldc,
            int M, int N, int K, int relu, unsigned* bmaxu)
{
    constexpr int A_SZ = TA ? 32 * 136 : 128 * 40;   // halfs per stage
    constexpr int B_SZ = TB ? 128 * 40 : 32 * 136;
    __shared__ __half As[2][A_SZ];
    __shared__ __half Bs[2][B_SZ];

    int bz = blockIdx.z;
    const __half* Ab = A + (long)bz * sA;
    const __half* Bb = Bw + (long)bz * sB;
    int m0 = blockIdx.y * 128, n0 = blockIdx.x * 128;
    int tid = threadIdx.x;
    int wid = tid >> 5, lane = tid & 31;
    int wm = wid >> 2, wn = wid & 3;
    int g = lane >> 2, tig = lane & 3;

    uint32_t abase = (uint32_t)__cvta_generic_to_shared(&As[0][0]);
    uint32_t bbase = (uint32_t)__cvta_generic_to_shared(&Bs[0][0]);

    float c[4][4][4];
#pragma unroll
    for (int i = 0; i < 4; i++)
#pragma unroll
        for (int j = 0; j < 4; j++)
#pragma unroll
            for (int q = 0; q < 4; q++) c[i][j][q] = 0.f;

    int KT = (K + 31) / 32;

    auto load_stage = [&](int st, int k0) {
#pragma unroll
        for (int it = 0; it < 2; it++) {
            int id = tid + it * 256;
            if (!TA) {
                int row = id >> 2, c8 = (id & 3) * 8;
                bool p = (m0 + row < M) && (k0 + c8 < K);
                long rg = iA ? (p ? (long)iA[bz * 256 + m0 + row] : 0)
                             : (long)(m0 + row);
                cp16(abase + (uint32_t)(st * A_SZ + row * 40 + c8) * 2,
                     Ab + rg * lda + k0 + c8, p);
            } else {
                int kr = id >> 4, c8 = (id & 15) * 8;
                bool p = (k0 + kr < K) && (m0 + c8 < M);
                cp16(abase + (uint32_t)(st * A_SZ + kr * 136 + c8) * 2,
                     Ab + (long)(k0 + kr) * lda + m0 + c8, p);
            }
            if (!TB) {
                int kr = id >> 4, c8 = (id & 15) * 8;
                bool p = (k0 + kr < K) && (n0 + c8 < N);
                long rg = iB ? ((k0 + kr < K) ? (long)iB[bz * 256 + k0 + kr] : 0)
                             : (long)(k0 + kr);
                cp16(bbase + (uint32_t)(st * B_SZ + kr * 136 + c8) * 2,
                     Bb + rg * ldb + n0 + c8, p);
            } else {
                int row = id >> 2, c8 = (id & 3) * 8;
                bool p = (n0 + row < N) && (k0 + c8 < K);
                long rg = iB ? ((n0 + row < N) ? (long)iB[bz * 256 + n0 + row] : 0)
                             : (long)(n0 + row);
                cp16(bbase + (uint32_t)(st * B_SZ + row * 40 + c8) * 2,
                     Bb + rg * ldb + k0 + c8, p);
            }
        }
        cp_commit();
    };

    load_stage(0, 0);

    for (int kt = 0; kt < KT; kt++) {
        if (kt + 1 < KT) { load_stage((kt + 1) & 1, (kt + 1) * 32); cp_wait<1>(); }
        else             { cp_wait<0>(); }
        __syncthreads();
        int st = kt & 1;
        uint32_t ab2 = abase + (uint32_t)(st * A_SZ) * 2;
        uint32_t bb2 = bbase + (uint32_t)(st * B_SZ) * 2;

#pragma unroll
        for (int s2 = 0; s2 < 2; s2++) {
            int ks = s2 * 16;
            uint32_t af[4][4], bf[4][2];
#pragma unroll
            for (int mt = 0; mt < 4; mt++) {
                if (!TA) {
                    int m = wm * 64 + mt * 16 + (lane & 15);
                    int kc = ks + ((lane >> 4) << 3);
                    ldsm4(af[mt], ab2 + (uint32_t)(m * 40 + kc) * 2);
                } else {
                    int kr = ks + (lane & 7) + ((lane >> 4) << 3);
                    int mc = wm * 64 + mt * 16 + (((lane >> 3) & 1) << 3);
                    ldsm4t(af[mt], ab2 + (uint32_t)(kr * 136 + mc) * 2);
                }
            }
#pragma unroll
            for (int nt = 0; nt < 4; nt++) {
                if (TB) {
                    int n = wn * 32 + nt * 8 + (lane & 7);
                    int kc = ks + (((lane >> 3) & 1) << 3);
                    ldsm2(bf[nt], bb2 + (uint32_t)(n * 40 + kc) * 2);
                } else {
                    int kr = ks + (lane & 7) + (((lane >> 3) & 1) << 3);
                    int nc = wn * 32 + nt * 8;
                    ldsm2t(bf[nt], bb2 + (uint32_t)(kr * 136 + nc) * 2);
                }
            }
#pragma unroll
            for (int mt = 0; mt < 4; mt++)
#pragma unroll
                for (int nt = 0; nt < 4; nt++)
                    mma16816(c[mt][nt], af[mt], bf[nt]);
        }
        __syncthreads();
    }

    __half* Ch = (__half*)Cv + (long)bz * sC;
    float*  Cf = (float*)Cv + (long)bz * sC;
#pragma unroll
    for (int mt = 0; mt < 4; mt++) {
#pragma unroll
        for (int r = 0; r < 2; r++) {
            int m = m0 + wm * 64 + mt * 16 + g + r * 8;
            if (m >= M) continue;
            float rsv = rs ? rs[(long)bz * sRS + m] : 1.f;
            long crow = 0;
            if (Cin) crow = iC ? (long)iC[bz * 256 + m] : (long)m;
#pragma unroll
            for (int nt = 0; nt < 4; nt++) {
                int n = n0 + wn * 32 + nt * 8 + tig * 2;
                if (n < N) {
                    float v0 = c[mt][nt][r * 2 + 0];
                    float v1 = c[mt][nt][r * 2 + 1];
                    if (Cin) {
                        v0 += __half2float(Cin[crow * ldc + n]);
                        v1 += __half2float(Cin[crow * ldc + n + 1]);
                    }
                    if (bias) { v0 += bias[n]; v1 += bias[n + 1]; }
                    if (relu) { v0 = fmaxf(v0, 0.f); v1 = fmaxf(v1, 0.f); }
                    v0 *= rsv; v1 *= rsv;
                    if (OUTH)
                        *(__half2*)(Ch + (long)m * ldc + n) = __floats2half2_rn(v0, v1);
                    else {
                        Cf[(long)m * ldc + n] = v0;
                        Cf[(long)m * ldc + n + 1] = v1;
                    }
                }
            }
        }
    }

    if (bmaxu) {   // per-batch max of this block's outputs (exact tiles only)
        float mx = -1e30f;
#pragma unroll
        for (int mt = 0; mt < 4; mt++)
#pragma unroll
            for (int nt = 0; nt < 4; nt++)
#pragma unroll
                for (int q = 0; q < 4; q++) mx = fmaxf(mx, c[mt][nt][q]);
#pragma unroll
        for (int o = 16; o; o >>= 1) mx = fmaxf(mx, __shfl_xor_sync(~0u, mx, o));
        if (lane == 0) atomicMax(&bmaxu[bz], fenc(mx));
    }
}

// ---------------- helper kernels ---------------------------------------------
__global__ void conv2h_k(const float* __restrict__ src, __half* __restrict__ dst,
                         int rows, int cols, int srcR, int srcC)
{
    long idx = (long)blockIdx.x * blockDim.x + threadIdx.x;
    if (idx >= (long)rows * cols) return;
    int r = (int)(idx / cols), c = (int)(idx % cols);
    float v = (r < srcR && c < srcC) ? src[(long)r * srcC + c] : 0.f;
    dst[idx] = __float2half_rn(v);
}

// masks + token index concat + bmax init
__global__ void mask_k(const int* __restrict__ s1, const int* __restrict__ s2,
                       const int* __restrict__ len1, const int* __restrict__ len2)
{
    long idx = (long)blockIdx.x * blockDim.x + threadIdx.x;
    if (idx >= 2 * BL) return;
    int seq = (int)(idx / BL);
    long r = idx % BL;
    int b = (int)(r / Lsz), l = (int)(r % Lsz);
    int len = seq ? len2[b] : len1[b];
    g_mask[idx] = (l < len) ? 1.f : 0.f;
    g_tok[idx] = seq ? s2[r] : s1[r];
    if (idx < Bsz) g_bmaxu[idx] = 0u;
}

// Fused softmax (shift-cancelled): p = exp(e - Mb);
// colsum(p*m1i) -> rsa; rowsum(p*m2j) -> rsb; emit fp16 ean/ebn normalized.
__global__ void sums_k()
{
    __shared__ float rowacc[256];
    __shared__ float colsm[1024];
    __shared__ float rsa_s[256];
    __shared__ float rsb_s[256];
    int b = blockIdx.x;
    int tid = threadIdx.x;
    int j = tid & 255, s = tid >> 8, lane = tid & 31;
    if (tid < 256) rowacc[tid] = 0.f;
    __syncthreads();

    long base = (long)b * LL;
    float Mb  = fdec(g_bmaxu[b]);
    float m2j = g_mask[BL + (long)b * Lsz + j];
    float da = 0.f;
    for (int t = 0; t < 64; t++) {
        int i = s * 64 + t;
        float p = __expf(g_scores[base + (long)i * Lsz + j] - Mb);
        da += p * g_mask[(long)b * Lsz + i];
        float v = p * m2j;
#pragma unroll
        for (int o = 16; o; o >>= 1) v += __shfl_xor_sync(~0u, v, o);
        if (lane == 0) atomicAdd(&rowacc[i], v);
    }
    colsm[tid] = da;
    __syncthreads();
    if (s == 0)
        rsa_s[j] = m2j / (colsm[j] + colsm[j + 256] + colsm[j + 512] + colsm[j + 768]);
    if (tid < 256)
        rsb_s[tid] = g_mask[(long)b * Lsz + tid] / rowacc[tid];
    __syncthreads();

    float rsaj = rsa_s[j];
    for (int t = 0; t < 64; t++) {
        int i = s * 64 + t;
        long idx = base + (long)i * Lsz + j;
        float p = __expf(g_scores[idx] - Mb);
        g_eanh[idx] = __float2half_rn(p * g_mask[(long)b * Lsz + i] * rsaj);
        g_ebnh[idx] = __float2half_rn(p * m2j * rsb_s[i]);
    }
}

__global__ void colsum_k()
{
    __shared__ float sm[1024];
    int b2 = blockIdx.x;
    int h = threadIdx.x & 255, s = threadIdx.x >> 8;
    float acc = 0.f;
    if (h < Hsz) {
        const __half* p = g_hoh + (long)b2 * Lsz * Hsz;
#pragma unroll 4
        for (int l = s * 64; l < s * 64 + 64; l++) acc += __half2float(p[(long)l * Hsz + h]);
    }
    sm[threadIdx.x] = acc;
    __syncthreads();
    if (s == 0 && h < Hsz) {
        int b = (b2 < Bsz) ? b2 : b2 - Bsz;
        int off = (b2 < Bsz) ? 0 : Hsz;
        g_vch[(long)b * 2 * Hsz + off + h] =
            __float2half_rn(sm[h] + sm[h + 256] + sm[h + 512] + sm[h + 768]);
    }
}

__global__ void final_k(const float* __restrict__ W2g,
                        const float* __restrict__ b2g, float* __restrict__ out)
{
    int b = blockIdx.x;
    int o = threadIdx.x >> 5;
    int lane = threadIdx.x & 31;
    const float* u = g_u + (long)b * Hsz;
    float s = 0.f;
    for (int h = lane; h < Hsz; h += 32) s += u[h] * W2g[h * 2 + o];
#pragma unroll
    for (int off = 16; off; off >>= 1) s += __shfl_xor_sync(~0u, s, off);
    if (lane == 0) out[b * 2 + o] = s + b2g[o];
}

// ---------------- launch -----------------------------------------------------
extern "C" void kernel_launch(void* const* d_in, const int* in_sizes, int n_in,
                              void* d_out, int out_size)
{
    const float* emb = (const float*)d_in[0];
    const float* W1a = (const float*)d_in[1];
    const float* b1a = (const float*)d_in[2];
    const float* W2a = (const float*)d_in[3];
    const float* b2a = (const float*)d_in[4];
    const float* W1c = (const float*)d_in[5];
    const float* b1c = (const float*)d_in[6];
    const float* W2c = (const float*)d_in[7];
    const float* b2c = (const float*)d_in[8];
    const float* W1g = (const float*)d_in[9];
    const float* b1g = (const float*)d_in[10];
    const float* W2g = (const float*)d_in[11];
    const float* b2g = (const float*)d_in[12];
    const int* s1   = (const int*)d_in[13];
    const int* s2   = (const int*)d_in[14];
    const int* len1 = (const int*)d_in[15];
    const int* len2 = (const int*)d_in[16];
    float* out = (float*)d_out;

    __half *pembh, *pW1a, *pW2a, *pW1cT, *pW1cB, *pW2c, *pW1g;
    __half *ptvh, *phvh, *pcvh, *pcv2h, *peanh, *pebnh, *pthh, *phoh, *pvch;
    float *pmask, *pu, *psc;
    int *ptok;
    unsigned *pbmx;
    cudaGetSymbolAddress((void**)&pembh, g_embh);
    cudaGetSymbolAddress((void**)&pW1a,  g_W1a);
    cudaGetSymbolAddress((void**)&pW2a,  g_W2a);
    cudaGetSymbolAddress((void**)&pW1cT, g_W1cT);
    cudaGetSymbolAddress((void**)&pW1cB, g_W1cB);
    cudaGetSymbolAddress((void**)&pW2c,  g_W2c);
    cudaGetSymbolAddress((void**)&pW1g,  g_W1g);
    cudaGetSymbolAddress((void**)&ptvh,  g_tvh);
    cudaGetSymbolAddress((void**)&phvh,  g_hvh);
    cudaGetSymbolAddress((void**)&pcvh,  g_cvh);
    cudaGetSymbolAddress((void**)&pcv2h, g_cv2h);
    cudaGetSymbolAddress((void**)&peanh, g_eanh);
    cudaGetSymbolAddress((void**)&pebnh, g_ebnh);
    cudaGetSymbolAddress((void**)&pthh,  g_thh);
    cudaGetSymbolAddress((void**)&phoh,  g_hoh);
    cudaGetSymbolAddress((void**)&pvch,  g_vch);
    cudaGetSymbolAddress((void**)&pmask, g_mask);
    cudaGetSymbolAddress((void**)&pu,    g_u);
    cudaGetSymbolAddress((void**)&psc,   g_scores);
    cudaGetSymbolAddress((void**)&ptok,  g_tok);
    cudaGetSymbolAddress((void**)&pbmx,  g_bmaxu);

    const int M2 = (int)(2 * BL);          // 262144
    const unsigned MV = (VOC + 127) / 128; // 391
    auto cdiv = [](long n, long d) { return (unsigned)((n + d - 1) / d); };

    // 0. fp32 -> fp16 conversions (emb + weights, zero-padded)
    conv2h_k<<<cdiv((long)VOC * EP, 256), 256>>>(emb, pembh, VOC, EP, VOC, Esz);
    conv2h_k<<<cdiv(EP * Hsz, 256), 256>>>(W1a, pW1a, EP, Hsz, Esz, Hsz);
    conv2h_k<<<cdiv(Hsz * Hsz, 256), 256>>>(W2a, pW2a, Hsz, Hsz, Hsz, Hsz);
    conv2h_k<<<cdiv(EP * Hsz, 256), 256>>>(W1c, pW1cT, EP, Hsz, Esz, Hsz);
    conv2h_k<<<cdiv(EP * Hsz, 256), 256>>>(W1c + (long)Esz * Hsz, pW1cB, EP, Hsz, Esz, Hsz);
    conv2h_k<<<cdiv(Hsz * Hsz, 256), 256>>>(W2c, pW2c, Hsz, Hsz, Hsz, Hsz);
    conv2h_k<<<cdiv(2 * Hsz * Hsz, 256), 256>>>(W1g, pW1g, 2 * Hsz, Hsz, 2 * Hsz, Hsz);

    // masks + tok + bmax init
    mask_k<<<cdiv(2 * BL, 256), 256>>>(s1, s2, len1, len2);

    // 1. per-vocab precompute: attend_ff, e@W1c_top, e@W1c_bottom
    gemm_h<false,false,true><<<dim3(2, MV, 1), 256>>>(
        pembh, 0, EP, nullptr, pW1a, 0, Hsz, nullptr, b1a, nullptr, 0,
        nullptr, nullptr, ptvh, 0, Hsz, VOC, Hsz, EP, 1, nullptr);
    gemm_h<false,false,true><<<dim3(2, MV, 1), 256>>>(
        ptvh, 0, Hsz, nullptr, pW2a, 0, Hsz, nullptr, b2a, nullptr, 0,
        nullptr, nullptr, phvh, 0, Hsz, VOC, Hsz, Hsz, 1, nullptr);
    gemm_h<false,false,true><<<dim3(2, MV, 1), 256>>>(
        pembh, 0, EP, nullptr, pW1cT, 0, Hsz, nullptr, nullptr, nullptr, 0,
        nullptr, nullptr, pcvh, 0, Hsz, VOC, Hsz, EP, 0, nullptr);
    gemm_h<false,false,true><<<dim3(2, MV, 1), 256>>>(
        pembh, 0, EP, nullptr, pW1cB, 0, Hsz, nullptr, nullptr, nullptr, 0,
        nullptr, nullptr, pcv2h, 0, Hsz, VOC, Hsz, EP, 0, nullptr);

    // 2. scores[b] = h1[b] @ h2[b]^T  (indexed rows of hv; epilogue batch-max)
    gemm_h<false,true,false><<<dim3(2, 2, Bsz), 256>>>(
        phvh, 0, Hsz, s1, phvh, 0, Hsz, s2, nullptr, nullptr, 0,
        nullptr, nullptr, psc, LL, Lsz, Lsz, Lsz, Hsz, 0, pbmx);

    // 3. fused softmax -> fp16 ean / ebn
    sums_k<<<Bsz, 1024>>>();

    // 4. compare hidden directly via pushed-through W1c_bottom:
    //    th1[i,h] = relu( cv[s1[i]] + sum_j ebn[i,j]*cv2[s2[j]] + b1c )
    gemm_h<false,false,true><<<dim3(2, 2, Bsz), 256>>>(
        pebnh, LL, Lsz, nullptr, pcv2h, 0, Hsz, s2, b1c, nullptr, 0,
        pcvh, ptok, pthh, (long)Lsz * Hsz, Hsz, Lsz, Hsz, Lsz, 1, nullptr);
    //    th2[j,h] = relu( cv[s2[j]] + sum_i ean[i,j]*cv2[s1[i]] + b1c )  (TN)
    gemm_h<true,false,true><<<dim3(2, 2, Bsz), 256>>>(
        peanh, LL, Lsz, nullptr, pcv2h, 0, Hsz, s1, b1c, nullptr, 0,
        pcvh, ptok + BL, pthh + BL * Hsz, (long)Lsz * Hsz, Hsz, Lsz, Hsz, Lsz, 1, nullptr);

    // 5. compare L2: ho = relu(th@W2c + b2c) * mask
    gemm_h<false,false,true><<<dim3(2, M2 / 128, 1), 256>>>(
        pthh, 0, Hsz, nullptr, pW2c, 0, Hsz, nullptr, b2c, pmask, 0,
        nullptr, nullptr, phoh, 0, Hsz, M2, Hsz, Hsz, 1, nullptr);

    // 6. masked sums -> vcat ; aggregate head
    colsum_k<<<2 * Bsz, 1024>>>();
    gemm_h<false,false,false><<<dim3(2, 4, 1), 256>>>(
        pvch, 0, 2 * Hsz, nullptr, pW1g, 0, Hsz, nullptr, b1g, nullptr, 0,
        nullptr, nullptr, pu, 0, Hsz, Bsz, Hsz, 2 * Hsz, 1, nullptr);
    final_k<<<Bsz, 64>>>(W2g, b2g, out);
}

// round 9
// speedup vs baseline: 9.7456x; 1.1072x over previous
#include <cuda_runtime.h>
#include <cuda_fp16.h>
#include <cstdint>

// Problem constants
#define Bsz 512
#define Lsz 256
#define Esz 300
#define EP  304              // padded E (16B-aligned fp16 rows)
#define Hsz 200
#define NCAT 640             // packed vocab-GEMM width: [W1a | W1cT | W1cB | pad]
#define VOC 50000
constexpr long BL  = (long)Bsz * Lsz;      // 131072
constexpr long LL  = (long)Lsz * Lsz;      // 65536
constexpr long BLL = BL * Lsz;             // 33,554,432

// ---------------- device scratch (static, no runtime allocation) -------------
__device__ __half g_embh[(long)VOC * EP];
__device__ __half g_Wcat[EP * NCAT];        // cols 0..199 W1a, 200..399 W1c top, 400..599 W1c bottom
__device__ __half g_W2a[Hsz * Hsz];
__device__ __half g_W2c[Hsz * Hsz];
__device__ __half g_W1g[2 * Hsz * Hsz];
__device__ float  g_b1acat[NCAT];           // b1a zero-extended to 640
__device__ __half g_vcb[(long)VOC * NCAT];  // vocab: [attendL1relu | e@W1cT | e@W1cB]
__device__ __half g_hvh[(long)VOC * Hsz];   // vocab attend_ff out
__device__ __half g_eanh[BLL];              // normalized alpha weights
__device__ __half g_ebnh[BLL];              // normalized beta weights
__device__ __half g_thh[2 * BL * Hsz];      // compare hidden
__device__ __half g_vch[Bsz * 2 * Hsz];     // vcat fp16
__device__ float  g_vcatf[Bsz * 2 * Hsz];   // vcat fp32 accumulator
__device__ float    g_scores[BLL];
__device__ float    g_mask[2 * BL];
__device__ int      g_tok[2 * BL];
__device__ unsigned g_bmaxu[Bsz];           // encoded per-batch max
__device__ float    g_u[Bsz * Hsz];

// ---------------- PTX helpers ------------------------------------------------
__device__ __forceinline__ void cp16(uint32_t dst, const void* src, bool pred)
{
    int sz = pred ? 16 : 0;                 // sz=0 -> 16B zero-fill
    asm volatile("cp.async.cg.shared.global [%0], [%1], 16, %2;"
                 :: "r"(dst), "l"(src), "r"(sz));
}
__device__ __forceinline__ void cp_commit() { asm volatile("cp.async.commit_group;"); }
template <int N>
__device__ __forceinline__ void cp_wait() { asm volatile("cp.async.wait_group %0;" :: "n"(N)); }

__device__ __forceinline__ void ldsm4(uint32_t* r, uint32_t a)
{
    asm volatile("ldmatrix.sync.aligned.m8n8.x4.shared.b16 {%0,%1,%2,%3}, [%4];"
                 : "=r"(r[0]), "=r"(r[1]), "=r"(r[2]), "=r"(r[3]) : "r"(a));
}
__device__ __forceinline__ void ldsm4t(uint32_t* r, uint32_t a)
{
    asm volatile("ldmatrix.sync.aligned.m8n8.x4.trans.shared.b16 {%0,%1,%2,%3}, [%4];"
                 : "=r"(r[0]), "=r"(r[1]), "=r"(r[2]), "=r"(r[3]) : "r"(a));
}
__device__ __forceinline__ void ldsm2(uint32_t* r, uint32_t a)
{
    asm volatile("ldmatrix.sync.aligned.m8n8.x2.shared.b16 {%0,%1}, [%2];"
                 : "=r"(r[0]), "=r"(r[1]) : "r"(a));
}
__device__ __forceinline__ void ldsm2t(uint32_t* r, uint32_t a)
{
    asm volatile("ldmatrix.sync.aligned.m8n8.x2.trans.shared.b16 {%0,%1}, [%2];"
                 : "=r"(r[0]), "=r"(r[1]) : "r"(a));
}
__device__ __forceinline__ void mma16816(float c[4], const uint32_t a[4], const uint32_t b[2])
{
    asm volatile(
        "mma.sync.aligned.m16n8k16.row.col.f32.f16.f16.f32 "
        "{%0,%1,%2,%3}, {%4,%5,%6,%7}, {%8,%9}, {%0,%1,%2,%3};"
        : "+f"(c[0]), "+f"(c[1]), "+f"(c[2]), "+f"(c[3])
        : "r"(a[0]), "r"(a[1]), "r"(a[2]), "r"(a[3]), "r"(b[0]), "r"(b[1]));
}

// ordered-uint encoding of float for atomicMax (monotone)
__device__ __forceinline__ unsigned fenc(float f)
{
    unsigned u = __float_as_uint(f);
    return (u & 0x80000000u) ? ~u : (u | 0x80000000u);
}
__device__ __forceinline__ float fdec(unsigned e)
{
    return (e & 0x80000000u) ? __uint_as_float(e & 0x7FFFFFFFu)
                             : __uint_as_float(~e);
}

// ---------------- 128x128x32 fp16 tensor GEMM, 2-stage cp.async + LDSM -------
// C[bz][m,n] = epi( sum_k A(m,k) * B(k,n) ), fp32 accumulate.
// TA: A[m,k]=A[k*lda+m]; TB: B[k,n]=B[n*ldb+k].
// iA (only !TA): source row of A-row m is iA[bz*256+m] (caller passes sA=0).
// iB: source row of B's leading dim (k if !TB, n if TB) is iB[bz*256+row].
// epilogue: v = acc (+ Cin[iC[bz*256+m], n] stride ldcin) (+ bias[n]);
//           relu iff n < nrelu; * rs[bz*sRS+m];
//           vacc: fused column-sum (2*BL row layout, 256 rows/segment) -> atomicAdd,
//                 no C store;  bmaxu: per-batch atomicMax of raw acc (exact tiles).
template <bool TA, bool TB, bool OUTH>
__global__ __launch_bounds__(256)
void gemm_h(const __half* __restrict__ A, long sA, int lda, const int* __restrict__ iA,
            const __half* __restrict__ Bw, long sB, int ldb, const int* __restrict__ iB,
            const float* __restrict__ bias,
            const float* __restrict__ rs, int sRS,
            const __half* __restrict__ Cin, const int* __restrict__ iC, int ldcin,
            void* __restrict__ Cv, long sC, int ldc,
            int M, int N, int K, int nrelu,
            unsigned* bmaxu, float* vacc)
{
    constexpr int A_SZ = TA ? 32 * 136 : 128 * 40;   // halfs per stage
    constexpr int B_SZ = TB ? 128 * 40 : 32 * 136;
    __shared__ __half As[2][A_SZ];
    __shared__ __half Bs[2][B_SZ];

    int bz = blockIdx.z;
    const __half* Ab = A + (long)bz * sA;
    const __half* Bb = Bw + (long)bz * sB;
    int m0 = blockIdx.y * 128, n0 = blockIdx.x * 128;
    int tid = threadIdx.x;
    int wid = tid >> 5, lane = tid & 31;
    int wm = wid >> 2, wn = wid & 3;
    int g = lane >> 2, tig = lane & 3;

    uint32_t abase = (uint32_t)__cvta_generic_to_shared(&As[0][0]);
    uint32_t bbase = (uint32_t)__cvta_generic_to_shared(&Bs[0][0]);

    float c[4][4][4];
#pragma unroll
    for (int i = 0; i < 4; i++)
#pragma unroll
        for (int j = 0; j < 4; j++)
#pragma unroll
            for (int q = 0; q < 4; q++) c[i][j][q] = 0.f;

    int KT = (K + 31) / 32;

    auto load_stage = [&](int st, int k0) {
#pragma unroll
        for (int it = 0; it < 2; it++) {
            int id = tid + it * 256;
            if (!TA) {
                int row = id >> 2, c8 = (id & 3) * 8;
                bool p = (m0 + row < M) && (k0 + c8 < K);
                long rg = iA ? (p ? (long)iA[bz * 256 + m0 + row] : 0)
                             : (long)(m0 + row);
                cp16(abase + (uint32_t)(st * A_SZ + row * 40 + c8) * 2,
                     Ab + rg * lda + k0 + c8, p);
            } else {
                int kr = id >> 4, c8 = (id & 15) * 8;
                bool p = (k0 + kr < K) && (m0 + c8 < M);
                cp16(abase + (uint32_t)(st * A_SZ + kr * 136 + c8) * 2,
                     Ab + (long)(k0 + kr) * lda + m0 + c8, p);
            }
            if (!TB) {
                int kr = id >> 4, c8 = (id & 15) * 8;
                bool p = (k0 + kr < K) && (n0 + c8 < N);
                long rg = iB ? ((k0 + kr < K) ? (long)iB[bz * 256 + k0 + kr] : 0)
                             : (long)(k0 + kr);
                cp16(bbase + (uint32_t)(st * B_SZ + kr * 136 + c8) * 2,
                     Bb + rg * ldb + n0 + c8, p);
            } else {
                int row = id >> 2, c8 = (id & 3) * 8;
                bool p = (n0 + row < N) && (k0 + c8 < K);
                long rg = iB ? ((n0 + row < N) ? (long)iB[bz * 256 + n0 + row] : 0)
                             : (long)(n0 + row);
                cp16(bbase + (uint32_t)(st * B_SZ + row * 40 + c8) * 2,
                     Bb + rg * ldb + k0 + c8, p);
            }
        }
        cp_commit();
    };

    load_stage(0, 0);

    for (int kt = 0; kt < KT; kt++) {
        if (kt + 1 < KT) { load_stage((kt + 1) & 1, (kt + 1) * 32); cp_wait<1>(); }
        else             { cp_wait<0>(); }
        __syncthreads();
        int st = kt & 1;
        uint32_t ab2 = abase + (uint32_t)(st * A_SZ) * 2;
        uint32_t bb2 = bbase + (uint32_t)(st * B_SZ) * 2;

#pragma unroll
        for (int s2 = 0; s2 < 2; s2++) {
            int ks = s2 * 16;
            uint32_t af[4][4], bf[4][2];
#pragma unroll
            for (int mt = 0; mt < 4; mt++) {
                if (!TA) {
                    int m = wm * 64 + mt * 16 + (lane & 15);
                    int kc = ks + ((lane >> 4) << 3);
                    ldsm4(af[mt], ab2 + (uint32_t)(m * 40 + kc) * 2);
                } else {
                    int kr = ks + (lane & 7) + ((lane >> 4) << 3);
                    int mc = wm * 64 + mt * 16 + (((lane >> 3) & 1) << 3);
                    ldsm4t(af[mt], ab2 + (uint32_t)(kr * 136 + mc) * 2);
                }
            }
#pragma unroll
            for (int nt = 0; nt < 4; nt++) {
                if (TB) {
                    int n = wn * 32 + nt * 8 + (lane & 7);
                    int kc = ks + (((lane >> 3) & 1) << 3);
                    ldsm2(bf[nt], bb2 + (uint32_t)(n * 40 + kc) * 2);
                } else {
                    int kr = ks + (lane & 7) + (((lane >> 3) & 1) << 3);
                    int nc = wn * 32 + nt * 8;
                    ldsm2t(bf[nt], bb2 + (uint32_t)(kr * 136 + nc) * 2);
                }
            }
#pragma unroll
            for (int mt = 0; mt < 4; mt++)
#pragma unroll
                for (int nt = 0; nt < 4; nt++)
                    mma16816(c[mt][nt], af[mt], bf[nt]);
        }
        __syncthreads();
    }

    // ---- fused column-sum epilogue (compare L2): no C store
    if (vacc) {
        int b2v = m0 >> 8;   // 128-row blocks never straddle a 256-row segment
        long voff = (b2v < Bsz) ? (long)b2v * (2 * Hsz)
                                : (long)(b2v - Bsz) * (2 * Hsz) + Hsz;
#pragma unroll
        for (int nt = 0; nt < 4; nt++) {
            int n = n0 + wn * 32 + nt * 8 + tig * 2;
            float s0 = 0.f, s1 = 0.f;
            if (n < N) {
#pragma unroll
                for (int mt = 0; mt < 4; mt++)
#pragma unroll
                    for (int r = 0; r < 2; r++) {
                        int m = m0 + wm * 64 + mt * 16 + g + r * 8;
                        float rsv = rs ? rs[(long)bz * sRS + m] : 1.f;
                        float v0 = c[mt][nt][r * 2 + 0];
                        float v1 = c[mt][nt][r * 2 + 1];
                        if (bias) { v0 += bias[n]; v1 += bias[n + 1]; }
                        if (n < nrelu) { v0 = fmaxf(v0, 0.f); v1 = fmaxf(v1, 0.f); }
                        s0 += v0 * rsv; s1 += v1 * rsv;
                    }
            }
            s0 += __shfl_down_sync(~0u, s0, 16);
            s0 += __shfl_down_sync(~0u, s0, 8);
            s0 += __shfl_down_sync(~0u, s0, 4);
            s1 += __shfl_down_sync(~0u, s1, 16);
            s1 += __shfl_down_sync(~0u, s1, 8);
            s1 += __shfl_down_sync(~0u, s1, 4);
            if (g == 0 && n < N) {
                atomicAdd(&vacc[voff + n], s0);
                atomicAdd(&vacc[voff + n + 1], s1);
            }
        }
        return;
    }

    __half* Ch = (__half*)Cv + (long)bz * sC;
    float*  Cf = (float*)Cv + (long)bz * sC;
#pragma unroll
    for (int mt = 0; mt < 4; mt++) {
#pragma unroll
        for (int r = 0; r < 2; r++) {
            int m = m0 + wm * 64 + mt * 16 + g + r * 8;
            if (m >= M) continue;
            float rsv = rs ? rs[(long)bz * sRS + m] : 1.f;
            long crow = 0;
            if (Cin) crow = iC ? (long)iC[bz * 256 + m] : (long)m;
#pragma unroll
            for (int nt = 0; nt < 4; nt++) {
                int n = n0 + wn * 32 + nt * 8 + tig * 2;
                if (n < N) {
                    float v0 = c[mt][nt][r * 2 + 0];
                    float v1 = c[mt][nt][r * 2 + 1];
                    if (Cin) {
                        v0 += __half2float(Cin[crow * ldcin + n]);
                        v1 += __half2float(Cin[crow * ldcin + n + 1]);
                    }
                    if (bias) { v0 += bias[n]; v1 += bias[n + 1]; }
                    if (n < nrelu) { v0 = fmaxf(v0, 0.f); v1 = fmaxf(v1, 0.f); }
                    v0 *= rsv; v1 *= rsv;
                    if (OUTH)
                        *(__half2*)(Ch + (long)m * ldc + n) = __floats2half2_rn(v0, v1);
                    else {
                        Cf[(long)m * ldc + n] = v0;
                        Cf[(long)m * ldc + n + 1] = v1;
                    }
                }
            }
        }
    }

    if (bmaxu) {   // per-batch max of this block's outputs (exact tiles only)
        float mx = -1e30f;
#pragma unroll
        for (int mt = 0; mt < 4; mt++)
#pragma unroll
            for (int nt = 0; nt < 4; nt++)
#pragma unroll
                for (int q = 0; q < 4; q++) mx = fmaxf(mx, c[mt][nt][q]);
#pragma unroll
        for (int o = 16; o; o >>= 1) mx = fmaxf(mx, __shfl_xor_sync(~0u, mx, o));
        if (lane == 0) atomicMax(&bmaxu[bz], fenc(mx));
    }
}

// ---------------- helper kernels ---------------------------------------------
__global__ void conv2h_k(const float* __restrict__ src, __half* __restrict__ dst,
                         int rows, int cols, int srcR, int srcC)
{
    long idx = (long)blockIdx.x * blockDim.x + threadIdx.x;
    if (idx >= (long)rows * cols) return;
    int r = (int)(idx / cols), c = (int)(idx % cols);
    float v = (r < srcR && c < srcC) ? src[(long)r * srcC + c] : 0.f;
    dst[idx] = __float2half_rn(v);
}

// all weight conversions in ONE kernel (Wcat packing + W2a/W2c/W1g + biascat)
__global__ void convw_k(const float* __restrict__ W1a, const float* __restrict__ W1c,
                        const float* __restrict__ W2a, const float* __restrict__ W2c,
                        const float* __restrict__ W1g, const float* __restrict__ b1a)
{
    long idx = (long)blockIdx.x * blockDim.x + threadIdx.x;
    const long NW = (long)EP * NCAT;
    if (idx < NW) {
        int r = (int)(idx / NCAT), cc = (int)(idx % NCAT);
        float v = 0.f;
        if (r < Esz) {
            if (cc < 200)      v = W1a[(long)r * Hsz + cc];
            else if (cc < 400) v = W1c[(long)r * Hsz + (cc - 200)];
            else if (cc < 600) v = W1c[(long)(Esz + r) * Hsz + (cc - 400)];
        }
        g_Wcat[idx] = __float2half_rn(v);
        return;
    }
    idx -= NW;
    if (idx < Hsz * Hsz) { g_W2a[idx] = __float2half_rn(W2a[idx]); return; }
    idx -= Hsz * Hsz;
    if (idx < Hsz * Hsz) { g_W2c[idx] = __float2half_rn(W2c[idx]); return; }
    idx -= Hsz * Hsz;
    if (idx < 2 * Hsz * Hsz) { g_W1g[idx] = __float2half_rn(W1g[idx]); return; }
    idx -= 2 * Hsz * Hsz;
    if (idx < NCAT) { g_b1acat[idx] = (idx < Hsz) ? b1a[idx] : 0.f; return; }
}

// masks + token index concat + bmax init + vcat accumulator zero
__global__ void mask_k(const int* __restrict__ s1, const int* __restrict__ s2,
                       const int* __restrict__ len1, const int* __restrict__ len2)
{
    long idx = (long)blockIdx.x * blockDim.x + threadIdx.x;
    if (idx >= 2 * BL) return;
    int seq = (int)(idx / BL);
    long r = idx % BL;
    int b = (int)(r / Lsz), l = (int)(r % Lsz);
    int len = seq ? len2[b] : len1[b];
    g_mask[idx] = (l < len) ? 1.f : 0.f;
    g_tok[idx] = seq ? s2[r] : s1[r];
    if (idx < Bsz) g_bmaxu[idx] = 0u;
    if (idx < Bsz * 2 * Hsz) g_vcatf[idx] = 0.f;
}

// Fused softmax (shift-cancelled): p = exp(e - Mb);
// colsum(p*m1i) -> rsa; rowsum(p*m2j) -> rsb; emit fp16 ean/ebn normalized.
__global__ void sums_k()
{
    __shared__ float rowacc[256];
    __shared__ float colsm[1024];
    __shared__ float rsa_s[256];
    __shared__ float rsb_s[256];
    int b = blockIdx.x;
    int tid = threadIdx.x;
    int j = tid & 255, s = tid >> 8, lane = tid & 31;
    if (tid < 256) rowacc[tid] = 0.f;
    __syncthreads();

    long base = (long)b * LL;
    float Mb  = fdec(g_bmaxu[b]);
    float m2j = g_mask[BL + (long)b * Lsz + j];
    float da = 0.f;
    for (int t = 0; t < 64; t++) {
        int i = s * 64 + t;
        float p = __expf(g_scores[base + (long)i * Lsz + j] - Mb);
        da += p * g_mask[(long)b * Lsz + i];
        float v = p * m2j;
#pragma unroll
        for (int o = 16; o; o >>= 1) v += __shfl_xor_sync(~0u, v, o);
        if (lane == 0) atomicAdd(&rowacc[i], v);
    }
    colsm[tid] = da;
    __syncthreads();
    if (s == 0)
        rsa_s[j] = m2j / (colsm[j] + colsm[j + 256] + colsm[j + 512] + colsm[j + 768]);
    if (tid < 256)
        rsb_s[tid] = g_mask[(long)b * Lsz + tid] / rowacc[tid];
    __syncthreads();

    float rsaj = rsa_s[j];
    for (int t = 0; t < 64; t++) {
        int i = s * 64 + t;
        long idx = base + (long)i * Lsz + j;
        float p = __expf(g_scores[idx] - Mb);
        g_eanh[idx] = __float2half_rn(p * g_mask[(long)b * Lsz + i] * rsaj);
        g_ebnh[idx] = __float2half_rn(p * m2j * rsb_s[i]);
    }
}

__global__ void vconv_k()    // fp32 vcat accumulator -> fp16
{
    int idx = blockIdx.x * blockDim.x + threadIdx.x;
    if (idx < Bsz * 2 * Hsz) g_vch[idx] = __float2half_rn(g_vcatf[idx]);
}

__global__ void final_k(const float* __restrict__ W2g,
                        const float* __restrict__ b2g, float* __restrict__ out)
{
    int b = blockIdx.x;
    int o = threadIdx.x >> 5;
    int lane = threadIdx.x & 31;
    const float* u = g_u + (long)b * Hsz;
    float s = 0.f;
    for (int h = lane; h < Hsz; h += 32) s += u[h] * W2g[h * 2 + o];
#pragma unroll
    for (int off = 16; off; off >>= 1) s += __shfl_xor_sync(~0u, s, off);
    if (lane == 0) out[b * 2 + o] = s + b2g[o];
}

// ---------------- launch -----------------------------------------------------
extern "C" void kernel_launch(void* const* d_in, const int* in_sizes, int n_in,
                              void* d_out, int out_size)
{
    const float* emb = (const float*)d_in[0];
    const float* W1a = (const float*)d_in[1];
    const float* b1a = (const float*)d_in[2];
    const float* W2a = (const float*)d_in[3];
    const float* b2a = (const float*)d_in[4];
    const float* W1c = (const float*)d_in[5];
    const float* b1c = (const float*)d_in[6];
    const float* W2c = (const float*)d_in[7];
    const float* b2c = (const float*)d_in[8];
    const float* W1g = (const float*)d_in[9];
    const float* b1g = (const float*)d_in[10];
    const float* W2g = (const float*)d_in[11];
    const float* b2g = (const float*)d_in[12];
    const int* s1   = (const int*)d_in[13];
    const int* s2   = (const int*)d_in[14];
    const int* len1 = (const int*)d_in[15];
    const int* len2 = (const int*)d_in[16];
    float* out = (float*)d_out;

    __half *pembh, *pWcat, *pW2a, *pW2c, *pW1g, *pvcb, *phvh;
    __half *peanh, *pebnh, *pthh, *pvch;
    float *pmask, *pu, *psc, *pb1acat, *pvcatf;
    int *ptok;
    unsigned *pbmx;
    cudaGetSymbolAddress((void**)&pembh,  g_embh);
    cudaGetSymbolAddress((void**)&pWcat,  g_Wcat);
    cudaGetSymbolAddress((void**)&pW2a,   g_W2a);
    cudaGetSymbolAddress((void**)&pW2c,   g_W2c);
    cudaGetSymbolAddress((void**)&pW1g,   g_W1g);
    cudaGetSymbolAddress((void**)&pvcb,   g_vcb);
    cudaGetSymbolAddress((void**)&phvh,   g_hvh);
    cudaGetSymbolAddress((void**)&peanh,  g_eanh);
    cudaGetSymbolAddress((void**)&pebnh,  g_ebnh);
    cudaGetSymbolAddress((void**)&pthh,   g_thh);
    cudaGetSymbolAddress((void**)&pvch,   g_vch);
    cudaGetSymbolAddress((void**)&pmask,  g_mask);
    cudaGetSymbolAddress((void**)&pu,     g_u);
    cudaGetSymbolAddress((void**)&psc,    g_scores);
    cudaGetSymbolAddress((void**)&pb1acat,g_b1acat);
    cudaGetSymbolAddress((void**)&pvcatf, g_vcatf);
    cudaGetSymbolAddress((void**)&ptok,   g_tok);
    cudaGetSymbolAddress((void**)&pbmx,   g_bmaxu);

    const int M2 = (int)(2 * BL);          // 262144
    const unsigned MV = (VOC + 127) / 128; // 391
    const int RALL = 1 << 30;              // relu on all columns
    auto cdiv = [](long n, long d) { return (unsigned)((n + d - 1) / d); };

    // 1. emb -> fp16 (padded)
    conv2h_k<<<cdiv((long)VOC * EP, 256), 256>>>(emb, pembh, VOC, EP, VOC, Esz);
    // 2. all weights in one kernel
    long wtot = (long)EP * NCAT + 2 * Hsz * Hsz + 2 * Hsz * Hsz + NCAT;
    convw_k<<<cdiv(wtot, 256), 256>>>(W1a, W1c, W2a, W2c, W1g, b1a);
    // 3. masks + tok + bmax + vcat zero
    mask_k<<<cdiv(2 * BL, 256), 256>>>(s1, s2, len1, len2);

    // 4. fused vocab GEMM: [attendL1(relu,b1a) | e@W1cT | e@W1cB]  (N=640)
    gemm_h<false,false,true><<<dim3(5, MV, 1), 256>>>(
        pembh, 0, EP, nullptr, pWcat, 0, NCAT, nullptr, pb1acat, nullptr, 0,
        nullptr, nullptr, 0, pvcb, 0, NCAT, VOC, NCAT, EP, Hsz, nullptr, nullptr);
    // 5. attend L2: hv = relu(vcb[:, :200] @ W2a + b2a)
    gemm_h<false,false,true><<<dim3(2, MV, 1), 256>>>(
        pvcb, 0, NCAT, nullptr, pW2a, 0, Hsz, nullptr, b2a, nullptr, 0,
        nullptr, nullptr, 0, phvh, 0, Hsz, VOC, Hsz, Hsz, RALL, nullptr, nullptr);

    // 6. scores[b] = hv[s1] @ hv[s2]^T  (profiled launch; epilogue batch-max)
    gemm_h<false,true,false><<<dim3(2, 2, Bsz), 256>>>(
        phvh, 0, Hsz, s1, phvh, 0, Hsz, s2, nullptr, nullptr, 0,
        nullptr, nullptr, 0, psc, LL, Lsz, Lsz, Lsz, Hsz, 0, pbmx, nullptr);

    // 7. fused softmax -> fp16 ean / ebn
    sums_k<<<Bsz, 1024>>>();

    // 8. compare hidden via pushed-through W1c_bottom (cv2 = vcb+400, cv = vcb+200)
    gemm_h<false,false,true><<<dim3(2, 2, Bsz), 256>>>(
        pebnh, LL, Lsz, nullptr, pvcb + 400, 0, NCAT, s2, b1c, nullptr, 0,
        pvcb + 200, ptok, NCAT, pthh, (long)Lsz * Hsz, Hsz,
        Lsz, Hsz, Lsz, RALL, nullptr, nullptr);
    gemm_h<true,false,true><<<dim3(2, 2, Bsz), 256>>>(
        peanh, LL, Lsz, nullptr, pvcb + 400, 0, NCAT, s1, b1c, nullptr, 0,
        pvcb + 200, ptok + BL, NCAT, pthh + BL * Hsz, (long)Lsz * Hsz, Hsz,
        Lsz, Hsz, Lsz, RALL, nullptr, nullptr);

    // 9. compare L2 with FUSED masked column-sum -> vcat accumulator (no store)
    gemm_h<false,false,true><<<dim3(2, M2 / 128, 1), 256>>>(
        pthh, 0, Hsz, nullptr, pW2c, 0, Hsz, nullptr, b2c, pmask, 0,
        nullptr, nullptr, 0, nullptr, 0, Hsz, M2, Hsz, Hsz, RALL, nullptr, pvcatf);

    // 10. vcat fp32 -> fp16 ; aggregate head
    vconv_k<<<cdiv(Bsz * 2 * Hsz, 256), 256>>>();
    gemm_h<false,false,false><<<dim3(2, 4, 1), 256>>>(
        pvch, 0, 2 * Hsz, nullptr, pW1g, 0, Hsz, nullptr, b1g, nullptr, 0,
        nullptr, nullptr, 0, pu, 0, Hsz, Bsz, Hsz, 2 * Hsz, RALL, nullptr, nullptr);
    final_k<<<Bsz, 64>>>(W2g, b2g, out);
}

// round 10
// speedup vs baseline: 10.9853x; 1.1272x over previous
#include <cuda_runtime.h>
#include <cuda_fp16.h>
#include <cstdint>

// Problem constants
#define Bsz 512
#define Lsz 256
#define Esz 300
#define EP  304              // padded E (16B-aligned fp16 rows)
#define Hsz 200
#define NCAT 640             // packed vocab-GEMM width: [W1a | W1cT | W1cB | pad]
#define VOC 50000
constexpr long BL  = (long)Bsz * Lsz;      // 131072
constexpr long LL  = (long)Lsz * Lsz;      // 65536
constexpr long BLL = BL * Lsz;             // 33,554,432

// ---------------- device scratch (static, no runtime allocation) -------------
__device__ __half g_embh[(long)VOC * EP];
__device__ __half g_Wcat[EP * NCAT];        // cols 0..199 W1a, 200..399 W1cT, 400..599 W1cB
__device__ __half g_W2a[Hsz * Hsz];
__device__ __half g_W2c[Hsz * Hsz];
__device__ __half g_W1g[2 * Hsz * Hsz];
__device__ float  g_b1acat[NCAT];           // b1a zero-extended to 640
__device__ __half g_vcb[(long)VOC * NCAT];  // vocab: [attendL1relu | e@W1cT | e@W1cB]
__device__ __half g_hvh[(long)VOC * Hsz];   // vocab attend_ff out
__device__ __half g_eanh[BLL];              // normalized alpha weights
__device__ __half g_ebnh[BLL];              // normalized beta weights
__device__ __half g_thh[2 * BL * Hsz];      // compare hidden
__device__ __half g_vch[Bsz * 2 * Hsz];     // vcat fp16
__device__ float  g_vcatf[Bsz * 2 * Hsz];   // vcat fp32 accumulator
__device__ float    g_scores[BLL];
__device__ float    g_mask[2 * BL];
__device__ int      g_tok[2 * BL];
__device__ unsigned g_bmaxu[Bsz];           // encoded per-batch max
__device__ float    g_u[Bsz * Hsz];

// ---------------- PTX helpers ------------------------------------------------
__device__ __forceinline__ void cp16(uint32_t dst, const void* src, bool pred)
{
    int sz = pred ? 16 : 0;                 // sz=0 -> 16B zero-fill
    asm volatile("cp.async.cg.shared.global [%0], [%1], 16, %2;"
                 :: "r"(dst), "l"(src), "r"(sz));
}
__device__ __forceinline__ void cp_commit() { asm volatile("cp.async.commit_group;"); }
template <int N>
__device__ __forceinline__ void cp_wait() { asm volatile("cp.async.wait_group %0;" :: "n"(N)); }

__device__ __forceinline__ void ldsm4(uint32_t* r, uint32_t a)
{
    asm volatile("ldmatrix.sync.aligned.m8n8.x4.shared.b16 {%0,%1,%2,%3}, [%4];"
                 : "=r"(r[0]), "=r"(r[1]), "=r"(r[2]), "=r"(r[3]) : "r"(a));
}
__device__ __forceinline__ void ldsm4t(uint32_t* r, uint32_t a)
{
    asm volatile("ldmatrix.sync.aligned.m8n8.x4.trans.shared.b16 {%0,%1,%2,%3}, [%4];"
                 : "=r"(r[0]), "=r"(r[1]), "=r"(r[2]), "=r"(r[3]) : "r"(a));
}
__device__ __forceinline__ void mma16816(float c[4], const uint32_t a[4], const uint32_t* b)
{
    asm volatile(
        "mma.sync.aligned.m16n8k16.row.col.f32.f16.f16.f32 "
        "{%0,%1,%2,%3}, {%4,%5,%6,%7}, {%8,%9}, {%0,%1,%2,%3};"
        : "+f"(c[0]), "+f"(c[1]), "+f"(c[2]), "+f"(c[3])
        : "r"(a[0]), "r"(a[1]), "r"(a[2]), "r"(a[3]), "r"(b[0]), "r"(b[1]));
}

// ordered-uint encoding of float for atomicMax (monotone)
__device__ __forceinline__ unsigned fenc(float f)
{
    unsigned u = __float_as_uint(f);
    return (u & 0x80000000u) ? ~u : (u | 0x80000000u);
}
__device__ __forceinline__ float fdec(unsigned e)
{
    return (e & 0x80000000u) ? __uint_as_float(e & 0x7FFFFFFFu)
                             : __uint_as_float(~e);
}

// ---------------- 128x128x32 fp16 tensor GEMM, 3-stage cp.async + LDSM -------
// C[bz][m,n] = epi( sum_k A(m,k) * B(k,n) ), fp32 accumulate.
// TA: A[m,k]=A[k*lda+m]; TB: B[k,n]=B[n*ldb+k].
// iA (only !TA): source row of A-row m is iA[bz*256+m] (caller passes sA=0).
// iB: source row of B's leading dim (k if !TB, n if TB) is iB[bz*256+row].
// epilogue: v = acc (+ Cin[iC[bz*256+m], n] stride ldcin) (+ bias[n]);
//           relu iff n < nrelu; * rs[bz*sRS+m];
//           vacc: fused column-sum -> atomicAdd, no C store;
//           bmaxu: per-batch atomicMax of raw acc (exact tiles only).
// All element offsets fit in int32 at every call site.
template <bool TA, bool TB, bool OUTH>
__global__ __launch_bounds__(256)
void gemm_h(const __half* __restrict__ A, long sA, int lda, const int* __restrict__ iA,
            const __half* __restrict__ Bw, long sB, int ldb, const int* __restrict__ iB,
            const float* __restrict__ bias,
            const float* __restrict__ rs, int sRS,
            const __half* __restrict__ Cin, const int* __restrict__ iC, int ldcin,
            void* __restrict__ Cv, long sC, int ldc,
            int M, int N, int K, int nrelu,
            unsigned* bmaxu, float* vacc)
{
    constexpr int A_SZ = TA ? 32 * 136 : 128 * 40;   // halfs per stage
    constexpr int B_SZ = TB ? 128 * 40 : 32 * 136;
    extern __shared__ __half smem_[];
    __half* Asm = smem_;                  // 3 stages of A
    __half* Bsm = smem_ + 3 * A_SZ;       // 3 stages of B

    int bz = blockIdx.z;
    const __half* Ab = A + (long)bz * sA;
    const __half* Bb = Bw + (long)bz * sB;
    int m0 = blockIdx.y * 128, n0 = blockIdx.x * 128;
    int tid = threadIdx.x;
    int wid = tid >> 5, lane = tid & 31;
    int wm = wid >> 2, wn = wid & 3;
    int g = lane >> 2, tig = lane & 3;

    uint32_t abase = (uint32_t)__cvta_generic_to_shared(Asm);
    uint32_t bbase = (uint32_t)__cvta_generic_to_shared(Bsm);

    float c[4][4][4];
#pragma unroll
    for (int i = 0; i < 4; i++)
#pragma unroll
        for (int j = 0; j < 4; j++)
#pragma unroll
            for (int q = 0; q < 4; q++) c[i][j][q] = 0.f;

    int KT = (K + 31) / 32;

    auto load_stage = [&](int st, int k0) {
#pragma unroll
        for (int it = 0; it < 2; it++) {
            int id = tid + it * 256;
            if (!TA) {
                int row = id >> 2, c8 = (id & 3) * 8;
                bool p = (m0 + row < M) && (k0 + c8 < K);
                int rg = iA ? (p ? iA[bz * 256 + m0 + row] : 0) : (m0 + row);
                cp16(abase + (uint32_t)(st * A_SZ + row * 40 + c8) * 2,
                     Ab + (long)rg * lda + (k0 + c8), p);
            } else {
                int kr = id >> 4, c8 = (id & 15) * 8;
                bool p = (k0 + kr < K) && (m0 + c8 < M);
                cp16(abase + (uint32_t)(st * A_SZ + kr * 136 + c8) * 2,
                     Ab + (long)(k0 + kr) * lda + (m0 + c8), p);
            }
            if (!TB) {
                int kr = id >> 4, c8 = (id & 15) * 8;
                bool p = (k0 + kr < K) && (n0 + c8 < N);
                int rg = iB ? ((k0 + kr < K) ? iB[bz * 256 + k0 + kr] : 0) : (k0 + kr);
                cp16(bbase + (uint32_t)(st * B_SZ + kr * 136 + c8) * 2,
                     Bb + (long)rg * ldb + (n0 + c8), p);
            } else {
                int row = id >> 2, c8 = (id & 3) * 8;
                bool p = (n0 + row < N) && (k0 + c8 < K);
                int rg = iB ? ((n0 + row < N) ? iB[bz * 256 + n0 + row] : 0) : (n0 + row);
                cp16(bbase + (uint32_t)(st * B_SZ + row * 40 + c8) * 2,
                     Bb + (long)rg * ldb + (k0 + c8), p);
            }
        }
        cp_commit();
    };

    load_stage(0, 0);
    if (KT > 1) load_stage(1, 32);

    for (int kt = 0; kt < KT; kt++) {
        if (kt + 1 < KT) cp_wait<1>(); else cp_wait<0>();
        __syncthreads();    // single barrier per iter: stage (kt-1)%3 is now free
        int st = kt - (kt / 3) * 3;
        uint32_t ab2 = abase + (uint32_t)(st * A_SZ) * 2;
        uint32_t bb2 = bbase + (uint32_t)(st * B_SZ) * 2;

#pragma unroll
        for (int s2 = 0; s2 < 2; s2++) {
            int ks = s2 * 16;
            uint32_t af[4][4], bq[2][4];
#pragma unroll
            for (int mt = 0; mt < 4; mt++) {
                if (!TA) {
                    int m = wm * 64 + mt * 16 + (lane & 15);
                    int kc = ks + ((lane >> 4) << 3);
                    ldsm4(af[mt], ab2 + (uint32_t)(m * 40 + kc) * 2);
                } else {
                    int kr = ks + (lane & 7) + ((lane >> 4) << 3);
                    int mc = wm * 64 + mt * 16 + (((lane >> 3) & 1) << 3);
                    ldsm4t(af[mt], ab2 + (uint32_t)(kr * 136 + mc) * 2);
                }
            }
            // B: two ldsm.x4 cover all four n-tiles (lanes 16-31 -> second tile)
#pragma unroll
            for (int np = 0; np < 2; np++) {
                if (TB) {
                    int n = wn * 32 + np * 16 + ((lane >> 4) << 3) + (lane & 7);
                    int kc = ks + (((lane >> 3) & 1) << 3);
                    ldsm4(bq[np], bb2 + (uint32_t)(n * 40 + kc) * 2);
                } else {
                    int kr = ks + (lane & 7) + (((lane >> 3) & 1) << 3);
                    int nc = wn * 32 + np * 16 + (((lane >> 4) & 1) << 3);
                    ldsm4t(bq[np], bb2 + (uint32_t)(kr * 136 + nc) * 2);
                }
            }
#pragma unroll
            for (int mt = 0; mt < 4; mt++)
#pragma unroll
                for (int nt = 0; nt < 4; nt++)
                    mma16816(c[mt][nt], af[mt], &bq[nt >> 1][(nt & 1) * 2]);
        }
        if (kt + 2 < KT) load_stage((kt + 2) - ((kt + 2) / 3) * 3, (kt + 2) * 32);
    }

    // ---- fused column-sum epilogue (compare L2): no C store
    if (vacc) {
        int b2v = m0 >> 8;   // 128-row blocks never straddle a 256-row segment
        int voff = (b2v < Bsz) ? b2v * (2 * Hsz) : (b2v - Bsz) * (2 * Hsz) + Hsz;
#pragma unroll
        for (int nt = 0; nt < 4; nt++) {
            int n = n0 + wn * 32 + nt * 8 + tig * 2;
            float s0 = 0.f, s1 = 0.f;
            if (n < N) {
#pragma unroll
                for (int mt = 0; mt < 4; mt++)
#pragma unroll
                    for (int r = 0; r < 2; r++) {
                        int m = m0 + wm * 64 + mt * 16 + g + r * 8;
                        float rsv = rs ? rs[(long)bz * sRS + m] : 1.f;
                        float v0 = c[mt][nt][r * 2 + 0];
                        float v1 = c[mt][nt][r * 2 + 1];
                        if (bias) { v0 += bias[n]; v1 += bias[n + 1]; }
                        if (n < nrelu) { v0 = fmaxf(v0, 0.f); v1 = fmaxf(v1, 0.f); }
                        s0 += v0 * rsv; s1 += v1 * rsv;
                    }
            }
            s0 += __shfl_down_sync(~0u, s0, 16);
            s0 += __shfl_down_sync(~0u, s0, 8);
            s0 += __shfl_down_sync(~0u, s0, 4);
            s1 += __shfl_down_sync(~0u, s1, 16);
            s1 += __shfl_down_sync(~0u, s1, 8);
            s1 += __shfl_down_sync(~0u, s1, 4);
            if (g == 0 && n < N) {
                atomicAdd(&vacc[voff + n], s0);
                atomicAdd(&vacc[voff + n + 1], s1);
            }
        }
        return;
    }

    __half* Ch = (__half*)Cv + (long)bz * sC;
    float*  Cf = (float*)Cv + (long)bz * sC;
#pragma unroll
    for (int mt = 0; mt < 4; mt++) {
#pragma unroll
        for (int r = 0; r < 2; r++) {
            int m = m0 + wm * 64 + mt * 16 + g + r * 8;
            if (m >= M) continue;
            float rsv = rs ? rs[(long)bz * sRS + m] : 1.f;
            int crow = 0;
            if (Cin) crow = iC ? iC[bz * 256 + m] : m;
#pragma unroll
            for (int nt = 0; nt < 4; nt++) {
                int n = n0 + wn * 32 + nt * 8 + tig * 2;
                if (n < N) {
                    float v0 = c[mt][nt][r * 2 + 0];
                    float v1 = c[mt][nt][r * 2 + 1];
                    if (Cin) {
                        v0 += __half2float(Cin[(long)crow * ldcin + n]);
                        v1 += __half2float(Cin[(long)crow * ldcin + n + 1]);
                    }
                    if (bias) { v0 += bias[n]; v1 += bias[n + 1]; }
                    if (n < nrelu) { v0 = fmaxf(v0, 0.f); v1 = fmaxf(v1, 0.f); }
                    v0 *= rsv; v1 *= rsv;
                    if (OUTH)
                        *(__half2*)(Ch + (long)m * ldc + n) = __floats2half2_rn(v0, v1);
                    else {
                        Cf[(long)m * ldc + n] = v0;
                        Cf[(long)m * ldc + n + 1] = v1;
                    }
                }
            }
        }
    }

    if (bmaxu) {   // per-batch max of this block's outputs (exact tiles only)
        float mx = -1e30f;
#pragma unroll
        for (int mt = 0; mt < 4; mt++)
#pragma unroll
            for (int nt = 0; nt < 4; nt++)
#pragma unroll
                for (int q = 0; q < 4; q++) mx = fmaxf(mx, c[mt][nt][q]);
#pragma unroll
        for (int o = 16; o; o >>= 1) mx = fmaxf(mx, __shfl_xor_sync(~0u, mx, o));
        if (lane == 0) atomicMax(&bmaxu[bz], fenc(mx));
    }
}

// dynamic smem bytes per instantiation
constexpr int smem_bytes(bool TA, bool TB)
{
    int a = TA ? 32 * 136 : 128 * 40;
    int b = TB ? 128 * 40 : 32 * 136;
    return 3 * (a + b) * 2;
}

// ---------------- helper kernels ---------------------------------------------
__global__ void conv2h_k(const float* __restrict__ src, __half* __restrict__ dst,
                         int rows, int cols, int srcR, int srcC)
{
    long idx = (long)blockIdx.x * blockDim.x + threadIdx.x;
    if (idx >= (long)rows * cols) return;
    int r = (int)(idx / cols), c = (int)(idx % cols);
    float v = (r < srcR && c < srcC) ? src[(long)r * srcC + c] : 0.f;
    dst[idx] = __float2half_rn(v);
}

// all weight conversions in ONE kernel (Wcat packing + W2a/W2c/W1g + biascat)
__global__ void convw_k(const float* __restrict__ W1a, const float* __restrict__ W1c,
                        const float* __restrict__ W2a, const float* __restrict__ W2c,
                        const float* __restrict__ W1g, const float* __restrict__ b1a)
{
    long idx = (long)blockIdx.x * blockDim.x + threadIdx.x;
    const long NW = (long)EP * NCAT;
    if (idx < NW) {
        int r = (int)(idx / NCAT), cc = (int)(idx % NCAT);
        float v = 0.f;
        if (r < Esz) {
            if (cc < 200)      v = W1a[(long)r * Hsz + cc];
            else if (cc < 400) v = W1c[(long)r * Hsz + (cc - 200)];
            else if (cc < 600) v = W1c[(long)(Esz + r) * Hsz + (cc - 400)];
        }
        g_Wcat[idx] = __float2half_rn(v);
        return;
    }
    idx -= NW;
    if (idx < Hsz * Hsz) { g_W2a[idx] = __float2half_rn(W2a[idx]); return; }
    idx -= Hsz * Hsz;
    if (idx < Hsz * Hsz) { g_W2c[idx] = __float2half_rn(W2c[idx]); return; }
    idx -= Hsz * Hsz;
    if (idx < 2 * Hsz * Hsz) { g_W1g[idx] = __float2half_rn(W1g[idx]); return; }
    idx -= 2 * Hsz * Hsz;
    if (idx < NCAT) { g_b1acat[idx] = (idx < Hsz) ? b1a[idx] : 0.f; return; }
}

// masks + token index concat + bmax init + vcat accumulator zero
__global__ void mask_k(const int* __restrict__ s1, const int* __restrict__ s2,
                       const int* __restrict__ len1, const int* __restrict__ len2)
{
    long idx = (long)blockIdx.x * blockDim.x + threadIdx.x;
    if (idx >= 2 * BL) return;
    int seq = (int)(idx / BL);
    long r = idx % BL;
    int b = (int)(r / Lsz), l = (int)(r % Lsz);
    int len = seq ? len2[b] : len1[b];
    g_mask[idx] = (l < len) ? 1.f : 0.f;
    g_tok[idx] = seq ? s2[r] : s1[r];
    if (idx < Bsz) g_bmaxu[idx] = 0u;
    if (idx < Bsz * 2 * Hsz) g_vcatf[idx] = 0.f;
}

// Fused softmax (shift-cancelled): p = exp(e - Mb);
// colsum(p*m1i) -> rsa; rowsum(p*m2j) -> rsb; emit fp16 ean/ebn normalized.
__global__ void sums_k()
{
    __shared__ float rowacc[256];
    __shared__ float colsm[1024];
    __shared__ float rsa_s[256];
    __shared__ float rsb_s[256];
    int b = blockIdx.x;
    int tid = threadIdx.x;
    int j = tid & 255, s = tid >> 8, lane = tid & 31;
    if (tid < 256) rowacc[tid] = 0.f;
    __syncthreads();

    long base = (long)b * LL;
    float Mb  = fdec(g_bmaxu[b]);
    float m2j = g_mask[BL + (long)b * Lsz + j];
    float da = 0.f;
    for (int t = 0; t < 64; t++) {
        int i = s * 64 + t;
        float p = __expf(g_scores[base + (long)i * Lsz + j] - Mb);
        da += p * g_mask[(long)b * Lsz + i];
        float v = p * m2j;
#pragma unroll
        for (int o = 16; o; o >>= 1) v += __shfl_xor_sync(~0u, v, o);
        if (lane == 0) atomicAdd(&rowacc[i], v);
    }
    colsm[tid] = da;
    __syncthreads();
    if (s == 0)
        rsa_s[j] = m2j / (colsm[j] + colsm[j + 256] + colsm[j + 512] + colsm[j + 768]);
    if (tid < 256)
        rsb_s[tid] = g_mask[(long)b * Lsz + tid] / rowacc[tid];
    __syncthreads();

    float rsaj = rsa_s[j];
    for (int t = 0; t < 64; t++) {
        int i = s * 64 + t;
        long idx = base + (long)i * Lsz + j;
        float p = __expf(g_scores[idx] - Mb);
        g_eanh[idx] = __float2half_rn(p * g_mask[(long)b * Lsz + i] * rsaj);
        g_ebnh[idx] = __float2half_rn(p * m2j * rsb_s[i]);
    }
}

__global__ void vconv_k()    // fp32 vcat accumulator -> fp16
{
    int idx = blockIdx.x * blockDim.x + threadIdx.x;
    if (idx < Bsz * 2 * Hsz) g_vch[idx] = __float2half_rn(g_vcatf[idx]);
}

__global__ void final_k(const float* __restrict__ W2g,
                        const float* __restrict__ b2g, float* __restrict__ out)
{
    int b = blockIdx.x;
    int o = threadIdx.x >> 5;
    int lane = threadIdx.x & 31;
    const float* u = g_u + (long)b * Hsz;
    float s = 0.f;
    for (int h = lane; h < Hsz; h += 32) s += u[h] * W2g[h * 2 + o];
#pragma unroll
    for (int off = 16; off; off >>= 1) s += __shfl_xor_sync(~0u, s, off);
    if (lane == 0) out[b * 2 + o] = s + b2g[o];
}

// ---------------- launch -----------------------------------------------------
extern "C" void kernel_launch(void* const* d_in, const int* in_sizes, int n_in,
                              void* d_out, int out_size)
{
    const float* emb = (const float*)d_in[0];
    const float* W1a = (const float*)d_in[1];
    const float* b1a = (const float*)d_in[2];
    const float* W2a = (const float*)d_in[3];
    const float* b2a = (const float*)d_in[4];
    const float* W1c = (const float*)d_in[5];
    const float* b1c = (const float*)d_in[6];
    const float* W2c = (const float*)d_in[7];
    const float* b2c = (const float*)d_in[8];
    const float* W1g = (const float*)d_in[9];
    const float* b1g = (const float*)d_in[10];
    const float* W2g = (const float*)d_in[11];
    const float* b2g = (const float*)d_in[12];
    const int* s1   = (const int*)d_in[13];
    const int* s2   = (const int*)d_in[14];
    const int* len1 = (const int*)d_in[15];
    const int* len2 = (const int*)d_in[16];
    float* out = (float*)d_out;

    __half *pembh, *pWcat, *pW2a, *pW2c, *pW1g, *pvcb, *phvh;
    __half *peanh, *pebnh, *pthh, *pvch;
    float *pmask, *pu, *psc, *pb1acat, *pvcatf;
    int *ptok;
    unsigned *pbmx;
    cudaGetSymbolAddress((void**)&pembh,  g_embh);
    cudaGetSymbolAddress((void**)&pWcat,  g_Wcat);
    cudaGetSymbolAddress((void**)&pW2a,   g_W2a);
    cudaGetSymbolAddress((void**)&pW2c,   g_W2c);
    cudaGetSymbolAddress((void**)&pW1g,   g_W1g);
    cudaGetSymbolAddress((void**)&pvcb,   g_vcb);
    cudaGetSymbolAddress((void**)&phvh,   g_hvh);
    cudaGetSymbolAddress((void**)&peanh,  g_eanh);
    cudaGetSymbolAddress((void**)&pebnh,  g_ebnh);
    cudaGetSymbolAddress((void**)&pthh,   g_thh);
    cudaGetSymbolAddress((void**)&pvch,   g_vch);
    cudaGetSymbolAddress((void**)&pmask,  g_mask);
    cudaGetSymbolAddress((void**)&pu,     g_u);
    cudaGetSymbolAddress((void**)&psc,    g_scores);
    cudaGetSymbolAddress((void**)&pb1acat,g_b1acat);
    cudaGetSymbolAddress((void**)&pvcatf, g_vcatf);
    cudaGetSymbolAddress((void**)&ptok,   g_tok);
    cudaGetSymbolAddress((void**)&pbmx,   g_bmaxu);

    const int M2 = (int)(2 * BL);          // 262144
    const unsigned MV = (VOC + 127) / 128; // 391
    const int RALL = 1 << 30;              // relu on all columns
    auto cdiv = [](long n, long d) { return (unsigned)((n + d - 1) / d); };

    // opt-in to >48KB dynamic smem per instantiation (host-side, capture-legal)
    constexpr int SM_FF = smem_bytes(false, false);   // 56832
    constexpr int SM_FT = smem_bytes(false, true);    // 61440
    constexpr int SM_TF = smem_bytes(true,  false);   // 52224
    cudaFuncSetAttribute((const void*)gemm_h<false,false,true>,
                         cudaFuncAttributeMaxDynamicSharedMemorySize, SM_FF);
    cudaFuncSetAttribute((const void*)gemm_h<false,false,false>,
                         cudaFuncAttributeMaxDynamicSharedMemorySize, SM_FF);
    cudaFuncSetAttribute((const void*)gemm_h<false,true,false>,
                         cudaFuncAttributeMaxDynamicSharedMemorySize, SM_FT);
    cudaFuncSetAttribute((const void*)gemm_h<true,false,true>,
                         cudaFuncAttributeMaxDynamicSharedMemorySize, SM_TF);

    // 1. emb -> fp16 (padded)
    conv2h_k<<<cdiv((long)VOC * EP, 256), 256>>>(emb, pembh, VOC, EP, VOC, Esz);
    // 2. all weights in one kernel
    long wtot = (long)EP * NCAT + 2 * Hsz * Hsz + 2 * Hsz * Hsz + NCAT;
    convw_k<<<cdiv(wtot, 256), 256>>>(W1a, W1c, W2a, W2c, W1g, b1a);
    // 3. masks + tok + bmax + vcat zero
    mask_k<<<cdiv(2 * BL, 256), 256>>>(s1, s2, len1, len2);

    // 4. fused vocab GEMM: [attendL1(relu,b1a) | e@W1cT | e@W1cB]  (N=640)
    gemm_h<false,false,true><<<dim3(5, MV, 1), 256, SM_FF>>>(
        pembh, 0, EP, nullptr, pWcat, 0, NCAT, nullptr, pb1acat, nullptr, 0,
        nullptr, nullptr, 0, pvcb, 0, NCAT, VOC, NCAT, EP, Hsz, nullptr, nullptr);
    // 5. attend L2: hv = relu(vcb[:, :200] @ W2a + b2a)
    gemm_h<false,false,true><<<dim3(2, MV, 1), 256, SM_FF>>>(
        pvcb, 0, NCAT, nullptr, pW2a, 0, Hsz, nullptr, b2a, nullptr, 0,
        nullptr, nullptr, 0, phvh, 0, Hsz, VOC, Hsz, Hsz, RALL, nullptr, nullptr);

    // 6. scores[b] = hv[s1] @ hv[s2]^T  (epilogue batch-max)
    gemm_h<false,true,false><<<dim3(2, 2, Bsz), 256, SM_FT>>>(
        phvh, 0, Hsz, s1, phvh, 0, Hsz, s2, nullptr, nullptr, 0,
        nullptr, nullptr, 0, psc, LL, Lsz, Lsz, Lsz, Hsz, 0, pbmx, nullptr);

    // 7. fused softmax -> fp16 ean / ebn
    sums_k<<<Bsz, 1024>>>();

    // 8. compare hidden via pushed-through W1c_bottom (cv2 = vcb+400, cv = vcb+200)
    gemm_h<false,false,true><<<dim3(2, 2, Bsz), 256, SM_FF>>>(
        pebnh, LL, Lsz, nullptr, pvcb + 400, 0, NCAT, s2, b1c, nullptr, 0,
        pvcb + 200, ptok, NCAT, pthh, (long)Lsz * Hsz, Hsz,
        Lsz, Hsz, Lsz, RALL, nullptr, nullptr);
    gemm_h<true,false,true><<<dim3(2, 2, Bsz), 256, SM_TF>>>(
        peanh, LL, Lsz, nullptr, pvcb + 400, 0, NCAT, s1, b1c, nullptr, 0,
        pvcb + 200, ptok + BL, NCAT, pthh + BL * Hsz, (long)Lsz * Hsz, Hsz,
        Lsz, Hsz, Lsz, RALL, nullptr, nullptr);

    // 9. compare L2 with FUSED masked column-sum -> vcat accumulator (no store)
    gemm_h<false,false,true><<<dim3(2, M2 / 128, 1), 256, SM_FF>>>(
        pthh, 0, Hsz, nullptr, pW2c, 0, Hsz, nullptr, b2c, pmask, 0,
        nullptr, nullptr, 0, nullptr, 0, Hsz, M2, Hsz, Hsz, RALL, nullptr, pvcatf);

    // 10. vcat fp32 -> fp16 ; aggregate head
    vconv_k<<<cdiv(Bsz * 2 * Hsz, 256), 256>>>();
    gemm_h<false,false,false><<<dim3(2, 4, 1), 256, SM_FF>>>(
        pvch, 0, 2 * Hsz, nullptr, pW1g, 0, Hsz, nullptr, b1g, nullptr, 0,
        nullptr, nullptr, 0, pu, 0, Hsz, Bsz, Hsz, 2 * Hsz, RALL, nullptr, nullptr);
    final_k<<<Bsz, 64>>>(W2g, b2g, out);
}

// round 11
// speedup vs baseline: 11.4199x; 1.0396x over previous
#include <cuda_runtime.h>
#include <cuda_fp16.h>
#include <cstdint>

// Problem constants
#define Bsz 512
#define Lsz 256
#define Esz 300
#define EP  304              // padded E (16B-aligned fp16 rows)
#define Hsz 200
#define NCAT 640             // packed vocab-GEMM width: [W1a | W1cT | W1cB | pad]
#define VOC 50000
constexpr long BL  = (long)Bsz * Lsz;      // 131072
constexpr long LL  = (long)Lsz * Lsz;      // 65536
constexpr long BLL = BL * Lsz;             // 33,554,432

// ---------------- device scratch (static, no runtime allocation) -------------
__device__ __half g_embh[(long)VOC * EP];
__device__ __half g_Wcat[EP * NCAT];        // cols 0..199 W1a, 200..399 W1cT, 400..599 W1cB
__device__ __half g_W2a[Hsz * Hsz];
__device__ __half g_W2c[Hsz * Hsz];
__device__ __half g_W1g[2 * Hsz * Hsz];
__device__ float  g_b1acat[NCAT];           // b1a zero-extended to 640
__device__ __half g_vcb[(long)VOC * NCAT];  // vocab: [attendL1relu | e@W1cT | e@W1cB]
__device__ __half g_hvh[(long)VOC * Hsz];   // vocab attend_ff out
__device__ __half g_eanh[BLL];              // normalized alpha weights
__device__ __half g_ebnh[BLL];              // normalized beta weights
__device__ __half g_thh[2 * BL * Hsz];      // compare hidden
__device__ __half g_vch[Bsz * 2 * Hsz];     // vcat fp16
__device__ float  g_vcatf[Bsz * 2 * Hsz];   // vcat fp32 accumulator
__device__ float    g_scores[BLL];
__device__ float    g_mask[2 * BL];
__device__ int      g_tok[2 * BL];
__device__ unsigned g_bmaxu[Bsz];           // encoded per-batch max
__device__ float    g_u[Bsz * Hsz];

// ---------------- PTX helpers ------------------------------------------------
__device__ __forceinline__ void cp16(uint32_t dst, const void* src, bool pred)
{
    int sz = pred ? 16 : 0;                 // sz=0 -> 16B zero-fill
    asm volatile("cp.async.cg.shared.global [%0], [%1], 16, %2;"
                 :: "r"(dst), "l"(src), "r"(sz));
}
__device__ __forceinline__ void cp_commit() { asm volatile("cp.async.commit_group;"); }
template <int N>
__device__ __forceinline__ void cp_wait() { asm volatile("cp.async.wait_group %0;" :: "n"(N)); }

__device__ __forceinline__ void ldsm4(uint32_t* r, uint32_t a)
{
    asm volatile("ldmatrix.sync.aligned.m8n8.x4.shared.b16 {%0,%1,%2,%3}, [%4];"
                 : "=r"(r[0]), "=r"(r[1]), "=r"(r[2]), "=r"(r[3]) : "r"(a));
}
__device__ __forceinline__ void ldsm4t(uint32_t* r, uint32_t a)
{
    asm volatile("ldmatrix.sync.aligned.m8n8.x4.trans.shared.b16 {%0,%1,%2,%3}, [%4];"
                 : "=r"(r[0]), "=r"(r[1]), "=r"(r[2]), "=r"(r[3]) : "r"(a));
}
__device__ __forceinline__ void mma16816(float c[4], const uint32_t a[4], const uint32_t* b)
{
    asm volatile(
        "mma.sync.aligned.m16n8k16.row.col.f32.f16.f16.f32 "
        "{%0,%1,%2,%3}, {%4,%5,%6,%7}, {%8,%9}, {%0,%1,%2,%3};"
        : "+f"(c[0]), "+f"(c[1]), "+f"(c[2]), "+f"(c[3])
        : "r"(a[0]), "r"(a[1]), "r"(a[2]), "r"(a[3]), "r"(b[0]), "r"(b[1]));
}

// ordered-uint encoding of float for atomicMax (monotone)
__device__ __forceinline__ unsigned fenc(float f)
{
    unsigned u = __float_as_uint(f);
    return (u & 0x80000000u) ? ~u : (u | 0x80000000u);
}
__device__ __forceinline__ float fdec(unsigned e)
{
    return (e & 0x80000000u) ? __uint_as_float(e & 0x7FFFFFFFu)
                             : __uint_as_float(~e);
}

// ---------------- 128x128x32 fp16 tensor GEMM, 4-stage cp.async + LDSM -------
// KT = number of 32-wide k-tiles (compile-time -> fully unrolled mainloop).
// C[bz][m,n] = epi( sum_k A(m,k) * B(k,n) ), fp32 accumulate.
// TA: A[m,k]=A[k*lda+m]; TB: B[k,n]=B[n*ldb+k].
// iA (only !TA): source row of A-row m is iA[bz*256+m] (caller passes sA=0).
// iB: source row of B's leading dim (k if !TB, n if TB) is iB[bz*256+row].
// epilogue: v = acc (+ Cin[iC[bz*256+m], n] stride ldcin) (+ bias[n]);
//           relu iff n < nrelu; * rs[bz*sRS+m];
//           vacc: fused column-sum -> atomicAdd, no C store;
//           bmaxu: per-batch atomicMax of raw acc (exact tiles only).
template <int KT, bool TA, bool TB, bool OUTH>
__global__ __launch_bounds__(256, 2)
void gemm_h(const __half* __restrict__ A, long sA, int lda, const int* __restrict__ iA,
            const __half* __restrict__ Bw, long sB, int ldb, const int* __restrict__ iB,
            const float* __restrict__ bias,
            const float* __restrict__ rs, int sRS,
            const __half* __restrict__ Cin, const int* __restrict__ iC, int ldcin,
            void* __restrict__ Cv, long sC, int ldc,
            int M, int N, int K, int nrelu,
            unsigned* bmaxu, float* vacc)
{
    constexpr int A_SZ = TA ? 32 * 136 : 128 * 40;   // halfs per stage
    constexpr int B_SZ = TB ? 128 * 40 : 32 * 136;
    extern __shared__ __half smem_[];
    __half* Asm = smem_;                  // 4 stages of A
    __half* Bsm = smem_ + 4 * A_SZ;       // 4 stages of B

    int bz = blockIdx.z;
    const __half* Ab = A + (long)bz * sA;
    const __half* Bb = Bw + (long)bz * sB;
    int m0 = blockIdx.y * 128, n0 = blockIdx.x * 128;
    int tid = threadIdx.x;
    int wid = tid >> 5, lane = tid & 31;
    int wm = wid >> 2, wn = wid & 3;
    int g = lane >> 2, tig = lane & 3;

    uint32_t abase = (uint32_t)__cvta_generic_to_shared(Asm);
    uint32_t bbase = (uint32_t)__cvta_generic_to_shared(Bsm);

    float c[4][4][4];
#pragma unroll
    for (int i = 0; i < 4; i++)
#pragma unroll
        for (int j = 0; j < 4; j++)
#pragma unroll
            for (int q = 0; q < 4; q++) c[i][j][q] = 0.f;

    auto load_stage = [&](int st, int k0) {
#pragma unroll
        for (int it = 0; it < 2; it++) {
            int id = tid + it * 256;
            if (!TA) {
                int row = id >> 2, c8 = (id & 3) * 8;
                bool p = (m0 + row < M) && (k0 + c8 < K);
                int rg = iA ? (p ? iA[bz * 256 + m0 + row] : 0) : (m0 + row);
                cp16(abase + (uint32_t)(st * A_SZ + row * 40 + c8) * 2,
                     Ab + (long)rg * lda + (k0 + c8), p);
            } else {
                int kr = id >> 4, c8 = (id & 15) * 8;
                bool p = (k0 + kr < K) && (m0 + c8 < M);
                cp16(abase + (uint32_t)(st * A_SZ + kr * 136 + c8) * 2,
                     Ab + (long)(k0 + kr) * lda + (m0 + c8), p);
            }
            if (!TB) {
                int kr = id >> 4, c8 = (id & 15) * 8;
                bool p = (k0 + kr < K) && (n0 + c8 < N);
                int rg = iB ? ((k0 + kr < K) ? iB[bz * 256 + k0 + kr] : 0) : (k0 + kr);
                cp16(bbase + (uint32_t)(st * B_SZ + kr * 136 + c8) * 2,
                     Bb + (long)rg * ldb + (n0 + c8), p);
            } else {
                int row = id >> 2, c8 = (id & 3) * 8;
                bool p = (n0 + row < N) && (k0 + c8 < K);
                int rg = iB ? ((n0 + row < N) ? iB[bz * 256 + n0 + row] : 0) : (n0 + row);
                cp16(bbase + (uint32_t)(st * B_SZ + row * 40 + c8) * 2,
                     Bb + (long)rg * ldb + (k0 + c8), p);
            }
        }
        cp_commit();
    };

    load_stage(0, 0);
    if (KT > 1) load_stage(1, 32);
    if (KT > 2) load_stage(2, 64);

#pragma unroll
    for (int kt = 0; kt < KT; kt++) {
        if (kt < KT - 2)      cp_wait<2>();
        else if (kt == KT - 2) cp_wait<1>();
        else                   cp_wait<0>();
        __syncthreads();    // single barrier: stage (kt+3)&3 == (kt-1)&3 is free
        int st = kt & 3;
        uint32_t ab2 = abase + (uint32_t)(st * A_SZ) * 2;
        uint32_t bb2 = bbase + (uint32_t)(st * B_SZ) * 2;

#pragma unroll
        for (int s2 = 0; s2 < 2; s2++) {
            int ks = s2 * 16;
            uint32_t af[4][4], bq[2][4];
#pragma unroll
            for (int mt = 0; mt < 4; mt++) {
                if (!TA) {
                    int m = wm * 64 + mt * 16 + (lane & 15);
                    int kc = ks + ((lane >> 4) << 3);
                    ldsm4(af[mt], ab2 + (uint32_t)(m * 40 + kc) * 2);
                } else {
                    int kr = ks + (lane & 7) + ((lane >> 4) << 3);
                    int mc = wm * 64 + mt * 16 + (((lane >> 3) & 1) << 3);
                    ldsm4t(af[mt], ab2 + (uint32_t)(kr * 136 + mc) * 2);
                }
            }
            // B: two ldsm.x4 cover all four n-tiles (lanes 16-31 -> second tile)
#pragma unroll
            for (int np = 0; np < 2; np++) {
                if (TB) {
                    int n = wn * 32 + np * 16 + ((lane >> 4) << 3) + (lane & 7);
                    int kc = ks + (((lane >> 3) & 1) << 3);
                    ldsm4(bq[np], bb2 + (uint32_t)(n * 40 + kc) * 2);
                } else {
                    int kr = ks + (lane & 7) + (((lane >> 3) & 1) << 3);
                    int nc = wn * 32 + np * 16 + (((lane >> 4) & 1) << 3);
                    ldsm4t(bq[np], bb2 + (uint32_t)(kr * 136 + nc) * 2);
                }
            }
#pragma unroll
            for (int mt = 0; mt < 4; mt++)
#pragma unroll
                for (int nt = 0; nt < 4; nt++)
                    mma16816(c[mt][nt], af[mt], &bq[nt >> 1][(nt & 1) * 2]);
        }
        if (kt + 3 < KT) load_stage((kt + 3) & 3, (kt + 3) * 32);
    }

    // ---- fused column-sum epilogue (compare L2): no C store
    if (vacc) {
        int b2v = m0 >> 8;   // 128-row blocks never straddle a 256-row segment
        int voff = (b2v < Bsz) ? b2v * (2 * Hsz) : (b2v - Bsz) * (2 * Hsz) + Hsz;
#pragma unroll
        for (int nt = 0; nt < 4; nt++) {
            int n = n0 + wn * 32 + nt * 8 + tig * 2;
            float s0 = 0.f, s1 = 0.f;
            if (n < N) {
#pragma unroll
                for (int mt = 0; mt < 4; mt++)
#pragma unroll
                    for (int r = 0; r < 2; r++) {
                        int m = m0 + wm * 64 + mt * 16 + g + r * 8;
                        float rsv = rs ? rs[(long)bz * sRS + m] : 1.f;
                        float v0 = c[mt][nt][r * 2 + 0];
                        float v1 = c[mt][nt][r * 2 + 1];
                        if (bias) { v0 += bias[n]; v1 += bias[n + 1]; }
                        if (n < nrelu) { v0 = fmaxf(v0, 0.f); v1 = fmaxf(v1, 0.f); }
                        s0 += v0 * rsv; s1 += v1 * rsv;
                    }
            }
            s0 += __shfl_down_sync(~0u, s0, 16);
            s0 += __shfl_down_sync(~0u, s0, 8);
            s0 += __shfl_down_sync(~0u, s0, 4);
            s1 += __shfl_down_sync(~0u, s1, 16);
            s1 += __shfl_down_sync(~0u, s1, 8);
            s1 += __shfl_down_sync(~0u, s1, 4);
            if (g == 0 && n < N) {
                atomicAdd(&vacc[voff + n], s0);
                atomicAdd(&vacc[voff + n + 1], s1);
            }
        }
        return;
    }

    __half* Ch = (__half*)Cv + (long)bz * sC;
    float*  Cf = (float*)Cv + (long)bz * sC;
#pragma unroll
    for (int mt = 0; mt < 4; mt++) {
#pragma unroll
        for (int r = 0; r < 2; r++) {
            int m = m0 + wm * 64 + mt * 16 + g + r * 8;
            if (m >= M) continue;
            float rsv = rs ? rs[(long)bz * sRS + m] : 1.f;
            int crow = 0;
            if (Cin) crow = iC ? iC[bz * 256 + m] : m;
#pragma unroll
            for (int nt = 0; nt < 4; nt++) {
                int n = n0 + wn * 32 + nt * 8 + tig * 2;
                if (n < N) {
                    float v0 = c[mt][nt][r * 2 + 0];
                    float v1 = c[mt][nt][r * 2 + 1];
                    if (Cin) {
                        v0 += __half2float(Cin[(long)crow * ldcin + n]);
                        v1 += __half2float(Cin[(long)crow * ldcin + n + 1]);
                    }
                    if (bias) { v0 += bias[n]; v1 += bias[n + 1]; }
                    if (n < nrelu) { v0 = fmaxf(v0, 0.f); v1 = fmaxf(v1, 0.f); }
                    v0 *= rsv; v1 *= rsv;
                    if (OUTH)
                        *(__half2*)(Ch + (long)m * ldc + n) = __floats2half2_rn(v0, v1);
                    else {
                        Cf[(long)m * ldc + n] = v0;
                        Cf[(long)m * ldc + n + 1] = v1;
                    }
                }
            }
        }
    }

    if (bmaxu) {   // per-batch max of this block's outputs (exact tiles only)
        float mx = -1e30f;
#pragma unroll
        for (int mt = 0; mt < 4; mt++)
#pragma unroll
            for (int nt = 0; nt < 4; nt++)
#pragma unroll
                for (int q = 0; q < 4; q++) mx = fmaxf(mx, c[mt][nt][q]);
#pragma unroll
        for (int o = 16; o; o >>= 1) mx = fmaxf(mx, __shfl_xor_sync(~0u, mx, o));
        if (lane == 0) atomicMax(&bmaxu[bz], fenc(mx));
    }
}

// dynamic smem bytes per instantiation (4 stages)
constexpr int smem_bytes(bool TA, bool TB)
{
    int a = TA ? 32 * 136 : 128 * 40;
    int b = TB ? 128 * 40 : 32 * 136;
    return 4 * (a + b) * 2;
}

// ---------------- helper kernels ---------------------------------------------
__global__ void conv2h_k(const float* __restrict__ src, __half* __restrict__ dst,
                         int rows, int cols, int srcR, int srcC)
{
    long idx = (long)blockIdx.x * blockDim.x + threadIdx.x;
    if (idx >= (long)rows * cols) return;
    int r = (int)(idx / cols), c = (int)(idx % cols);
    float v = (r < srcR && c < srcC) ? src[(long)r * srcC + c] : 0.f;
    dst[idx] = __float2half_rn(v);
}

// all weight conversions in ONE kernel (Wcat packing + W2a/W2c/W1g + biascat)
__global__ void convw_k(const float* __restrict__ W1a, const float* __restrict__ W1c,
                        const float* __restrict__ W2a, const float* __restrict__ W2c,
                        const float* __restrict__ W1g, const float* __restrict__ b1a)
{
    long idx = (long)blockIdx.x * blockDim.x + threadIdx.x;
    const long NW = (long)EP * NCAT;
    if (idx < NW) {
        int r = (int)(idx / NCAT), cc = (int)(idx % NCAT);
        float v = 0.f;
        if (r < Esz) {
            if (cc < 200)      v = W1a[(long)r * Hsz + cc];
            else if (cc < 400) v = W1c[(long)r * Hsz + (cc - 200)];
            else if (cc < 600) v = W1c[(long)(Esz + r) * Hsz + (cc - 400)];
        }
        g_Wcat[idx] = __float2half_rn(v);
        return;
    }
    idx -= NW;
    if (idx < Hsz * Hsz) { g_W2a[idx] = __float2half_rn(W2a[idx]); return; }
    idx -= Hsz * Hsz;
    if (idx < Hsz * Hsz) { g_W2c[idx] = __float2half_rn(W2c[idx]); return; }
    idx -= Hsz * Hsz;
    if (idx < 2 * Hsz * Hsz) { g_W1g[idx] = __float2half_rn(W1g[idx]); return; }
    idx -= 2 * Hsz * Hsz;
    if (idx < NCAT) { g_b1acat[idx] = (idx < Hsz) ? b1a[idx] : 0.f; return; }
}

// masks + token index concat + bmax init + vcat accumulator zero
__global__ void mask_k(const int* __restrict__ s1, const int* __restrict__ s2,
                       const int* __restrict__ len1, const int* __restrict__ len2)
{
    long idx = (long)blockIdx.x * blockDim.x + threadIdx.x;
    if (idx >= 2 * BL) return;
    int seq = (int)(idx / BL);
    long r = idx % BL;
    int b = (int)(r / Lsz), l = (int)(r % Lsz);
    int len = seq ? len2[b] : len1[b];
    g_mask[idx] = (l < len) ? 1.f : 0.f;
    g_tok[idx] = seq ? s2[r] : s1[r];
    if (idx < Bsz) g_bmaxu[idx] = 0u;
    if (idx < Bsz * 2 * Hsz) g_vcatf[idx] = 0.f;
}

// Fused softmax (shift-cancelled): p = exp(e - Mb);
// colsum(p*m1i) -> rsa; rowsum(p*m2j) -> rsb; emit fp16 ean/ebn normalized.
__global__ void sums_k()
{
    __shared__ float rowacc[256];
    __shared__ float colsm[1024];
    __shared__ float rsa_s[256];
    __shared__ float rsb_s[256];
    int b = blockIdx.x;
    int tid = threadIdx.x;
    int j = tid & 255, s = tid >> 8, lane = tid & 31;
    if (tid < 256) rowacc[tid] = 0.f;
    __syncthreads();

    long base = (long)b * LL;
    float Mb  = fdec(g_bmaxu[b]);
    float m2j = g_mask[BL + (long)b * Lsz + j];
    float da = 0.f;
    for (int t = 0; t < 64; t++) {
        int i = s * 64 + t;
        float p = __expf(g_scores[base + (long)i * Lsz + j] - Mb);
        da += p * g_mask[(long)b * Lsz + i];
        float v = p * m2j;
#pragma unroll
        for (int o = 16; o; o >>= 1) v += __shfl_xor_sync(~0u, v, o);
        if (lane == 0) atomicAdd(&rowacc[i], v);
    }
    colsm[tid] = da;
    __syncthreads();
    if (s == 0)
        rsa_s[j] = m2j / (colsm[j] + colsm[j + 256] + colsm[j + 512] + colsm[j + 768]);
    if (tid < 256)
        rsb_s[tid] = g_mask[(long)b * Lsz + tid] / rowacc[tid];
    __syncthreads();

    float rsaj = rsa_s[j];
    for (int t = 0; t < 64; t++) {
        int i = s * 64 + t;
        long idx = base + (long)i * Lsz + j;
        float p = __expf(g_scores[idx] - Mb);
        g_eanh[idx] = __float2half_rn(p * g_mask[(long)b * Lsz + i] * rsaj);
        g_ebnh[idx] = __float2half_rn(p * m2j * rsb_s[i]);
    }
}

__global__ void vconv_k()    // fp32 vcat accumulator -> fp16
{
    int idx = blockIdx.x * blockDim.x + threadIdx.x;
    if (idx < Bsz * 2 * Hsz) g_vch[idx] = __float2half_rn(g_vcatf[idx]);
}

__global__ void final_k(const float* __restrict__ W2g,
                        const float* __restrict__ b2g, float* __restrict__ out)
{
    int b = blockIdx.x;
    int o = threadIdx.x >> 5;
    int lane = threadIdx.x & 31;
    const float* u = g_u + (long)b * Hsz;
    float s = 0.f;
    for (int h = lane; h < Hsz; h += 32) s += u[h] * W2g[h * 2 + o];
#pragma unroll
    for (int off = 16; off; off >>= 1) s += __shfl_xor_sync(~0u, s, off);
    if (lane == 0) out[b * 2 + o] = s + b2g[o];
}

// ---------------- launch -----------------------------------------------------
extern "C" void kernel_launch(void* const* d_in, const int* in_sizes, int n_in,
                              void* d_out, int out_size)
{
    const float* emb = (const float*)d_in[0];
    const float* W1a = (const float*)d_in[1];
    const float* b1a = (const float*)d_in[2];
    const float* W2a = (const float*)d_in[3];
    const float* b2a = (const float*)d_in[4];
    const float* W1c = (const float*)d_in[5];
    const float* b1c = (const float*)d_in[6];
    const float* W2c = (const float*)d_in[7];
    const float* b2c = (const float*)d_in[8];
    const float* W1g = (const float*)d_in[9];
    const float* b1g = (const float*)d_in[10];
    const float* W2g = (const float*)d_in[11];
    const float* b2g = (const float*)d_in[12];
    const int* s1   = (const int*)d_in[13];
    const int* s2   = (const int*)d_in[14];
    const int* len1 = (const int*)d_in[15];
    const int* len2 = (const int*)d_in[16];
    float* out = (float*)d_out;

    __half *pembh, *pWcat, *pW2a, *pW2c, *pW1g, *pvcb, *phvh;
    __half *peanh, *pebnh, *pthh, *pvch;
    float *pmask, *pu, *psc, *pb1acat, *pvcatf;
    int *ptok;
    unsigned *pbmx;
    cudaGetSymbolAddress((void**)&pembh,  g_embh);
    cudaGetSymbolAddress((void**)&pWcat,  g_Wcat);
    cudaGetSymbolAddress((void**)&pW2a,   g_W2a);
    cudaGetSymbolAddress((void**)&pW2c,   g_W2c);
    cudaGetSymbolAddress((void**)&pW1g,   g_W1g);
    cudaGetSymbolAddress((void**)&pvcb,   g_vcb);
    cudaGetSymbolAddress((void**)&phvh,   g_hvh);
    cudaGetSymbolAddress((void**)&peanh,  g_eanh);
    cudaGetSymbolAddress((void**)&pebnh,  g_ebnh);
    cudaGetSymbolAddress((void**)&pthh,   g_thh);
    cudaGetSymbolAddress((void**)&pvch,   g_vch);
    cudaGetSymbolAddress((void**)&pmask,  g_mask);
    cudaGetSymbolAddress((void**)&pu,     g_u);
    cudaGetSymbolAddress((void**)&psc,    g_scores);
    cudaGetSymbolAddress((void**)&pb1acat,g_b1acat);
    cudaGetSymbolAddress((void**)&pvcatf, g_vcatf);
    cudaGetSymbolAddress((void**)&ptok,   g_tok);
    cudaGetSymbolAddress((void**)&pbmx,   g_bmaxu);

    const int M2 = (int)(2 * BL);          // 262144
    const unsigned MV = (VOC + 127) / 128; // 391
    const int RALL = 1 << 30;              // relu on all columns
    auto cdiv = [](long n, long d) { return (unsigned)((n + d - 1) / d); };

    // KT per call site: EP=304 -> 10, K=200 -> 7, K=256 -> 8, K=400 -> 13
    constexpr int SM_FF = smem_bytes(false, false);   // 75776
    constexpr int SM_FT = smem_bytes(false, true);    // 81920
    constexpr int SM_TF = smem_bytes(true,  false);   // 75776
    cudaFuncSetAttribute((const void*)gemm_h<10,false,false,true>,
                         cudaFuncAttributeMaxDynamicSharedMemorySize, SM_FF);
    cudaFuncSetAttribute((const void*)gemm_h<7,false,false,true>,
                         cudaFuncAttributeMaxDynamicSharedMemorySize, SM_FF);
    cudaFuncSetAttribute((const void*)gemm_h<7,false,true,false>,
                         cudaFuncAttributeMaxDynamicSharedMemorySize, SM_FT);
    cudaFuncSetAttribute((const void*)gemm_h<8,false,false,true>,
                         cudaFuncAttributeMaxDynamicSharedMemorySize, SM_FF);
    cudaFuncSetAttribute((const void*)gemm_h<8,true,false,true>,
                         cudaFuncAttributeMaxDynamicSharedMemorySize, SM_TF);
    cudaFuncSetAttribute((const void*)gemm_h<13,false,false,false>,
                         cudaFuncAttributeMaxDynamicSharedMemorySize, SM_FF);

    // 1. emb -> fp16 (padded)
    conv2h_k<<<cdiv((long)VOC * EP, 256), 256>>>(emb, pembh, VOC, EP, VOC, Esz);
    // 2. all weights in one kernel
    long wtot = (long)EP * NCAT + 2 * Hsz * Hsz + 2 * Hsz * Hsz + NCAT;
    convw_k<<<cdiv(wtot, 256), 256>>>(W1a, W1c, W2a, W2c, W1g, b1a);
    // 3. masks + tok + bmax + vcat zero
    mask_k<<<cdiv(2 * BL, 256), 256>>>(s1, s2, len1, len2);

    // 4. fused vocab GEMM: [attendL1(relu,b1a) | e@W1cT | e@W1cB]  (N=640, K=EP)
    gemm_h<10,false,false,true><<<dim3(5, MV, 1), 256, SM_FF>>>(
        pembh, 0, EP, nullptr, pWcat, 0, NCAT, nullptr, pb1acat, nullptr, 0,
        nullptr, nullptr, 0, pvcb, 0, NCAT, VOC, NCAT, EP, Hsz, nullptr, nullptr);
    // 5. attend L2: hv = relu(vcb[:, :200] @ W2a + b2a)   (K=200)
    gemm_h<7,false,false,true><<<dim3(2, MV, 1), 256, SM_FF>>>(
        pvcb, 0, NCAT, nullptr, pW2a, 0, Hsz, nullptr, b2a, nullptr, 0,
        nullptr, nullptr, 0, phvh, 0, Hsz, VOC, Hsz, Hsz, RALL, nullptr, nullptr);

    // 6. scores[b] = hv[s1] @ hv[s2]^T  (K=200; epilogue batch-max)
    gemm_h<7,false,true,false><<<dim3(2, 2, Bsz), 256, SM_FT>>>(
        phvh, 0, Hsz, s1, phvh, 0, Hsz, s2, nullptr, nullptr, 0,
        nullptr, nullptr, 0, psc, LL, Lsz, Lsz, Lsz, Hsz, 0, pbmx, nullptr);

    // 7. fused softmax -> fp16 ean / ebn
    sums_k<<<Bsz, 1024>>>();

    // 8. compare hidden via pushed-through W1c_bottom (K=256)
    gemm_h<8,false,false,true><<<dim3(2, 2, Bsz), 256, SM_FF>>>(
        pebnh, LL, Lsz, nullptr, pvcb + 400, 0, NCAT, s2, b1c, nullptr, 0,
        pvcb + 200, ptok, NCAT, pthh, (long)Lsz * Hsz, Hsz,
        Lsz, Hsz, Lsz, RALL, nullptr, nullptr);
    gemm_h<8,true,false,true><<<dim3(2, 2, Bsz), 256, SM_TF>>>(
        peanh, LL, Lsz, nullptr, pvcb + 400, 0, NCAT, s1, b1c, nullptr, 0,
        pvcb + 200, ptok + BL, NCAT, pthh + BL * Hsz, (long)Lsz * Hsz, Hsz,
        Lsz, Hsz, Lsz, RALL, nullptr, nullptr);

    // 9. compare L2 with FUSED masked column-sum -> vcat accumulator (K=200)
    gemm_h<7,false,false,true><<<dim3(2, M2 / 128, 1), 256, SM_FF>>>(
        pthh, 0, Hsz, nullptr, pW2c, 0, Hsz, nullptr, b2c, pmask, 0,
        nullptr, nullptr, 0, nullptr, 0, Hsz, M2, Hsz, Hsz, RALL, nullptr, pvcatf);

    // 10. vcat fp32 -> fp16 ; aggregate head (K=400)
    vconv_k<<<cdiv(Bsz * 2 * Hsz, 256), 256>>>();
    gemm_h<13,false,false,false><<<dim3(2, 4, 1), 256, SM_FF>>>(
        pvch, 0, 2 * Hsz, nullptr, pW1g, 0, Hsz, nullptr, b1g, nullptr, 0,
        nullptr, nullptr, 0, pu, 0, Hsz, Bsz, Hsz, 2 * Hsz, RALL, nullptr, nullptr);
    final_k<<<Bsz, 64>>>(W2g, b2g, out);
}

// round 13
// speedup vs baseline: 12.2998x; 1.0771x over previous
#include <cuda_runtime.h>
#include <cuda_fp16.h>
#include <cstdint>

// Problem constants
#define Bsz 512
#define Lsz 256
#define Esz 300
#define EP  304              // padded E (16B-aligned fp16 rows)
#define Hsz 200
#define NCAT 640             // packed vocab-GEMM width: [W1a | W1cT | W1cB | pad]
#define VOC 50000
constexpr long BL  = (long)Bsz * Lsz;      // 131072
constexpr long LL  = (long)Lsz * Lsz;      // 65536
constexpr long BLL = BL * Lsz;             // 33,554,432

// ---------------- device scratch (static, no runtime allocation) -------------
__device__ __half g_embh[(long)VOC * EP];
__device__ __half g_Wcat[EP * NCAT];        // cols 0..199 W1a, 200..399 W1cT, 400..599 W1cB
__device__ __half g_W2a[Hsz * Hsz];
__device__ __half g_W2c[Hsz * Hsz];
__device__ __half g_W1g[2 * Hsz * Hsz];
__device__ float  g_b1acat[NCAT];           // b1a zero-extended to 640
__device__ __half g_vcb[(long)VOC * NCAT];  // vocab: [attendL1relu | e@W1cT | e@W1cB]
__device__ __half g_hvh[(long)VOC * Hsz];   // vocab attend_ff out
__device__ __half g_eanh[BLL];              // normalized alpha weights
__device__ __half g_ebnh[BLL];              // normalized beta weights
__device__ __half g_thh[2 * BL * Hsz];      // compare hidden
__device__ __half g_vch[Bsz * 2 * Hsz];     // vcat fp16
__device__ float  g_vcatf[Bsz * 2 * Hsz];   // vcat fp32 accumulator
__device__ float    g_scores[BLL];
__device__ float    g_mask[2 * BL];
__device__ int      g_tok[2 * BL];
__device__ int      g_len12[2 * Bsz];       // [len1 ; len2]
__device__ unsigned g_bmaxu[Bsz];           // encoded per-batch max
__device__ float    g_u[Bsz * Hsz];

// ---------------- PTX helpers ------------------------------------------------
__device__ __forceinline__ void cp16(uint32_t dst, const void* src, bool pred)
{
    int sz = pred ? 16 : 0;                 // sz=0 -> 16B zero-fill
    asm volatile("cp.async.cg.shared.global [%0], [%1], 16, %2;"
                 :: "r"(dst), "l"(src), "r"(sz));
}
__device__ __forceinline__ void cp_commit() { asm volatile("cp.async.commit_group;"); }
template <int N>
__device__ __forceinline__ void cp_wait() { asm volatile("cp.async.wait_group %0;" :: "n"(N)); }

__device__ __forceinline__ void ldsm4(uint32_t* r, uint32_t a)
{
    asm volatile("ldmatrix.sync.aligned.m8n8.x4.shared.b16 {%0,%1,%2,%3}, [%4];"
                 : "=r"(r[0]), "=r"(r[1]), "=r"(r[2]), "=r"(r[3]) : "r"(a));
}
__device__ __forceinline__ void ldsm4t(uint32_t* r, uint32_t a)
{
    asm volatile("ldmatrix.sync.aligned.m8n8.x4.trans.shared.b16 {%0,%1,%2,%3}, [%4];"
                 : "=r"(r[0]), "=r"(r[1]), "=r"(r[2]), "=r"(r[3]) : "r"(a));
}
__device__ __forceinline__ void mma16816(float c[4], const uint32_t a[4], const uint32_t* b)
{
    asm volatile(
        "mma.sync.aligned.m16n8k16.row.col.f32.f16.f16.f32 "
        "{%0,%1,%2,%3}, {%4,%5,%6,%7}, {%8,%9}, {%0,%1,%2,%3};"
        : "+f"(c[0]), "+f"(c[1]), "+f"(c[2]), "+f"(c[3])
        : "r"(a[0]), "r"(a[1]), "r"(a[2]), "r"(a[3]), "r"(b[0]), "r"(b[1]));
}

// ordered-uint encoding of float for atomicMax (monotone)
__device__ __forceinline__ unsigned fenc(float f)
{
    unsigned u = __float_as_uint(f);
    return (u & 0x80000000u) ? ~u : (u | 0x80000000u);
}
__device__ __forceinline__ float fdec(unsigned e)
{
    return (e & 0x80000000u) ? __uint_as_float(e & 0x7FFFFFFFu)
                             : __uint_as_float(~e);
}

// ---------------- 128x128x32 fp16 tensor GEMM, 4-stage cp.async + LDSM -------
// KT = number of 32-wide k-tiles (compile-time -> fully unrolled mainloop).
// C[bz][m,n] = epi( sum_k A(m,k) * B(k,n) ), fp32 accumulate.
// TA: A[m,k]=A[k*lda+m]; TB: B[k,n]=B[n*ldb+k].
// iA (only !TA): source row of A-row m is iA[bz*256+m] (caller passes sA=0).
// iB: source row of B's leading dim (k if !TB, n if TB) is iB[bz*256+row].
// lenRow/lenCol: masked-block skipping. seg = bz + (m0>>8) (resp n0).
//   If lenCol==null: skip block iff (m0&255) >= lenRow[seg]   (output is
//   mask-multiplied downstream, so skipped blocks are "don't care").
//   If lenCol!=null: skip iff BOTH row-block and col-block are masked
//   (scores tile feeding only masked ean/ebn entries).
// epilogue: v = acc (+ Cin[iC[bz*256+m], n] stride ldcin) (+ bias[n]);
//           relu iff n < nrelu; * rs[bz*sRS+m];
//           vacc: fused column-sum -> atomicAdd, no C store;
//           bmaxu: per-batch atomicMax of raw acc (exact tiles only).
template <int KT, bool TA, bool TB, bool OUTH>
__global__ __launch_bounds__(256, 2)
void gemm_h(const __half* __restrict__ A, long sA, int lda, const int* __restrict__ iA,
            const __half* __restrict__ Bw, long sB, int ldb, const int* __restrict__ iB,
            const float* __restrict__ bias,
            const float* __restrict__ rs, int sRS,
            const __half* __restrict__ Cin, const int* __restrict__ iC, int ldcin,
            void* __restrict__ Cv, long sC, int ldc,
            int M, int N, int K, int nrelu,
            unsigned* bmaxu, float* vacc,
            const int* __restrict__ lenRow, const int* __restrict__ lenCol)
{
    constexpr int A_SZ = TA ? 32 * 136 : 128 * 40;   // halfs per stage
    constexpr int B_SZ = TB ? 128 * 40 : 32 * 136;
    extern __shared__ __half smem_[];
    __half* Asm = smem_;                  // 4 stages of A
    __half* Bsm = smem_ + 4 * A_SZ;       // 4 stages of B

    int bz = blockIdx.z;
    int m0 = blockIdx.y * 128, n0 = blockIdx.x * 128;

    // ---- masked-block skip
    if (lenRow) {
        bool rskip = (m0 & 255) >= lenRow[bz + (m0 >> 8)];
        bool cskip = lenCol ? ((n0 & 255) >= lenCol[bz + (n0 >> 8)]) : true;
        if (rskip && cskip) return;
    }

    const __half* Ab = A + (long)bz * sA;
    const __half* Bb = Bw + (long)bz * sB;
    int tid = threadIdx.x;
    int wid = tid >> 5, lane = tid & 31;
    int wm = wid >> 2, wn = wid & 3;
    int g = lane >> 2, tig = lane & 3;

    uint32_t abase = (uint32_t)__cvta_generic_to_shared(Asm);
    uint32_t bbase = (uint32_t)__cvta_generic_to_shared(Bsm);

    float c[4][4][4];
#pragma unroll
    for (int i = 0; i < 4; i++)
#pragma unroll
        for (int j = 0; j < 4; j++)
#pragma unroll
            for (int q = 0; q < 4; q++) c[i][j][q] = 0.f;

    auto load_stage = [&](int st, int k0) {
#pragma unroll
        for (int it = 0; it < 2; it++) {
            int id = tid + it * 256;
            if (!TA) {
                int row = id >> 2, c8 = (id & 3) * 8;
                bool p = (m0 + row < M) && (k0 + c8 < K);
                int rg = iA ? (p ? iA[bz * 256 + m0 + row] : 0) : (m0 + row);
                cp16(abase + (uint32_t)(st * A_SZ + row * 40 + c8) * 2,
                     Ab + (long)rg * lda + (k0 + c8), p);
            } else {
                int kr = id >> 4, c8 = (id & 15) * 8;
                bool p = (k0 + kr < K) && (m0 + c8 < M);
                cp16(abase + (uint32_t)(st * A_SZ + kr * 136 + c8) * 2,
                     Ab + (long)(k0 + kr) * lda + (m0 + c8), p);
            }
            if (!TB) {
                int kr = id >> 4, c8 = (id & 15) * 8;
                bool p = (k0 + kr < K) && (n0 + c8 < N);
                int rg = iB ? ((k0 + kr < K) ? iB[bz * 256 + k0 + kr] : 0) : (k0 + kr);
                cp16(bbase + (uint32_t)(st * B_SZ + kr * 136 + c8) * 2,
                     Bb + (long)rg * ldb + (n0 + c8), p);
            } else {
                int row = id >> 2, c8 = (id & 3) * 8;
                bool p = (n0 + row < N) && (k0 + c8 < K);
                int rg = iB ? ((n0 + row < N) ? iB[bz * 256 + n0 + row] : 0) : (n0 + row);
                cp16(bbase + (uint32_t)(st * B_SZ + row * 40 + c8) * 2,
                     Bb + (long)rg * ldb + (k0 + c8), p);
            }
        }
        cp_commit();
    };

    load_stage(0, 0);
    if (KT > 1) load_stage(1, 32);
    if (KT > 2) load_stage(2, 64);

#pragma unroll
    for (int kt = 0; kt < KT; kt++) {
        if (kt < KT - 2)       cp_wait<2>();
        else if (kt == KT - 2) cp_wait<1>();
        else                   cp_wait<0>();
        __syncthreads();    // single barrier: stage (kt+3)&3 == (kt-1)&3 is free
        int st = kt & 3;
        uint32_t ab2 = abase + (uint32_t)(st * A_SZ) * 2;
        uint32_t bb2 = bbase + (uint32_t)(st * B_SZ) * 2;

#pragma unroll
        for (int s2 = 0; s2 < 2; s2++) {
            int ks = s2 * 16;
            uint32_t af[4][4], bq[2][4];
#pragma unroll
            for (int mt = 0; mt < 4; mt++) {
                if (!TA) {
                    int m = wm * 64 + mt * 16 + (lane & 15);
                    int kc = ks + ((lane >> 4) << 3);
                    ldsm4(af[mt], ab2 + (uint32_t)(m * 40 + kc) * 2);
                } else {
                    int kr = ks + (lane & 7) + ((lane >> 4) << 3);
                    int mc = wm * 64 + mt * 16 + (((lane >> 3) & 1) << 3);
                    ldsm4t(af[mt], ab2 + (uint32_t)(kr * 136 + mc) * 2);
                }
            }
            // B: two ldsm.x4 cover all four n-tiles (lanes 16-31 -> second tile)
#pragma unroll
            for (int np = 0; np < 2; np++) {
                if (TB) {
                    int n = wn * 32 + np * 16 + ((lane >> 4) << 3) + (lane & 7);
                    int kc = ks + (((lane >> 3) & 1) << 3);
                    ldsm4(bq[np], bb2 + (uint32_t)(n * 40 + kc) * 2);
                } else {
                    int kr = ks + (lane & 7) + (((lane >> 3) & 1) << 3);
                    int nc = wn * 32 + np * 16 + (((lane >> 4) & 1) << 3);
                    ldsm4t(bq[np], bb2 + (uint32_t)(kr * 136 + nc) * 2);
                }
            }
#pragma unroll
            for (int mt = 0; mt < 4; mt++)
#pragma unroll
                for (int nt = 0; nt < 4; nt++)
                    mma16816(c[mt][nt], af[mt], &bq[nt >> 1][(nt & 1) * 2]);
        }
        if (kt + 3 < KT) load_stage((kt + 3) & 3, (kt + 3) * 32);
    }

    // ---- fused column-sum epilogue (compare L2): no C store
    if (vacc) {
        int b2v = m0 >> 8;   // 128-row blocks never straddle a 256-row segment
        int voff = (b2v < Bsz) ? b2v * (2 * Hsz) : (b2v - Bsz) * (2 * Hsz) + Hsz;
#pragma unroll
        for (int nt = 0; nt < 4; nt++) {
            int n = n0 + wn * 32 + nt * 8 + tig * 2;
            float s0 = 0.f, s1 = 0.f;
            if (n < N) {
#pragma unroll
                for (int mt = 0; mt < 4; mt++)
#pragma unroll
                    for (int r = 0; r < 2; r++) {
                        int m = m0 + wm * 64 + mt * 16 + g + r * 8;
                        float rsv = rs ? rs[(long)bz * sRS + m] : 1.f;
                        float v0 = c[mt][nt][r * 2 + 0];
                        float v1 = c[mt][nt][r * 2 + 1];
                        if (bias) { v0 += bias[n]; v1 += bias[n + 1]; }
                        if (n < nrelu) { v0 = fmaxf(v0, 0.f); v1 = fmaxf(v1, 0.f); }
                        s0 += v0 * rsv; s1 += v1 * rsv;
                    }
            }
            s0 += __shfl_down_sync(~0u, s0, 16);
            s0 += __shfl_down_sync(~0u, s0, 8);
            s0 += __shfl_down_sync(~0u, s0, 4);
            s1 += __shfl_down_sync(~0u, s1, 16);
            s1 += __shfl_down_sync(~0u, s1, 8);
            s1 += __shfl_down_sync(~0u, s1, 4);
            if (g == 0 && n < N) {
                atomicAdd(&vacc[voff + n], s0);
                atomicAdd(&vacc[voff + n + 1], s1);
            }
        }
        return;
    }

    __half* Ch = (__half*)Cv + (long)bz * sC;
    float*  Cf = (float*)Cv + (long)bz * sC;
#pragma unroll
    for (int mt = 0; mt < 4; mt++) {
#pragma unroll
        for (int r = 0; r < 2; r++) {
            int m = m0 + wm * 64 + mt * 16 + g + r * 8;
            if (m >= M) continue;
            float rsv = rs ? rs[(long)bz * sRS + m] : 1.f;
            int crow = 0;
            if (Cin) crow = iC ? iC[bz * 256 + m] : m;
#pragma unroll
            for (int nt = 0; nt < 4; nt++) {
                int n = n0 + wn * 32 + nt * 8 + tig * 2;
                if (n < N) {
                    float v0 = c[mt][nt][r * 2 + 0];
                    float v1 = c[mt][nt][r * 2 + 1];
                    if (Cin) {
                        v0 += __half2float(Cin[(long)crow * ldcin + n]);
                        v1 += __half2float(Cin[(long)crow * ldcin + n + 1]);
                    }
                    if (bias) { v0 += bias[n]; v1 += bias[n + 1]; }
                    if (n < nrelu) { v0 = fmaxf(v0, 0.f); v1 = fmaxf(v1, 0.f); }
                    v0 *= rsv; v1 *= rsv;
                    if (OUTH)
                        *(__half2*)(Ch + (long)m * ldc + n) = __floats2half2_rn(v0, v1);
                    else {
                        Cf[(long)m * ldc + n] = v0;
                        Cf[(long)m * ldc + n + 1] = v1;
                    }
                }
            }
        }
    }

    if (bmaxu) {   // per-batch max of this block's outputs (exact tiles only)
        float mx = -1e30f;
#pragma unroll
        for (int mt = 0; mt < 4; mt++)
#pragma unroll
            for (int nt = 0; nt < 4; nt++)
#pragma unroll
                for (int q = 0; q < 4; q++) mx = fmaxf(mx, c[mt][nt][q]);
#pragma unroll
        for (int o = 16; o; o >>= 1) mx = fmaxf(mx, __shfl_xor_sync(~0u, mx, o));
        if (lane == 0) atomicMax(&bmaxu[bz], fenc(mx));
    }
}

// dynamic smem bytes per instantiation (4 stages)
constexpr int smem_bytes(bool TA, bool TB)
{
    int a = TA ? 32 * 136 : 128 * 40;
    int b = TB ? 128 * 40 : 32 * 136;
    return 4 * (a + b) * 2;
}

// ---------------- helper kernels ---------------------------------------------
__global__ void conv2h_k(const float* __restrict__ src, __half* __restrict__ dst,
                         int rows, int cols, int srcR, int srcC)
{
    long idx = (long)blockIdx.x * blockDim.x + threadIdx.x;
    if (idx >= (long)rows * cols) return;
    int r = (int)(idx / cols), c = (int)(idx % cols);
    float v = (r < srcR && c < srcC) ? src[(long)r * srcC + c] : 0.f;
    dst[idx] = __float2half_rn(v);
}

// all weight conversions in ONE kernel (Wcat packing + W2a/W2c/W1g + biascat)
__global__ void convw_k(const float* __restrict__ W1a, const float* __restrict__ W1c,
                        const float* __restrict__ W2a, const float* __restrict__ W2c,
                        const float* __restrict__ W1g, const float* __restrict__ b1a)
{
    long idx = (long)blockIdx.x * blockDim.x + threadIdx.x;
    const long NW = (long)EP * NCAT;
    if (idx < NW) {
        int r = (int)(idx / NCAT), cc = (int)(idx % NCAT);
        float v = 0.f;
        if (r < Esz) {
            if (cc < 200)      v = W1a[(long)r * Hsz + cc];
            else if (cc < 400) v = W1c[(long)r * Hsz + (cc - 200)];
            else if (cc < 600) v = W1c[(long)(Esz + r) * Hsz + (cc - 400)];
        }
        g_Wcat[idx] = __float2half_rn(v);
        return;
    }
    idx -= NW;
    if (idx < Hsz * Hsz) { g_W2a[idx] = __float2half_rn(W2a[idx]); return; }
    idx -= Hsz * Hsz;
    if (idx < Hsz * Hsz) { g_W2c[idx] = __float2half_rn(W2c[idx]); return; }
    idx -= Hsz * Hsz;
    if (idx < 2 * Hsz * Hsz) { g_W1g[idx] = __float2half_rn(W1g[idx]); return; }
    idx -= 2 * Hsz * Hsz;
    if (idx < NCAT) { g_b1acat[idx] = (idx < Hsz) ? b1a[idx] : 0.f; return; }
}

// masks + token index concat + lens + bmax init + vcat accumulator zero
__global__ void mask_k(const int* __restrict__ s1, const int* __restrict__ s2,
                       const int* __restrict__ len1, const int* __restrict__ len2)
{
    long idx = (long)blockIdx.x * blockDim.x + threadIdx.x;
    if (idx >= 2 * BL) return;
    int seq = (int)(idx / BL);
    long r = idx % BL;
    int b = (int)(r / Lsz), l = (int)(r % Lsz);
    int len = seq ? len2[b] : len1[b];
    g_mask[idx] = (l < len) ? 1.f : 0.f;
    g_tok[idx] = seq ? s2[r] : s1[r];
    if (idx < Bsz) g_bmaxu[idx] = 0u;
    if (idx < 2 * Bsz) g_len12[idx] = (idx < Bsz) ? len1[idx] : len2[idx - Bsz];
    if (idx < Bsz * 2 * Hsz) g_vcatf[idx] = 0.f;
}

// Fused softmax (shift-cancelled): p = exp(e - Mb);
// colsum(p*m1i) -> rsa; rowsum(p*m2j) -> rsb; emit fp16 ean/ebn normalized.
__global__ void sums_k()
{
    __shared__ float rowacc[256];
    __shared__ float colsm[1024];
    __shared__ float rsa_s[256];
    __shared__ float rsb_s[256];
    int b = blockIdx.x;
    int tid = threadIdx.x;
    int j = tid & 255, s = tid >> 8, lane = tid & 31;
    if (tid < 256) rowacc[tid] = 0.f;
    __syncthreads();

    long base = (long)b * LL;
    float Mb  = fdec(g_bmaxu[b]);
    float m2j = g_mask[BL + (long)b * Lsz + j];
    float da = 0.f;
    for (int t = 0; t < 64; t++) {
        int i = s * 64 + t;
        float p = __expf(g_scores[base + (long)i * Lsz + j] - Mb);
        da += p * g_mask[(long)b * Lsz + i];
        float v = p * m2j;
#pragma unroll
        for (int o = 16; o; o >>= 1) v += __shfl_xor_sync(~0u, v, o);
        if (lane == 0) atomicAdd(&rowacc[i], v);
    }
    colsm[tid] = da;
    __syncthreads();
    if (s == 0)
        rsa_s[j] = m2j / (colsm[j] + colsm[j + 256] + colsm[j + 512] + colsm[j + 768]);
    if (tid < 256)
        rsb_s[tid] = g_mask[(long)b * Lsz + tid] / rowacc[tid];
    __syncthreads();

    float rsaj = rsa_s[j];
    for (int t = 0; t < 64; t++) {
        int i = s * 64 + t;
        long idx = base + (long)i * Lsz + j;
        float p = __expf(g_scores[idx] - Mb);
        g_eanh[idx] = __float2half_rn(p * g_mask[(long)b * Lsz + i] * rsaj);
        g_ebnh[idx] = __float2half_rn(p * m2j * rsb_s[i]);
    }
}

__global__ void vconv_k()    // fp32 vcat accumulator -> fp16
{
    int idx = blockIdx.x * blockDim.x + threadIdx.x;
    if (idx < Bsz * 2 * Hsz) g_vch[idx] = __float2half_rn(g_vcatf[idx]);
}

__global__ void final_k(const float* __restrict__ W2g,
                        const float* __restrict__ b2g, float* __restrict__ out)
{
    int b = blockIdx.x;
    int o = threadIdx.x >> 5;
    int lane = threadIdx.x & 31;
    const float* u = g_u + (long)b * Hsz;
    float s = 0.f;
    for (int h = lane; h < Hsz; h += 32) s += u[h] * W2g[h * 2 + o];
#pragma unroll
    for (int off = 16; off; off >>= 1) s += __shfl_xor_sync(~0u, s, off);
    if (lane == 0) out[b * 2 + o] = s + b2g[o];
}

// ---------------- launch -----------------------------------------------------
extern "C" void kernel_launch(void* const* d_in, const int* in_sizes, int n_in,
                              void* d_out, int out_size)
{
    const float* emb = (const float*)d_in[0];
    const float* W1a = (const float*)d_in[1];
    const float* b1a = (const float*)d_in[2];
    const float* W2a = (const float*)d_in[3];
    const float* b2a = (const float*)d_in[4];
    const float* W1c = (const float*)d_in[5];
    const float* b1c = (const float*)d_in[6];
    const float* W2c = (const float*)d_in[7];
    const float* b2c = (const float*)d_in[8];
    const float* W1g = (const float*)d_in[9];
    const float* b1g = (const float*)d_in[10];
    const float* W2g = (const float*)d_in[11];
    const float* b2g = (const float*)d_in[12];
    const int* s1   = (const int*)d_in[13];
    const int* s2   = (const int*)d_in[14];
    const int* len1 = (const int*)d_in[15];
    const int* len2 = (const int*)d_in[16];
    float* out = (float*)d_out;

    __half *pembh, *pWcat, *pW2a, *pW2c, *pW1g, *pvcb, *phvh;
    __half *peanh, *pebnh, *pthh, *pvch;
    float *pmask, *pu, *psc, *pb1acat, *pvcatf;
    int *ptok, *plen;
    unsigned *pbmx;
    cudaGetSymbolAddress((void**)&pembh,  g_embh);
    cudaGetSymbolAddress((void**)&pWcat,  g_Wcat);
    cudaGetSymbolAddress((void**)&pW2a,   g_W2a);
    cudaGetSymbolAddress((void**)&pW2c,   g_W2c);
    cudaGetSymbolAddress((void**)&pW1g,   g_W1g);
    cudaGetSymbolAddress((void**)&pvcb,   g_vcb);
    cudaGetSymbolAddress((void**)&phvh,   g_hvh);
    cudaGetSymbolAddress((void**)&peanh,  g_eanh);
    cudaGetSymbolAddress((void**)&pebnh,  g_ebnh);
    cudaGetSymbolAddress((void**)&pthh,   g_thh);
    cudaGetSymbolAddress((void**)&pvch,   g_vch);
    cudaGetSymbolAddress((void**)&pmask,  g_mask);
    cudaGetSymbolAddress((void**)&pu,     g_u);
    cudaGetSymbolAddress((void**)&psc,    g_scores);
    cudaGetSymbolAddress((void**)&pb1acat,g_b1acat);
    cudaGetSymbolAddress((void**)&pvcatf, g_vcatf);
    cudaGetSymbolAddress((void**)&ptok,   g_tok);
    cudaGetSymbolAddress((void**)&plen,   g_len12);
    cudaGetSymbolAddress((void**)&pbmx,   g_bmaxu);

    const int M2 = (int)(2 * BL);          // 262144
    const unsigned MV = (VOC + 127) / 128; // 391
    const int RALL = 1 << 30;              // relu on all columns
    auto cdiv = [](long n, long d) { return (unsigned)((n + d - 1) / d); };

    // KT per call site: EP=304 -> 10, K=200 -> 7, K=256 -> 8, K=400 -> 13
    constexpr int SM_FF = smem_bytes(false, false);   // 75776
    constexpr int SM_FT = smem_bytes(false, true);    // 81920
    constexpr int SM_TF = smem_bytes(true,  false);   // 75776
    cudaFuncSetAttribute((const void*)gemm_h<10,false,false,true>,
                         cudaFuncAttributeMaxDynamicSharedMemorySize, SM_FF);
    cudaFuncSetAttribute((const void*)gemm_h<7,false,false,true>,
                         cudaFuncAttributeMaxDynamicSharedMemorySize, SM_FF);
    cudaFuncSetAttribute((const void*)gemm_h<7,false,true,false>,
                         cudaFuncAttributeMaxDynamicSharedMemorySize, SM_FT);
    cudaFuncSetAttribute((const void*)gemm_h<8,false,false,true>,
                         cudaFuncAttributeMaxDynamicSharedMemorySize, SM_FF);
    cudaFuncSetAttribute((const void*)gemm_h<8,true,false,true>,
                         cudaFuncAttributeMaxDynamicSharedMemorySize, SM_TF);
    cudaFuncSetAttribute((const void*)gemm_h<13,false,false,false>,
                         cudaFuncAttributeMaxDynamicSharedMemorySize, SM_FF);

    // 1. emb -> fp16 (padded)
    conv2h_k<<<cdiv((long)VOC * EP, 256), 256>>>(emb, pembh, VOC, EP, VOC, Esz);
    // 2. all weights in one kernel
    long wtot = (long)EP * NCAT + 2 * Hsz * Hsz + 2 * Hsz * Hsz + NCAT;
    convw_k<<<cdiv(wtot, 256), 256>>>(W1a, W1c, W2a, W2c, W1g, b1a);
    // 3. masks + tok + lens + bmax + vcat zero
    mask_k<<<cdiv(2 * BL, 256), 256>>>(s1, s2, len1, len2);

    // 4. fused vocab GEMM: [attendL1(relu,b1a) | e@W1cT | e@W1cB]  (N=640, K=EP)
    gemm_h<10,false,false,true><<<dim3(5, MV, 1), 256, SM_FF>>>(
        pembh, 0, EP, nullptr, pWcat, 0, NCAT, nullptr, pb1acat, nullptr, 0,
        nullptr, nullptr, 0, pvcb, 0, NCAT, VOC, NCAT, EP, Hsz,
        nullptr, nullptr, nullptr, nullptr);
    // 5. attend L2: hv = relu(vcb[:, :200] @ W2a + b2a)   (K=200)
    gemm_h<7,false,false,true><<<dim3(2, MV, 1), 256, SM_FF>>>(
        pvcb, 0, NCAT, nullptr, pW2a, 0, Hsz, nullptr, b2a, nullptr, 0,
        nullptr, nullptr, 0, phvh, 0, Hsz, VOC, Hsz, Hsz, RALL,
        nullptr, nullptr, nullptr, nullptr);

    // 6. scores[b] = hv[s1] @ hv[s2]^T (K=200; batch-max; skip both-masked tile)
    gemm_h<7,false,true,false><<<dim3(2, 2, Bsz), 256, SM_FT>>>(
        phvh, 0, Hsz, s1, phvh, 0, Hsz, s2, nullptr, nullptr, 0,
        nullptr, nullptr, 0, psc, LL, Lsz, Lsz, Lsz, Hsz, 0,
        pbmx, nullptr, plen, plen + Bsz);

    // 7. fused softmax -> fp16 ean / ebn
    sums_k<<<Bsz, 1024>>>();

    // 8. compare hidden via pushed-through W1c_bottom (K=256; skip masked rows)
    gemm_h<8,false,false,true><<<dim3(2, 2, Bsz), 256, SM_FF>>>(
        pebnh, LL, Lsz, nullptr, pvcb + 400, 0, NCAT, s2, b1c, nullptr, 0,
        pvcb + 200, ptok, NCAT, pthh, (long)Lsz * Hsz, Hsz,
        Lsz, Hsz, Lsz, RALL, nullptr, nullptr, plen, nullptr);
    gemm_h<8,true,false,true><<<dim3(2, 2, Bsz), 256, SM_TF>>>(
        peanh, LL, Lsz, nullptr, pvcb + 400, 0, NCAT, s1, b1c, nullptr, 0,
        pvcb + 200, ptok + BL, NCAT, pthh + BL * Hsz, (long)Lsz * Hsz, Hsz,
        Lsz, Hsz, Lsz, RALL, nullptr, nullptr, plen + Bsz, nullptr);

    // 9. compare L2 with fused masked column-sum (K=200; skip fully-masked blocks)
    gemm_h<7,false,false,true><<<dim3(2, M2 / 128, 1), 256, SM_FF>>>(
        pthh, 0, Hsz, nullptr, pW2c, 0, Hsz, nullptr, b2c, pmask, 0,
        nullptr, nullptr, 0, nullptr, 0, Hsz, M2, Hsz, Hsz, RALL,
        nullptr, pvcatf, plen, nullptr);

    // 10. vcat fp32 -> fp16 ; aggregate head (K=400)
    vconv_k<<<cdiv(Bsz * 2 * Hsz, 256), 256>>>();
    gemm_h<13,false,false,false><<<dim3(2, 4, 1), 256, SM_FF>>>(
        pvch, 0, 2 * Hsz, nullptr, pW1g, 0, Hsz, nullptr, b1g, nullptr, 0,
        nullptr, nullptr, 0, pu, 0, Hsz, Bsz, Hsz, 2 * Hsz, RALL,
        nullptr, nullptr, nullptr, nullptr);
    final_k<<<Bsz, 64>>>(W2g, b2g, out);
}

// round 14
// speedup vs baseline: 14.0206x; 1.1399x over previous
#include <cuda_runtime.h>
#include <cuda_fp16.h>
#include <cstdint>

// Problem constants
#define Bsz 512
#define Lsz 256
#define Esz 300
#define EP  304              // padded E (16B-aligned fp16 rows)
#define Hsz 200
#define NCAT 640             // packed vocab-GEMM width: [W1a | W1cT | W1cB | pad]
#define VOC 50000
constexpr long BL  = (long)Bsz * Lsz;      // 131072
constexpr long LL  = (long)Lsz * Lsz;      // 65536
constexpr long BLL = BL * Lsz;             // 33,554,432

// ---------------- device scratch (static, no runtime allocation) -------------
__device__ __half g_embh[(long)VOC * EP];
__device__ __half g_Wcat[EP * NCAT];        // cols 0..199 W1a, 200..399 W1cT, 400..599 W1cB
__device__ __half g_W2a[Hsz * Hsz];
__device__ __half g_W2c[Hsz * Hsz];
__device__ __half g_W1g[2 * Hsz * Hsz];
__device__ float  g_b1acat[NCAT];           // b1a zero-extended to 640
__device__ __half g_vcb[(long)VOC * NCAT];  // vocab: [attendL1relu | e@W1cT | e@W1cB]
__device__ __half g_hvh[(long)VOC * Hsz];   // vocab attend_ff out
__device__ __half g_eanh[BLL];              // RAW q = p*mask1[i]   (fp16)
__device__ __half g_ebnh[BLL];              // RAW w = p*mask2[j]   (fp16)
__device__ __half g_thh[2 * BL * Hsz];      // compare hidden
__device__ __half g_vch[Bsz * 2 * Hsz];     // vcat fp16
__device__ float  g_vcatf[Bsz * 2 * Hsz];   // vcat fp32 accumulator
__device__ float    g_scores[BLL];          // zero-init; skipped tiles stay 0
__device__ float    g_mask[2 * BL];
__device__ int      g_tok[2 * BL];
__device__ int      g_len12[2 * Bsz];       // [len1 ; len2]
__device__ unsigned g_bmaxu[Bsz];           // encoded per-batch max
__device__ float    g_rsa[BL];              // mask2[j] / d_alpha_j
__device__ float    g_rsb[BL];              // mask1[i] / d_beta_i
__device__ float    g_u[Bsz * Hsz];

// ---------------- PTX helpers ------------------------------------------------
__device__ __forceinline__ void cp16(uint32_t dst, const void* src, bool pred)
{
    int sz = pred ? 16 : 0;                 // sz=0 -> 16B zero-fill
    asm volatile("cp.async.cg.shared.global [%0], [%1], 16, %2;"
                 :: "r"(dst), "l"(src), "r"(sz));
}
__device__ __forceinline__ void cp_commit() { asm volatile("cp.async.commit_group;"); }
template <int N>
__device__ __forceinline__ void cp_wait() { asm volatile("cp.async.wait_group %0;" :: "n"(N)); }

__device__ __forceinline__ void ldsm4(uint32_t* r, uint32_t a)
{
    asm volatile("ldmatrix.sync.aligned.m8n8.x4.shared.b16 {%0,%1,%2,%3}, [%4];"
                 : "=r"(r[0]), "=r"(r[1]), "=r"(r[2]), "=r"(r[3]) : "r"(a));
}
__device__ __forceinline__ void ldsm4t(uint32_t* r, uint32_t a)
{
    asm volatile("ldmatrix.sync.aligned.m8n8.x4.trans.shared.b16 {%0,%1,%2,%3}, [%4];"
                 : "=r"(r[0]), "=r"(r[1]), "=r"(r[2]), "=r"(r[3]) : "r"(a));
}
__device__ __forceinline__ void mma16816(float c[4], const uint32_t a[4], const uint32_t* b)
{
    asm volatile(
        "mma.sync.aligned.m16n8k16.row.col.f32.f16.f16.f32 "
        "{%0,%1,%2,%3}, {%4,%5,%6,%7}, {%8,%9}, {%0,%1,%2,%3};"
        : "+f"(c[0]), "+f"(c[1]), "+f"(c[2]), "+f"(c[3])
        : "r"(a[0]), "r"(a[1]), "r"(a[2]), "r"(a[3]), "r"(b[0]), "r"(b[1]));
}

// ordered-uint encoding of float for atomicMax (monotone)
__device__ __forceinline__ unsigned fenc(float f)
{
    unsigned u = __float_as_uint(f);
    return (u & 0x80000000u) ? ~u : (u | 0x80000000u);
}
__device__ __forceinline__ float fdec(unsigned e)
{
    return (e & 0x80000000u) ? __uint_as_float(e & 0x7FFFFFFFu)
                             : __uint_as_float(~e);
}

// ---------------- 128x128x32 fp16 tensor GEMM, 4-stage cp.async + LDSM -------
// KT = number of 32-wide k-tiles (compile-time -> fully unrolled mainloop).
// C[bz][m,n] = epi( sum_k A(m,k) * B(k,n) ), fp32 accumulate.
// TA: A[m,k]=A[k*lda+m]; TB: B[k,n]=B[n*ldb+k].
// iA (only !TA): source row of A-row m is iA[bz*256+m] (caller passes sA=0).
// iB: source row of B's leading dim (k if !TB, n if TB) is iB[bz*256+row].
// Masked-block skip: skip iff rskip OR cskip (each consumer multiplies the
//   skipped output region by a zero mask; scores buffer stays 0 there).
// klimP: per-batch K limit (elements): k-tiles with kt*32 >= klimP[bz] carry
//   all-zero A columns -> skip LDSM+MMA only (loads stay uniform).
// epilogue: rsPre ? (acc*rs then +Cin+bias, relu)
//                 : (+Cin+bias, relu, *rs);   relu iff n < nrelu;
//           vacc: fused column-sum -> atomicAdd, no C store;
//           bmaxu: per-batch atomicMax of raw acc (exact tiles only).
template <int KT, bool TA, bool TB, bool OUTH>
__global__ __launch_bounds__(256, 2)
void gemm_h(const __half* __restrict__ A, long sA, int lda, const int* __restrict__ iA,
            const __half* __restrict__ Bw, long sB, int ldb, const int* __restrict__ iB,
            const float* __restrict__ bias,
            const float* __restrict__ rs, int sRS, int rsPre,
            const __half* __restrict__ Cin, const int* __restrict__ iC, int ldcin,
            void* __restrict__ Cv, long sC, int ldc,
            int M, int N, int K, int nrelu,
            unsigned* bmaxu, float* vacc,
            const int* __restrict__ lenRow, const int* __restrict__ lenCol,
            const int* __restrict__ klimP)
{
    constexpr int A_SZ = TA ? 32 * 136 : 128 * 40;   // halfs per stage
    constexpr int B_SZ = TB ? 128 * 40 : 32 * 136;
    extern __shared__ __half smem_[];
    __half* Asm = smem_;                  // 4 stages of A
    __half* Bsm = smem_ + 4 * A_SZ;       // 4 stages of B

    int bz = blockIdx.z;
    int m0 = blockIdx.y * 128, n0 = blockIdx.x * 128;

    // ---- masked-block skip (OR semantics)
    if (lenRow) {
        bool rskip = (m0 & 255) >= lenRow[bz + (m0 >> 8)];
        bool cskip = lenCol && ((n0 & 255) >= lenCol[bz + (n0 >> 8)]);
        if (rskip || cskip) return;
    }
    int kl = klimP ? ((klimP[bz] + 31) >> 5) : KT;   // active k-tiles

    const __half* Ab = A + (long)bz * sA;
    const __half* Bb = Bw + (long)bz * sB;
    int tid = threadIdx.x;
    int wid = tid >> 5, lane = tid & 31;
    int wm = wid >> 2, wn = wid & 3;
    int g = lane >> 2, tig = lane & 3;

    uint32_t abase = (uint32_t)__cvta_generic_to_shared(Asm);
    uint32_t bbase = (uint32_t)__cvta_generic_to_shared(Bsm);

    float c[4][4][4];
#pragma unroll
    for (int i = 0; i < 4; i++)
#pragma unroll
        for (int j = 0; j < 4; j++)
#pragma unroll
            for (int q = 0; q < 4; q++) c[i][j][q] = 0.f;

    auto load_stage = [&](int st, int k0) {
#pragma unroll
        for (int it = 0; it < 2; it++) {
            int id = tid + it * 256;
            if (!TA) {
                int row = id >> 2, c8 = (id & 3) * 8;
                bool p = (m0 + row < M) && (k0 + c8 < K);
                int rg = iA ? (p ? iA[bz * 256 + m0 + row] : 0) : (m0 + row);
                cp16(abase + (uint32_t)(st * A_SZ + row * 40 + c8) * 2,
                     Ab + (long)rg * lda + (k0 + c8), p);
            } else {
                int kr = id >> 4, c8 = (id & 15) * 8;
                bool p = (k0 + kr < K) && (m0 + c8 < M);
                cp16(abase + (uint32_t)(st * A_SZ + kr * 136 + c8) * 2,
                     Ab + (long)(k0 + kr) * lda + (m0 + c8), p);
            }
            if (!TB) {
                int kr = id >> 4, c8 = (id & 15) * 8;
                bool p = (k0 + kr < K) && (n0 + c8 < N);
                int rg = iB ? ((k0 + kr < K) ? iB[bz * 256 + k0 + kr] : 0) : (k0 + kr);
                cp16(bbase + (uint32_t)(st * B_SZ + kr * 136 + c8) * 2,
                     Bb + (long)rg * ldb + (n0 + c8), p);
            } else {
                int row = id >> 2, c8 = (id & 3) * 8;
                bool p = (n0 + row < N) && (k0 + c8 < K);
                int rg = iB ? ((n0 + row < N) ? iB[bz * 256 + n0 + row] : 0) : (n0 + row);
                cp16(bbase + (uint32_t)(st * B_SZ + row * 40 + c8) * 2,
                     Bb + (long)rg * ldb + (k0 + c8), p);
            }
        }
        cp_commit();
    };

    load_stage(0, 0);
    if (KT > 1) load_stage(1, 32);
    if (KT > 2) load_stage(2, 64);

#pragma unroll
    for (int kt = 0; kt < KT; kt++) {
        if (kt < KT - 2)       cp_wait<2>();
        else if (kt == KT - 2) cp_wait<1>();
        else                   cp_wait<0>();
        __syncthreads();    // single barrier: stage (kt+3)&3 == (kt-1)&3 is free
        if (kt < kl) {      // block-uniform: skip dead k-tiles' compute only
            int st = kt & 3;
            uint32_t ab2 = abase + (uint32_t)(st * A_SZ) * 2;
            uint32_t bb2 = bbase + (uint32_t)(st * B_SZ) * 2;

#pragma unroll
            for (int s2 = 0; s2 < 2; s2++) {
                int ks = s2 * 16;
                uint32_t af[4][4], bq[2][4];
#pragma unroll
                for (int mt = 0; mt < 4; mt++) {
                    if (!TA) {
                        int m = wm * 64 + mt * 16 + (lane & 15);
                        int kc = ks + ((lane >> 4) << 3);
                        ldsm4(af[mt], ab2 + (uint32_t)(m * 40 + kc) * 2);
                    } else {
                        int kr = ks + (lane & 7) + ((lane >> 4) << 3);
                        int mc = wm * 64 + mt * 16 + (((lane >> 3) & 1) << 3);
                        ldsm4t(af[mt], ab2 + (uint32_t)(kr * 136 + mc) * 2);
                    }
                }
#pragma unroll
                for (int np = 0; np < 2; np++) {
                    if (TB) {
                        int n = wn * 32 + np * 16 + ((lane >> 4) << 3) + (lane & 7);
                        int kc = ks + (((lane >> 3) & 1) << 3);
                        ldsm4(bq[np], bb2 + (uint32_t)(n * 40 + kc) * 2);
                    } else {
                        int kr = ks + (lane & 7) + (((lane >> 3) & 1) << 3);
                        int nc = wn * 32 + np * 16 + (((lane >> 4) & 1) << 3);
                        ldsm4t(bq[np], bb2 + (uint32_t)(kr * 136 + nc) * 2);
                    }
                }
#pragma unroll
                for (int mt = 0; mt < 4; mt++)
#pragma unroll
                    for (int nt = 0; nt < 4; nt++)
                        mma16816(c[mt][nt], af[mt], &bq[nt >> 1][(nt & 1) * 2]);
            }
        }
        if (kt + 3 < KT) load_stage((kt + 3) & 3, (kt + 3) * 32);
    }

    // ---- fused column-sum epilogue (compare L2): no C store
    if (vacc) {
        int b2v = m0 >> 8;   // 128-row blocks never straddle a 256-row segment
        int voff = (b2v < Bsz) ? b2v * (2 * Hsz) : (b2v - Bsz) * (2 * Hsz) + Hsz;
#pragma unroll
        for (int nt = 0; nt < 4; nt++) {
            int n = n0 + wn * 32 + nt * 8 + tig * 2;
            float s0 = 0.f, s1 = 0.f;
            if (n < N) {
#pragma unroll
                for (int mt = 0; mt < 4; mt++)
#pragma unroll
                    for (int r = 0; r < 2; r++) {
                        int m = m0 + wm * 64 + mt * 16 + g + r * 8;
                        float rsv = rs ? rs[(long)bz * sRS + m] : 1.f;
                        float v0 = c[mt][nt][r * 2 + 0];
                        float v1 = c[mt][nt][r * 2 + 1];
                        if (bias) { v0 += bias[n]; v1 += bias[n + 1]; }
                        if (n < nrelu) { v0 = fmaxf(v0, 0.f); v1 = fmaxf(v1, 0.f); }
                        s0 += v0 * rsv; s1 += v1 * rsv;
                    }
            }
            s0 += __shfl_down_sync(~0u, s0, 16);
            s0 += __shfl_down_sync(~0u, s0, 8);
            s0 += __shfl_down_sync(~0u, s0, 4);
            s1 += __shfl_down_sync(~0u, s1, 16);
            s1 += __shfl_down_sync(~0u, s1, 8);
            s1 += __shfl_down_sync(~0u, s1, 4);
            if (g == 0 && n < N) {
                atomicAdd(&vacc[voff + n], s0);
                atomicAdd(&vacc[voff + n + 1], s1);
            }
        }
        return;
    }

    __half* Ch = (__half*)Cv + (long)bz * sC;
    float*  Cf = (float*)Cv + (long)bz * sC;
#pragma unroll
    for (int mt = 0; mt < 4; mt++) {
#pragma unroll
        for (int r = 0; r < 2; r++) {
            int m = m0 + wm * 64 + mt * 16 + g + r * 8;
            if (m >= M) continue;
            float rsv = rs ? rs[(long)bz * sRS + m] : 1.f;
            int crow = 0;
            if (Cin) crow = iC ? iC[bz * 256 + m] : m;
#pragma unroll
            for (int nt = 0; nt < 4; nt++) {
                int n = n0 + wn * 32 + nt * 8 + tig * 2;
                if (n < N) {
                    float v0 = c[mt][nt][r * 2 + 0];
                    float v1 = c[mt][nt][r * 2 + 1];
                    if (rsPre) { v0 *= rsv; v1 *= rsv; }
                    if (Cin) {
                        v0 += __half2float(Cin[(long)crow * ldcin + n]);
                        v1 += __half2float(Cin[(long)crow * ldcin + n + 1]);
                    }
                    if (bias) { v0 += bias[n]; v1 += bias[n + 1]; }
                    if (n < nrelu) { v0 = fmaxf(v0, 0.f); v1 = fmaxf(v1, 0.f); }
                    if (!rsPre) { v0 *= rsv; v1 *= rsv; }
                    if (OUTH)
                        *(__half2*)(Ch + (long)m * ldc + n) = __floats2half2_rn(v0, v1);
                    else {
                        Cf[(long)m * ldc + n] = v0;
                        Cf[(long)m * ldc + n + 1] = v1;
                    }
                }
            }
        }
    }

    if (bmaxu) {   // per-batch max of this block's outputs (exact tiles only)
        float mx = -1e30f;
#pragma unroll
        for (int mt = 0; mt < 4; mt++)
#pragma unroll
            for (int nt = 0; nt < 4; nt++)
#pragma unroll
                for (int q = 0; q < 4; q++) mx = fmaxf(mx, c[mt][nt][q]);
#pragma unroll
        for (int o = 16; o; o >>= 1) mx = fmaxf(mx, __shfl_xor_sync(~0u, mx, o));
        if (lane == 0) atomicMax(&bmaxu[bz], fenc(mx));
    }
}

// dynamic smem bytes per instantiation (4 stages)
constexpr int smem_bytes(bool TA, bool TB)
{
    int a = TA ? 32 * 136 : 128 * 40;
    int b = TB ? 128 * 40 : 32 * 136;
    return 4 * (a + b) * 2;
}

// ---------------- helper kernels ---------------------------------------------
__global__ void conv2h_k(const float* __restrict__ src, __half* __restrict__ dst,
                         int rows, int cols, int srcR, int srcC)
{
    long idx = (long)blockIdx.x * blockDim.x + threadIdx.x;
    if (idx >= (long)rows * cols) return;
    int r = (int)(idx / cols), c = (int)(idx % cols);
    float v = (r < srcR && c < srcC) ? src[(long)r * srcC + c] : 0.f;
    dst[idx] = __float2half_rn(v);
}

// all weight conversions in ONE kernel (Wcat packing + W2a/W2c/W1g + biascat)
__global__ void convw_k(const float* __restrict__ W1a, const float* __restrict__ W1c,
                        const float* __restrict__ W2a, const float* __restrict__ W2c,
                        const float* __restrict__ W1g, const float* __restrict__ b1a)
{
    long idx = (long)blockIdx.x * blockDim.x + threadIdx.x;
    const long NW = (long)EP * NCAT;
    if (idx < NW) {
        int r = (int)(idx / NCAT), cc = (int)(idx % NCAT);
        float v = 0.f;
        if (r < Esz) {
            if (cc < 200)      v = W1a[(long)r * Hsz + cc];
            else if (cc < 400) v = W1c[(long)r * Hsz + (cc - 200)];
            else if (cc < 600) v = W1c[(long)(Esz + r) * Hsz + (cc - 400)];
        }
        g_Wcat[idx] = __float2half_rn(v);
        return;
    }
    idx -= NW;
    if (idx < Hsz * Hsz) { g_W2a[idx] = __float2half_rn(W2a[idx]); return; }
    idx -= Hsz * Hsz;
    if (idx < Hsz * Hsz) { g_W2c[idx] = __float2half_rn(W2c[idx]); return; }
    idx -= Hsz * Hsz;
    if (idx < 2 * Hsz * Hsz) { g_W1g[idx] = __float2half_rn(W1g[idx]); return; }
    idx -= 2 * Hsz * Hsz;
    if (idx < NCAT) { g_b1acat[idx] = (idx < Hsz) ? b1a[idx] : 0.f; return; }
}

// masks + token index concat + lens + bmax init + vcat accumulator zero
__global__ void mask_k(const int* __restrict__ s1, const int* __restrict__ s2,
                       const int* __restrict__ len1, const int* __restrict__ len2)
{
    long idx = (long)blockIdx.x * blockDim.x + threadIdx.x;
    if (idx >= 2 * BL) return;
    int seq = (int)(idx / BL);
    long r = idx % BL;
    int b = (int)(r / Lsz), l = (int)(r % Lsz);
    int len = seq ? len2[b] : len1[b];
    g_mask[idx] = (l < len) ? 1.f : 0.f;
    g_tok[idx] = seq ? s2[r] : s1[r];
    if (idx < Bsz) g_bmaxu[idx] = 0u;
    if (idx < 2 * Bsz) g_len12[idx] = (idx < Bsz) ? len1[idx] : len2[idx - Bsz];
    if (idx < Bsz * 2 * Hsz) g_vcatf[idx] = 0.f;
}

// Single-pass softmax (shift-cancelled, raw outputs): p = exp(e - Mb);
// write q=p*m1i -> g_eanh, w=p*m2j -> g_ebnh; colsum(q) -> rsa, rowsum(w) -> rsb.
// Normalization moved into th-GEMM epilogues (rsPre row scale).
__global__ void sums_k()
{
    __shared__ float rowacc[256];
    __shared__ float colsm[1024];
    int b = blockIdx.x;
    int tid = threadIdx.x;
    int j = tid & 255, s = tid >> 8, lane = tid & 31;
    if (tid < 256) rowacc[tid] = 0.f;
    __syncthreads();

    long base = (long)b * LL;
    float Mb  = fdec(g_bmaxu[b]);
    float m2j = g_mask[BL + (long)b * Lsz + j];
    float da = 0.f;
    for (int t = 0; t < 64; t++) {
        int i = s * 64 + t;
        long idx = base + (long)i * Lsz + j;
        float p = __expf(g_scores[idx] - Mb);
        float q = p * g_mask[(long)b * Lsz + i];
        da += q;
        g_eanh[idx] = __float2half_rn(q);
        float w = p * m2j;
        g_ebnh[idx] = __float2half_rn(w);
#pragma unroll
        for (int o = 16; o; o >>= 1) w += __shfl_xor_sync(~0u, w, o);
        if (lane == 0) atomicAdd(&rowacc[i], w);
    }
    colsm[tid] = da;
    __syncthreads();
    if (s == 0)
        g_rsa[(long)b * Lsz + j] =
            m2j / (colsm[j] + colsm[j + 256] + colsm[j + 512] + colsm[j + 768]);
    if (tid < 256)
        g_rsb[(long)b * Lsz + tid] = g_mask[(long)b * Lsz + tid] / rowacc[tid];
}

__global__ void vconv_k()    // fp32 vcat accumulator -> fp16
{
    int idx = blockIdx.x * blockDim.x + threadIdx.x;
    if (idx < Bsz * 2 * Hsz) g_vch[idx] = __float2half_rn(g_vcatf[idx]);
}

__global__ void final_k(const float* __restrict__ W2g,
                        const float* __restrict__ b2g, float* __restrict__ out)
{
    int b = blockIdx.x;
    int o = threadIdx.x >> 5;
    int lane = threadIdx.x & 31;
    const float* u = g_u + (long)b * Hsz;
    float s = 0.f;
    for (int h = lane; h < Hsz; h += 32) s += u[h] * W2g[h * 2 + o];
#pragma unroll
    for (int off = 16; off; off >>= 1) s += __shfl_xor_sync(~0u, s, off);
    if (lane == 0) out[b * 2 + o] = s + b2g[o];
}

// ---------------- launch -----------------------------------------------------
extern "C" void kernel_launch(void* const* d_in, const int* in_sizes, int n_in,
                              void* d_out, int out_size)
{
    const float* emb = (const float*)d_in[0];
    const float* W1a = (const float*)d_in[1];
    const float* b1a = (const float*)d_in[2];
    const float* W2a = (const float*)d_in[3];
    const float* b2a = (const float*)d_in[4];
    const float* W1c = (const float*)d_in[5];
    const float* b1c = (const float*)d_in[6];
    const float* W2c = (const float*)d_in[7];
    const float* b2c = (const float*)d_in[8];
    const float* W1g = (const float*)d_in[9];
    const float* b1g = (const float*)d_in[10];
    const float* W2g = (const float*)d_in[11];
    const float* b2g = (const float*)d_in[12];
    const int* s1   = (const int*)d_in[13];
    const int* s2   = (const int*)d_in[14];
    const int* len1 = (const int*)d_in[15];
    const int* len2 = (const int*)d_in[16];
    float* out = (float*)d_out;

    __half *pembh, *pWcat, *pW2a, *pW2c, *pW1g, *pvcb, *phvh;
    __half *peanh, *pebnh, *pthh, *pvch;
    float *pmask, *pu, *psc, *pb1acat, *pvcatf, *prsa, *prsb;
    int *ptok, *plen;
    unsigned *pbmx;
    cudaGetSymbolAddress((void**)&pembh,  g_embh);
    cudaGetSymbolAddress((void**)&pWcat,  g_Wcat);
    cudaGetSymbolAddress((void**)&pW2a,   g_W2a);
    cudaGetSymbolAddress((void**)&pW2c,   g_W2c);
    cudaGetSymbolAddress((void**)&pW1g,   g_W1g);
    cudaGetSymbolAddress((void**)&pvcb,   g_vcb);
    cudaGetSymbolAddress((void**)&phvh,   g_hvh);
    cudaGetSymbolAddress((void**)&peanh,  g_eanh);
    cudaGetSymbolAddress((void**)&pebnh,  g_ebnh);
    cudaGetSymbolAddress((void**)&pthh,   g_thh);
    cudaGetSymbolAddress((void**)&pvch,   g_vch);
    cudaGetSymbolAddress((void**)&pmask,  g_mask);
    cudaGetSymbolAddress((void**)&pu,     g_u);
    cudaGetSymbolAddress((void**)&psc,    g_scores);
    cudaGetSymbolAddress((void**)&pb1acat,g_b1acat);
    cudaGetSymbolAddress((void**)&pvcatf, g_vcatf);
    cudaGetSymbolAddress((void**)&prsa,   g_rsa);
    cudaGetSymbolAddress((void**)&prsb,   g_rsb);
    cudaGetSymbolAddress((void**)&ptok,   g_tok);
    cudaGetSymbolAddress((void**)&plen,   g_len12);
    cudaGetSymbolAddress((void**)&pbmx,   g_bmaxu);

    const int M2 = (int)(2 * BL);          // 262144
    const unsigned MV = (VOC + 127) / 128; // 391
    const int RALL = 1 << 30;              // relu on all columns
    auto cdiv = [](long n, long d) { return (unsigned)((n + d - 1) / d); };

    // KT per call site: EP=304 -> 10, K=200 -> 7, K=256 -> 8, K=400 -> 13
    constexpr int SM_FF = smem_bytes(false, false);   // 75776
    constexpr int SM_FT = smem_bytes(false, true);    // 81920
    constexpr int SM_TF = smem_bytes(true,  false);   // 75776
    cudaFuncSetAttribute((const void*)gemm_h<10,false,false,true>,
                         cudaFuncAttributeMaxDynamicSharedMemorySize, SM_FF);
    cudaFuncSetAttribute((const void*)gemm_h<7,false,false,true>,
                         cudaFuncAttributeMaxDynamicSharedMemorySize, SM_FF);
    cudaFuncSetAttribute((const void*)gemm_h<7,false,true,false>,
                         cudaFuncAttributeMaxDynamicSharedMemorySize, SM_FT);
    cudaFuncSetAttribute((const void*)gemm_h<8,false,false,true>,
                         cudaFuncAttributeMaxDynamicSharedMemorySize, SM_FF);
    cudaFuncSetAttribute((const void*)gemm_h<8,true,false,true>,
                         cudaFuncAttributeMaxDynamicSharedMemorySize, SM_TF);
    cudaFuncSetAttribute((const void*)gemm_h<13,false,false,false>,
                         cudaFuncAttributeMaxDynamicSharedMemorySize, SM_FF);

    // 1. emb -> fp16 (padded)
    conv2h_k<<<cdiv((long)VOC * EP, 256), 256>>>(emb, pembh, VOC, EP, VOC, Esz);
    // 2. all weights in one kernel
    long wtot = (long)EP * NCAT + 2 * Hsz * Hsz + 2 * Hsz * Hsz + NCAT;
    convw_k<<<cdiv(wtot, 256), 256>>>(W1a, W1c, W2a, W2c, W1g, b1a);
    // 3. masks + tok + lens + bmax + vcat zero
    mask_k<<<cdiv(2 * BL, 256), 256>>>(s1, s2, len1, len2);

    // 4. fused vocab GEMM: [attendL1(relu,b1a) | e@W1cT | e@W1cB]  (N=640, K=EP)
    gemm_h<10,false,false,true><<<dim3(5, MV, 1), 256, SM_FF>>>(
        pembh, 0, EP, nullptr, pWcat, 0, NCAT, nullptr, pb1acat, nullptr, 0, 0,
        nullptr, nullptr, 0, pvcb, 0, NCAT, VOC, NCAT, EP, Hsz,
        nullptr, nullptr, nullptr, nullptr, nullptr);
    // 5. attend L2: hv = relu(vcb[:, :200] @ W2a + b2a)   (K=200)
    gemm_h<7,false,false,true><<<dim3(2, MV, 1), 256, SM_FF>>>(
        pvcb, 0, NCAT, nullptr, pW2a, 0, Hsz, nullptr, b2a, nullptr, 0, 0,
        nullptr, nullptr, 0, phvh, 0, Hsz, VOC, Hsz, Hsz, RALL,
        nullptr, nullptr, nullptr, nullptr, nullptr);

    // 6. scores[b] = hv[s1] @ hv[s2]^T (K=200; batch-max; OR-skip masked tiles)
    gemm_h<7,false,true,false><<<dim3(2, 2, Bsz), 256, SM_FT>>>(
        phvh, 0, Hsz, s1, phvh, 0, Hsz, s2, nullptr, nullptr, 0, 0,
        nullptr, nullptr, 0, psc, LL, Lsz, Lsz, Lsz, Hsz, 0,
        pbmx, nullptr, plen, plen + Bsz, nullptr);

    // 7. single-pass softmax -> raw fp16 q/w + rsa/rsb
    sums_k<<<Bsz, 1024>>>();

    // 8. compare hidden: th1[i] = relu(rsb_i*(w_raw@cv2[s2]) + cv[tok] + b1c)
    //    (K=256, k-tiles beyond ceil(len2/32) skipped; row-blocks >= len1 skipped)
    gemm_h<8,false,false,true><<<dim3(2, 2, Bsz), 256, SM_FF>>>(
        pebnh, LL, Lsz, nullptr, pvcb + 400, 0, NCAT, s2, b1c, prsb, Lsz, 1,
        pvcb + 200, ptok, NCAT, pthh, (long)Lsz * Hsz, Hsz,
        Lsz, Hsz, Lsz, RALL, nullptr, nullptr, plen, nullptr, plen + Bsz);
    //    th2[j] = relu(rsa_j*(q_raw^T@cv2[s1]) + cv[tok2] + b1c)
    gemm_h<8,true,false,true><<<dim3(2, 2, Bsz), 256, SM_TF>>>(
        peanh, LL, Lsz, nullptr, pvcb + 400, 0, NCAT, s1, b1c, prsa, Lsz, 1,
        pvcb + 200, ptok + BL, NCAT, pthh + BL * Hsz, (long)Lsz * Hsz, Hsz,
        Lsz, Hsz, Lsz, RALL, nullptr, nullptr, plen + Bsz, nullptr, plen);

    // 9. compare L2 with fused masked column-sum (K=200; skip fully-masked blocks)
    gemm_h<7,false,false,true><<<dim3(2, M2 / 128, 1), 256, SM_FF>>>(
        pthh, 0, Hsz, nullptr, pW2c, 0, Hsz, nullptr, b2c, pmask, 0, 0,
        nullptr, nullptr, 0, nullptr, 0, Hsz, M2, Hsz, Hsz, RALL,
        nullptr, pvcatf, plen, nullptr, nullptr);

    // 10. vcat fp32 -> fp16 ; aggregate head (K=400)
    vconv_k<<<cdiv(Bsz * 2 * Hsz, 256), 256>>>();
    gemm_h<13,false,false,false><<<dim3(2, 4, 1), 256, SM_FF>>>(
        pvch, 0, 2 * Hsz, nullptr, pW1g, 0, Hsz, nullptr, b1g, nullptr, 0, 0,
        nullptr, nullptr, 0, pu, 0, Hsz, Bsz, Hsz, 2 * Hsz, RALL,
        nullptr, nullptr, nullptr, nullptr, nullptr);
    final_k<<<Bsz, 64>>>(W2g, b2g, out);
}